// round 2
// baseline (speedup 1.0000x reference)
#include <cuda_runtime.h>
#include <math.h>
#include <stdint.h>

#define NN   32768
#define CC   128
#define EE   524288
#define BBG  64
#define NGR  512
#define HH   4
#define DH   32
#define KEIG 128
#define KCH  5
#define BN_EPS 1e-5f

// ---------------- static scratch (no dynamic allocation allowed) ----------------
__device__ float g_hid [NN * 2 * CC];     // mlp hidden / spa hidden / spe hidden
__device__ float g_T0  [NN * CC];
__device__ float g_T1  [NN * CC];
__device__ float g_T2  [NN * CC];
__device__ float g_loc [NN * CC];         // out_local accumulator, later out0
__device__ float g_pre1[NN * CC];
__device__ float g_xspec[NN * CC];        // x_spec, later attention output
__device__ float g_hproj[NN * CC];        // h_proj, later h2
__device__ float g_qkv [NN * 3 * CC];
__device__ float g_scores[(size_t)BBG * HH * NGR * NGR];   // 256 MB
__device__ float g_S   [KEIG * CC];
__device__ float g_dis [NN];
__device__ int   g_outdeg[NN];
__device__ int   g_indeg [NN];
__device__ int   g_rowptr[NN + 1];
__device__ int   g_cursor[NN];
__device__ int   g_ecol  [EE];
__device__ float g_sums[6 * CC];          // sum1,sq1,sum2,sq2,sum3,sq3
__device__ float g_ab  [6 * CC];          // a1,b1,a2,b2,a3,b3

// ---------------- graph preprocessing ----------------
__global__ void k_count(const int* __restrict__ src, const int* __restrict__ dst) {
    int e = blockIdx.x * blockDim.x + threadIdx.x;
    if (e < EE) {
        atomicAdd(&g_outdeg[src[e]], 1);
        atomicAdd(&g_indeg [dst[e]], 1);
    }
}

__global__ void k_dis() {
    int n = blockIdx.x * blockDim.x + threadIdx.x;
    if (n < NN) {
        int d = g_outdeg[n];
        g_dis[n] = (d > 0) ? rsqrtf((float)d) : 0.0f;
    }
}

__global__ void k_scan() {   // single block, 256 threads, 128 nodes each
    __shared__ int tot[256];
    __shared__ int base[257];
    int t = threadIdx.x;
    int s = 0;
    for (int i = 0; i < 128; i++) s += g_indeg[t * 128 + i];
    tot[t] = s;
    __syncthreads();
    if (t == 0) {
        int a = 0;
        for (int i = 0; i < 256; i++) { base[i] = a; a += tot[i]; }
        base[256] = a;
    }
    __syncthreads();
    int a = base[t];
    for (int i = 0; i < 128; i++) {
        int n = t * 128 + i;
        g_rowptr[n] = a;
        g_cursor[n] = a;
        a += g_indeg[n];
    }
    if (t == 0) g_rowptr[NN] = base[256];
}

__global__ void k_fill(const int* __restrict__ src, const int* __restrict__ dst) {
    int e = blockIdx.x * blockDim.x + threadIdx.x;
    if (e < EE) {
        int p = atomicAdd(&g_cursor[dst[e]], 1);
        g_ecol[p] = src[e];
    }
}

// ---------------- generic tiled fp32 GEMM: C = act(A@W + bias + res (+C)) ----------------
// A: [M, Kd] row-major, W: [Kd, Cout] row-major, C/res: [M, Cout]
__global__ __launch_bounds__(256) void k_gemm(
    const float* __restrict__ A, const float* __restrict__ W,
    const float* __restrict__ bias, const float* __restrict__ res,
    float* __restrict__ C, int M, int Kd, int Cout, int relu, int accum)
{
    __shared__ float As[8][128];
    __shared__ float Bs[8][128];
    int bm = blockIdx.x * 128;
    int bn = blockIdx.y * 128;
    int tid = threadIdx.x;
    int tx = tid & 15, ty = tid >> 4;
    int arow = tid >> 1;
    int ac4  = (tid & 1) * 4;
    int brow = tid >> 5;
    int bc4  = (tid & 31) * 4;

    float acc[8][8];
#pragma unroll
    for (int i = 0; i < 8; i++)
#pragma unroll
        for (int j = 0; j < 8; j++) acc[i][j] = 0.0f;

    const float* Ap = A + (size_t)(bm + arow) * Kd + ac4;
    const float* Wp = W + (size_t)brow * Cout + bn + bc4;

    for (int k0 = 0; k0 < Kd; k0 += 8) {
        float4 av = *(const float4*)(Ap + k0);
        As[ac4 + 0][arow] = av.x; As[ac4 + 1][arow] = av.y;
        As[ac4 + 2][arow] = av.z; As[ac4 + 3][arow] = av.w;
        float4 wv = *(const float4*)(Wp + (size_t)k0 * Cout);
        *(float4*)&Bs[brow][bc4] = wv;
        __syncthreads();
#pragma unroll
        for (int kk = 0; kk < 8; kk++) {
            float a[8], b[8];
            *(float4*)(a)     = *(const float4*)&As[kk][ty * 8];
            *(float4*)(a + 4) = *(const float4*)&As[kk][ty * 8 + 4];
            *(float4*)(b)     = *(const float4*)&Bs[kk][tx * 8];
            *(float4*)(b + 4) = *(const float4*)&Bs[kk][tx * 8 + 4];
#pragma unroll
            for (int i = 0; i < 8; i++)
#pragma unroll
                for (int j = 0; j < 8; j++)
                    acc[i][j] = fmaf(a[i], b[j], acc[i][j]);
        }
        __syncthreads();
    }

#pragma unroll
    for (int i = 0; i < 8; i++) {
        int row = bm + ty * 8 + i;
        size_t ro = (size_t)row * Cout;
#pragma unroll
        for (int j = 0; j < 8; j += 4) {
            int col = bn + tx * 8 + j;
            float4 v = make_float4(acc[i][j], acc[i][j+1], acc[i][j+2], acc[i][j+3]);
            if (bias) {
                float4 bv = *(const float4*)&bias[col];
                v.x += bv.x; v.y += bv.y; v.z += bv.z; v.w += bv.w;
            }
            if (res) {
                float4 rv = *(const float4*)&res[ro + col];
                v.x += rv.x; v.y += rv.y; v.z += rv.z; v.w += rv.w;
            }
            if (accum) {
                float4 cv = *(const float4*)&C[ro + col];
                v.x += cv.x; v.y += cv.y; v.z += cv.z; v.w += cv.w;
            }
            if (relu) {
                v.x = fmaxf(v.x, 0.f); v.y = fmaxf(v.y, 0.f);
                v.z = fmaxf(v.z, 0.f); v.w = fmaxf(v.w, 0.f);
            }
            *(float4*)&C[ro + col] = v;
        }
    }
}

// ---------------- Chebyshev lhat step (gather via CSR-by-dst, fused recurrence) ----------------
// mode 0: Vo = (sc-1)*Vc - sc*agg(Vc)
// mode 1: Vo = 2*((sc-1)*Vc - sc*agg(Vc)) - Vp
__global__ void k_cheb(const float* __restrict__ Vc, const float* __restrict__ Vp,
                       float* __restrict__ Vo, const float* __restrict__ lam, int mode)
{
    int gw = (blockIdx.x * blockDim.x + threadIdx.x) >> 5;
    int lane = threadIdx.x & 31;
    if (gw >= NN) return;
    float sc = 2.0f / lam[0];
    int beg = g_rowptr[gw], end = g_rowptr[gw + 1];
    float dn = g_dis[gw];
    float4 acc = make_float4(0.f, 0.f, 0.f, 0.f);
    for (int j = beg; j < end; j++) {
        int s = g_ecol[j];
        float w = dn * g_dis[s];
        float4 v = *(const float4*)&Vc[(size_t)s * CC + lane * 4];
        acc.x = fmaf(w, v.x, acc.x);
        acc.y = fmaf(w, v.y, acc.y);
        acc.z = fmaf(w, v.z, acc.z);
        acc.w = fmaf(w, v.w, acc.w);
    }
    float4 vc = *(const float4*)&Vc[(size_t)gw * CC + lane * 4];
    float sm1 = sc - 1.0f;
    float4 r;
    r.x = sm1 * vc.x - sc * acc.x;
    r.y = sm1 * vc.y - sc * acc.y;
    r.z = sm1 * vc.z - sc * acc.z;
    r.w = sm1 * vc.w - sc * acc.w;
    if (mode) {
        float4 vp = *(const float4*)&Vp[(size_t)gw * CC + lane * 4];
        r.x = 2.f * r.x - vp.x; r.y = 2.f * r.y - vp.y;
        r.z = 2.f * r.z - vp.z; r.w = 2.f * r.w - vp.w;
    }
    *(float4*)&Vo[(size_t)gw * CC + lane * 4] = r;
}

// ---------------- split-K: S[k][c] += sum_n U[n][k] * Hp[n][c] ----------------
__global__ __launch_bounds__(256) void k_utgemm(const float* __restrict__ U,
                                                const float* __restrict__ Hp)
{
    __shared__ float Us[8][128];
    __shared__ float Hs[8][128];
    int n0 = blockIdx.x * 128;
    int tid = threadIdx.x, tx = tid & 15, ty = tid >> 4;
    int r = tid >> 5, c4 = (tid & 31) * 4;
    float acc[8][8];
#pragma unroll
    for (int i = 0; i < 8; i++)
#pragma unroll
        for (int j = 0; j < 8; j++) acc[i][j] = 0.f;

    for (int nn = 0; nn < 128; nn += 8) {
        *(float4*)&Us[r][c4] = *(const float4*)&U [(size_t)(n0 + nn + r) * 128 + c4];
        *(float4*)&Hs[r][c4] = *(const float4*)&Hp[(size_t)(n0 + nn + r) * 128 + c4];
        __syncthreads();
#pragma unroll
        for (int q = 0; q < 8; q++) {
            float a[8], b[8];
            *(float4*)(a)     = *(const float4*)&Us[q][ty * 8];
            *(float4*)(a + 4) = *(const float4*)&Us[q][ty * 8 + 4];
            *(float4*)(b)     = *(const float4*)&Hs[q][tx * 8];
            *(float4*)(b + 4) = *(const float4*)&Hs[q][tx * 8 + 4];
#pragma unroll
            for (int i = 0; i < 8; i++)
#pragma unroll
                for (int j = 0; j < 8; j++)
                    acc[i][j] = fmaf(a[i], b[j], acc[i][j]);
        }
        __syncthreads();
    }
#pragma unroll
    for (int i = 0; i < 8; i++)
#pragma unroll
        for (int j = 0; j < 8; j++)
            atomicAdd(&g_S[(ty * 8 + i) * 128 + tx * 8 + j], acc[i][j]);
}

__global__ void k_scaleS(const float* __restrict__ Lambda, const float* __restrict__ gamma) {
    int i = blockIdx.x * blockDim.x + threadIdx.x;
    if (i < KEIG * CC) {
        int k = i >> 7;
        float l = Lambda[k];
        g_S[i] *= expf(-gamma[0] * l * l);
    }
}

// ---------------- elementwise ----------------
__global__ void k_pre1(const float* __restrict__ x, const float* __restrict__ chb) {
    int i = blockIdx.x * blockDim.x + threadIdx.x;   // float4 index
    int col4 = (i & 31) * 4;
    float4 l  = ((const float4*)g_loc)[i];
    float4 xx = ((const float4*)x)[i];
    float4 cb = *(const float4*)&chb[col4];
    float4 rv;
    rv.x = l.x + cb.x + xx.x; rv.y = l.y + cb.y + xx.y;
    rv.z = l.z + cb.z + xx.z; rv.w = l.w + cb.w + xx.w;
    ((float4*)g_pre1)[i] = rv;
}

__global__ void k_bnstats(const float* __restrict__ X, float* __restrict__ sum,
                          float* __restrict__ sumsq)
{
    int c = threadIdx.x & 127;
    int half = threadIdx.x >> 7;
    float s = 0.f, s2 = 0.f;
    for (int row = blockIdx.x * 2 + half; row < NN; row += gridDim.x * 2) {
        float v = X[(size_t)row * CC + c];
        s += v;
        s2 = fmaf(v, v, s2);
    }
    __shared__ float sh[256], sh2[256];
    sh[threadIdx.x] = s; sh2[threadIdx.x] = s2;
    __syncthreads();
    if (threadIdx.x < 128) {
        atomicAdd(&sum[c],   sh [threadIdx.x] + sh [threadIdx.x + 128]);
        atomicAdd(&sumsq[c], sh2[threadIdx.x] + sh2[threadIdx.x + 128]);
    }
}

__global__ void k_bnfin(const float* __restrict__ sum, const float* __restrict__ sq,
                        const float* __restrict__ w, const float* __restrict__ b,
                        float* __restrict__ a, float* __restrict__ bs)
{
    int c = threadIdx.x;
    float mu  = sum[c] * (1.0f / NN);
    float var = sq[c]  * (1.0f / NN) - mu * mu;
    float aa = w[c] * rsqrtf(var + BN_EPS);
    a[c]  = aa;
    bs[c] = b[c] - mu * aa;
}

// out0 = bn1(pre1) + bn2(h2)
__global__ void k_combine(const float* __restrict__ h2) {
    int i = blockIdx.x * blockDim.x + threadIdx.x;
    int col4 = (i & 31) * 4;
    float4 p = ((const float4*)g_pre1)[i];
    float4 q = ((const float4*)h2)[i];
    float4 a1 = *(const float4*)&g_ab[col4];
    float4 b1 = *(const float4*)&g_ab[128 + col4];
    float4 a2 = *(const float4*)&g_ab[256 + col4];
    float4 b2 = *(const float4*)&g_ab[384 + col4];
    float4 rv;
    rv.x = fmaf(p.x, a1.x, b1.x) + fmaf(q.x, a2.x, b2.x);
    rv.y = fmaf(p.y, a1.y, b1.y) + fmaf(q.y, a2.y, b2.y);
    rv.z = fmaf(p.z, a1.z, b1.z) + fmaf(q.z, a2.z, b2.z);
    rv.w = fmaf(p.w, a1.w, b1.w) + fmaf(q.w, a2.w, b2.w);
    ((float4*)g_loc)[i] = rv;
}

__global__ void k_final(const float* __restrict__ X, float* __restrict__ out) {
    int i = blockIdx.x * blockDim.x + threadIdx.x;
    int col4 = (i & 31) * 4;
    float4 v = ((const float4*)X)[i];
    float4 a3 = *(const float4*)&g_ab[512 + col4];
    float4 b3 = *(const float4*)&g_ab[640 + col4];
    float4 rv;
    rv.x = fmaf(v.x, a3.x, b3.x); rv.y = fmaf(v.y, a3.y, b3.y);
    rv.z = fmaf(v.z, a3.z, b3.z); rv.w = fmaf(v.w, a3.w, b3.w);
    ((float4*)out)[i] = rv;
}

// ---------------- attention ----------------
// scores[bh][i][j] = (1/sqrt(32)) * sum_d q[b,i,h,d] k[b,j,h,d]
__global__ __launch_bounds__(256) void k_qk(const float* __restrict__ qkv,
                                            float* __restrict__ scores)
{
    int bh = blockIdx.z;
    int b = bh >> 2, h = bh & 3;
    int i0 = blockIdx.x * 128, j0 = blockIdx.y * 128;
    __shared__ float Qt[32][136];
    __shared__ float Kt[32][136];
    int tid = threadIdx.x;
    const float* qb = qkv + (size_t)(b * NGR + i0) * 384 + h * DH;
    const float* kb = qkv + (size_t)(b * NGR + j0) * 384 + h * DH + 128;
#pragma unroll
    for (int l = 0; l < 4; l++) {
        int f4 = tid + l * 256;
        int row = f4 >> 3, c4 = (f4 & 7) * 4;
        float4 q = *(const float4*)&qb[(size_t)row * 384 + c4];
        Qt[c4 + 0][row] = q.x; Qt[c4 + 1][row] = q.y;
        Qt[c4 + 2][row] = q.z; Qt[c4 + 3][row] = q.w;
        float4 kx = *(const float4*)&kb[(size_t)row * 384 + c4];
        Kt[c4 + 0][row] = kx.x; Kt[c4 + 1][row] = kx.y;
        Kt[c4 + 2][row] = kx.z; Kt[c4 + 3][row] = kx.w;
    }
    __syncthreads();
    int tx = tid & 15, ty = tid >> 4;
    float acc[8][8];
#pragma unroll
    for (int i = 0; i < 8; i++)
#pragma unroll
        for (int j = 0; j < 8; j++) acc[i][j] = 0.f;
#pragma unroll
    for (int d = 0; d < 32; d++) {
        float a[8], b2[8];
        *(float4*)(a)      = *(const float4*)&Qt[d][ty * 8];
        *(float4*)(a + 4)  = *(const float4*)&Qt[d][ty * 8 + 4];
        *(float4*)(b2)     = *(const float4*)&Kt[d][tx * 8];
        *(float4*)(b2 + 4) = *(const float4*)&Kt[d][tx * 8 + 4];
#pragma unroll
        for (int i = 0; i < 8; i++)
#pragma unroll
            for (int j = 0; j < 8; j++)
                acc[i][j] = fmaf(a[i], b2[j], acc[i][j]);
    }
    const float scl = 0.17677669529663687f;  // 1/sqrt(32)
#pragma unroll
    for (int i = 0; i < 8; i++) {
        int row = i0 + ty * 8 + i;
        size_t ro = ((size_t)bh * NGR + row) * NGR;
#pragma unroll
        for (int j = 0; j < 8; j += 4) {
            int col = j0 + tx * 8 + j;
            float4 v = make_float4(acc[i][j] * scl, acc[i][j+1] * scl,
                                   acc[i][j+2] * scl, acc[i][j+3] * scl);
            *(float4*)&scores[ro + col] = v;
        }
    }
}

__global__ void k_softmax(float* __restrict__ sc) {
    int gw = (blockIdx.x * blockDim.x + threadIdx.x) >> 5;
    int lane = threadIdx.x & 31;
    if (gw >= BBG * HH * NGR) return;
    float4* row = (float4*)(sc + (size_t)gw * NGR);
    float4 v[4];
    float m = -1e30f;
#pragma unroll
    for (int t = 0; t < 4; t++) {
        v[t] = row[lane + 32 * t];
        m = fmaxf(m, fmaxf(fmaxf(v[t].x, v[t].y), fmaxf(v[t].z, v[t].w)));
    }
#pragma unroll
    for (int o = 16; o; o >>= 1) m = fmaxf(m, __shfl_xor_sync(0xffffffffu, m, o));
    float s = 0.f;
#pragma unroll
    for (int t = 0; t < 4; t++) {
        v[t].x = expf(v[t].x - m); v[t].y = expf(v[t].y - m);
        v[t].z = expf(v[t].z - m); v[t].w = expf(v[t].w - m);
        s += v[t].x + v[t].y + v[t].z + v[t].w;
    }
#pragma unroll
    for (int o = 16; o; o >>= 1) s += __shfl_xor_sync(0xffffffffu, s, o);
    float inv = 1.0f / s;
#pragma unroll
    for (int t = 0; t < 4; t++) {
        v[t].x *= inv; v[t].y *= inv; v[t].z *= inv; v[t].w *= inv;
        row[lane + 32 * t] = v[t];
    }
}

// out[b*512+i][h*32+d] = sum_j P[bh][i][j] * v[b,j,h,d]
__global__ __launch_bounds__(256) void k_pv(const float* __restrict__ qkv,
                                            const float* __restrict__ scores,
                                            float* __restrict__ out)
{
    int bh = blockIdx.y;
    int b = bh >> 2, h = bh & 3;
    int i0 = blockIdx.x * 128;
    __shared__ float Pt[32][136];
    __shared__ float Vs[32][36];
    int tid = threadIdx.x, tx = tid & 15, ty = tid >> 4;
    float acc[8][2];
#pragma unroll
    for (int i = 0; i < 8; i++) { acc[i][0] = 0.f; acc[i][1] = 0.f; }
    const float* vb = qkv + (size_t)(b * NGR) * 384 + h * DH + 256;
    const float* pb = scores + ((size_t)bh * NGR + i0) * NGR;

    for (int jc = 0; jc < NGR; jc += 32) {
#pragma unroll
        for (int l = 0; l < 4; l++) {
            int f4 = tid + l * 256;
            int row = f4 >> 3, c4 = (f4 & 7) * 4;
            float4 p = *(const float4*)&pb[(size_t)row * NGR + jc + c4];
            Pt[c4 + 0][row] = p.x; Pt[c4 + 1][row] = p.y;
            Pt[c4 + 2][row] = p.z; Pt[c4 + 3][row] = p.w;
        }
        {
            int row = tid >> 3, c4 = (tid & 7) * 4;
            float4 v = *(const float4*)&vb[(size_t)(jc + row) * 384 + c4];
            Vs[row][c4 + 0] = v.x; Vs[row][c4 + 1] = v.y;
            Vs[row][c4 + 2] = v.z; Vs[row][c4 + 3] = v.w;
        }
        __syncthreads();
#pragma unroll
        for (int j = 0; j < 32; j++) {
            float a[8];
            *(float4*)(a)     = *(const float4*)&Pt[j][ty * 8];
            *(float4*)(a + 4) = *(const float4*)&Pt[j][ty * 8 + 4];
            float b0 = Vs[j][tx * 2], b1 = Vs[j][tx * 2 + 1];
#pragma unroll
            for (int i = 0; i < 8; i++) {
                acc[i][0] = fmaf(a[i], b0, acc[i][0]);
                acc[i][1] = fmaf(a[i], b1, acc[i][1]);
            }
        }
        __syncthreads();
    }
#pragma unroll
    for (int i = 0; i < 8; i++) {
        int row = i0 + ty * 8 + i;
        float* op = &out[(size_t)(b * NGR + row) * CC + h * DH + tx * 2];
        op[0] = acc[i][0];
        op[1] = acc[i][1];
    }
}

// ---------------- host ----------------
static float* symf(const void* p) { return (float*)p; }

extern "C" void kernel_launch(void* const* d_in, const int* in_sizes, int n_in,
                              void* d_out, int out_size)
{
    const float* x      = (const float*)d_in[0];
    const float* U      = (const float*)d_in[1];
    const float* Lambda = (const float*)d_in[2];
    const float* lamMax = (const float*)d_in[3];
    const float* w_spa1 = (const float*)d_in[4];  const float* b_spa1 = (const float*)d_in[5];
    const float* w_spa2 = (const float*)d_in[6];  const float* b_spa2 = (const float*)d_in[7];
    const float* w_spe1 = (const float*)d_in[8];  const float* b_spe1 = (const float*)d_in[9];
    const float* w_spe2 = (const float*)d_in[10]; const float* b_spe2 = (const float*)d_in[11];
    const float* cheb_w = (const float*)d_in[12]; const float* cheb_b = (const float*)d_in[13];
    const float* gamma  = (const float*)d_in[14]; const float* w_proj = (const float*)d_in[15];
    const float* w_qkv  = (const float*)d_in[16]; const float* b_qkv  = (const float*)d_in[17];
    const float* w_out  = (const float*)d_in[18]; const float* b_out  = (const float*)d_in[19];
    const float* mlp_w1 = (const float*)d_in[20]; const float* mlp_b1 = (const float*)d_in[21];
    const float* mlp_w2 = (const float*)d_in[22]; const float* mlp_b2 = (const float*)d_in[23];
    const float* bn1w = (const float*)d_in[24]; const float* bn1b = (const float*)d_in[25];
    const float* bn2w = (const float*)d_in[26]; const float* bn2b = (const float*)d_in[27];
    const float* bn3w = (const float*)d_in[28]; const float* bn3b = (const float*)d_in[29];
    const int*   ei   = (const int*)d_in[30];
    const int* src = ei;
    const int* dst = ei + EE;
    float* out = (float*)d_out;

    void *pHID, *pT0, *pT1, *pT2, *pLOC, *pPRE, *pXSP, *pHPJ, *pQKV, *pSCO, *pS;
    void *pOUTD, *pIND, *pSUMS, *pAB;
    cudaGetSymbolAddress(&pHID, g_hid);   cudaGetSymbolAddress(&pT0, g_T0);
    cudaGetSymbolAddress(&pT1, g_T1);     cudaGetSymbolAddress(&pT2, g_T2);
    cudaGetSymbolAddress(&pLOC, g_loc);   cudaGetSymbolAddress(&pPRE, g_pre1);
    cudaGetSymbolAddress(&pXSP, g_xspec); cudaGetSymbolAddress(&pHPJ, g_hproj);
    cudaGetSymbolAddress(&pQKV, g_qkv);   cudaGetSymbolAddress(&pSCO, g_scores);
    cudaGetSymbolAddress(&pS, g_S);
    cudaGetSymbolAddress(&pOUTD, g_outdeg); cudaGetSymbolAddress(&pIND, g_indeg);
    cudaGetSymbolAddress(&pSUMS, g_sums);   cudaGetSymbolAddress(&pAB, g_ab);

    float* HID = symf(pHID); float* T0 = symf(pT0); float* T1 = symf(pT1); float* T2 = symf(pT2);
    float* LOC = symf(pLOC); float* PRE = symf(pPRE); float* XSP = symf(pXSP);
    float* HPJ = symf(pHPJ); float* QKV = symf(pQKV); float* SCO = symf(pSCO);
    float* S = symf(pS); float* SUMS = symf(pSUMS);

    // zero the per-launch accumulators
    cudaMemsetAsync(pOUTD, 0, NN * sizeof(int));
    cudaMemsetAsync(pIND,  0, NN * sizeof(int));
    cudaMemsetAsync(pS,    0, KEIG * CC * sizeof(float));
    cudaMemsetAsync(pSUMS, 0, 6 * CC * sizeof(float));

    // graph preprocessing: degrees + CSR by dst
    k_count<<<EE / 256, 256>>>(src, dst);
    k_dis<<<NN / 256, 256>>>();
    k_scan<<<1, 256>>>();
    k_fill<<<EE / 256, 256>>>(src, dst);

    auto GEMM = [&](const float* A, const float* W, const float* bias, const float* res,
                    float* C, int M, int Kd, int Cout, int relu, int accum) {
        dim3 g(M / 128, Cout / 128);
        k_gemm<<<g, 256>>>(A, W, bias, res, C, M, Kd, Cout, relu, accum);
    };

    // ---- spatial MLP -> x_sp (T0) ----
    GEMM(x, w_spa1, b_spa1, nullptr, HID, NN, 128, 128, 1, 0);
    GEMM(HID, w_spa2, b_spa2, nullptr, T0, NN, 128, 128, 0, 0);

    // ---- Chebyshev conv, accumulate into LOC ----
    GEMM(T0, cheb_w, nullptr, nullptr, LOC, NN, 128, 128, 0, 0);
    k_cheb<<<NN / 8, 256>>>(T0, nullptr, T1, lamMax, 0);
    GEMM(T1, cheb_w + 1 * 128 * 128, nullptr, nullptr, LOC, NN, 128, 128, 0, 1);
    {
        float* prev = T0; float* cur = T1; float* nxt = T2;
        for (int k = 2; k < KCH; k++) {
            k_cheb<<<NN / 8, 256>>>(cur, prev, nxt, lamMax, 1);
            GEMM(nxt, cheb_w + (size_t)k * 128 * 128, nullptr, nullptr, LOC, NN, 128, 128, 0, 1);
            float* t = prev; prev = cur; cur = nxt; nxt = t;
        }
    }

    // ---- spectral branch ----
    GEMM(x, w_spe1, b_spe1, nullptr, HID, NN, 128, 128, 1, 0);
    GEMM(HID, w_spe2, b_spe2, nullptr, XSP, NN, 128, 128, 0, 0);
    GEMM(XSP, w_proj, nullptr, nullptr, HPJ, NN, 128, 128, 0, 0);
    k_utgemm<<<NN / 128, 256>>>(U, HPJ);
    k_scaleS<<<(KEIG * CC) / 256, 256>>>(Lambda, gamma);
    GEMM(U, S, nullptr, nullptr, LOC, NN, 128, 128, 0, 1);   // LOC += out_spectral

    // pre1 = LOC + cheb_b + x ; BN1 stats
    k_pre1<<<(NN * CC / 4) / 256, 256>>>(x, cheb_b);
    k_bnstats<<<256, 256>>>(PRE, SUMS, SUMS + 128);

    // ---- global attention ----
    GEMM(x, w_qkv, b_qkv, nullptr, QKV, NN, 128, 384, 0, 0);
    {
        dim3 gqk(4, 4, BBG * HH);
        k_qk<<<gqk, 256>>>(QKV, SCO);
        k_softmax<<<(BBG * HH * NGR) / 8, 256>>>(SCO);
        dim3 gpv(4, BBG * HH);
        k_pv<<<gpv, 256>>>(QKV, SCO, XSP);   // XSP reused as attention output
    }
    GEMM(XSP, w_out, b_out, x, HPJ, NN, 128, 128, 0, 0);     // HPJ = h2raw + x
    k_bnstats<<<256, 256>>>(HPJ, SUMS + 256, SUMS + 384);

    // BN affine params 1 & 2, then combine into out0 (LOC)
    k_bnfin<<<1, 128>>>(SUMS,       SUMS + 128, bn1w, bn1b, symf(pAB),       symf(pAB) + 128);
    k_bnfin<<<1, 128>>>(SUMS + 256, SUMS + 384, bn2w, bn2b, symf(pAB) + 256, symf(pAB) + 384);
    k_combine<<<(NN * CC / 4) / 256, 256>>>(HPJ);

    // ---- final MLP with residual ----
    GEMM(LOC, mlp_w1, mlp_b1, nullptr, HID, NN, 128, 256, 1, 0);
    GEMM(HID, mlp_w2, mlp_b2, LOC, T0, NN, 256, 128, 0, 0);  // T0 = out0 + mlp2(out0)

    // ---- BN3 -> output ----
    k_bnstats<<<256, 256>>>(T0, SUMS + 512, SUMS + 640);
    k_bnfin<<<1, 128>>>(SUMS + 512, SUMS + 640, bn3w, bn3b, symf(pAB) + 512, symf(pAB) + 640);
    k_final<<<(NN * CC / 4) / 256, 256>>>(T0, out);
}

// round 4
// speedup vs baseline: 1.6141x; 1.6141x over previous
#include <cuda_runtime.h>
#include <math.h>
#include <stdint.h>

#define NN   32768
#define CC   128
#define EE   524288
#define BBG  64
#define NGR  512
#define HH   4
#define DH   32
#define KEIG 128
#define KCH  5
#define BN_EPS 1e-5f

// ---------------- static scratch ----------------
__device__ float g_hid [NN * 2 * CC];
__device__ float g_T0  [NN * CC];
__device__ float g_T1  [NN * CC];
__device__ float g_T2  [NN * CC];
__device__ float g_loc [NN * CC];
__device__ float g_pre1[NN * CC];
__device__ float g_xspec[NN * CC];
__device__ float g_hproj[NN * CC];
__device__ float g_qkv [NN * 3 * CC];
__device__ float g_scores[(size_t)BBG * HH * NGR * NGR];
__device__ float g_S   [KEIG * CC];
__device__ float g_dis [NN];
__device__ int   g_outdeg[NN];
__device__ int   g_indeg [NN];
__device__ int   g_rowptr[NN + 1];
__device__ int   g_cursor[NN];
__device__ int   g_ecol  [EE];
__device__ float g_sums[6 * CC];
__device__ float g_ab  [6 * CC];

__device__ __forceinline__ float cvt_tf32(float x) {
    float r;
    asm("cvt.rna.tf32.f32 %0, %1;" : "=f"(r) : "f"(x));
    return r;
}
__device__ __forceinline__ float4 cvt_tf32_4(float4 v) {
    v.x = cvt_tf32(v.x); v.y = cvt_tf32(v.y);
    v.z = cvt_tf32(v.z); v.w = cvt_tf32(v.w);
    return v;
}
#define MMA_TF32(d0,d1,d2,d3,a0,a1,a2,a3,b0,b1)                               \
    asm volatile("mma.sync.aligned.m16n8k8.row.col.f32.tf32.tf32.f32 "        \
        "{%0,%1,%2,%3}, {%4,%5,%6,%7}, {%8,%9}, {%0,%1,%2,%3};"               \
        : "+f"(d0), "+f"(d1), "+f"(d2), "+f"(d3)                              \
        : "r"(a0), "r"(a1), "r"(a2), "r"(a3), "r"(b0), "r"(b1))

// ---------------- graph preprocessing ----------------
__global__ void k_count(const int* __restrict__ src, const int* __restrict__ dst) {
    int e = blockIdx.x * blockDim.x + threadIdx.x;
    if (e < EE) {
        atomicAdd(&g_outdeg[src[e]], 1);
        atomicAdd(&g_indeg [dst[e]], 1);
    }
}

__global__ void k_dis() {
    int n = blockIdx.x * blockDim.x + threadIdx.x;
    if (n < NN) {
        int d = g_outdeg[n];
        g_dis[n] = (d > 0) ? rsqrtf((float)d) : 0.0f;
    }
}

__global__ void k_scan() {
    __shared__ int tot[256];
    __shared__ int base[257];
    int t = threadIdx.x;
    int s = 0;
    for (int i = 0; i < 128; i++) s += g_indeg[t * 128 + i];
    tot[t] = s;
    __syncthreads();
    if (t == 0) {
        int a = 0;
        for (int i = 0; i < 256; i++) { base[i] = a; a += tot[i]; }
        base[256] = a;
    }
    __syncthreads();
    int a = base[t];
    for (int i = 0; i < 128; i++) {
        int n = t * 128 + i;
        g_rowptr[n] = a;
        g_cursor[n] = a;
        a += g_indeg[n];
    }
    if (t == 0) g_rowptr[NN] = base[256];
}

__global__ void k_fill(const int* __restrict__ src, const int* __restrict__ dst) {
    int e = blockIdx.x * blockDim.x + threadIdx.x;
    if (e < EE) {
        int p = atomicAdd(&g_cursor[dst[e]], 1);
        g_ecol[p] = src[e];
    }
}

// ---------------- tf32 tensor-core GEMM: C = act(A@W + bias + res (+C)) ----------------
// A [M,Kd] row-major, W [Kd,Cout] row-major. Block tile 128x128, BK=16, 8 warps.
#define AS_STR 20
#define BS_STR 136
__global__ __launch_bounds__(256) void k_gemm(
    const float* __restrict__ A, const float* __restrict__ W,
    const float* __restrict__ bias, const float* __restrict__ res,
    float* __restrict__ C, int M, int Kd, int Cout, int relu, int accum)
{
    __shared__ float As[128 * AS_STR];
    __shared__ float Bs[16 * BS_STR];
    int bm = blockIdx.x * 128;
    int bn = blockIdx.y * 128;
    int tid = threadIdx.x;
    int warp = tid >> 5, lane = tid & 31;
    int wm = (warp >> 1) * 32;        // warp M offset (0,32,64,96)
    int wn = (warp & 1) * 64;         // warp N offset (0,64)
    int lr = lane >> 2;               // 0..7
    int lc = lane & 3;                // 0..3

    float acc[2][8][4];
#pragma unroll
    for (int i = 0; i < 2; i++)
#pragma unroll
        for (int j = 0; j < 8; j++)
#pragma unroll
            for (int q = 0; q < 4; q++) acc[i][j][q] = 0.0f;

    for (int k0 = 0; k0 < Kd; k0 += 16) {
        // load A tile 128x16
#pragma unroll
        for (int l = 0; l < 2; l++) {
            int i = tid + l * 256;            // f4 index, 512 total
            int row = i >> 2, c4 = (i & 3) * 4;
            float4 v = *(const float4*)&A[(size_t)(bm + row) * Kd + k0 + c4];
            *(float4*)&As[row * AS_STR + c4] = cvt_tf32_4(v);
        }
        // load W tile 16x128
#pragma unroll
        for (int l = 0; l < 2; l++) {
            int i = tid + l * 256;
            int row = i >> 5, c4 = (i & 31) * 4;
            float4 v = *(const float4*)&W[(size_t)(k0 + row) * Cout + bn + c4];
            *(float4*)&Bs[row * BS_STR + c4] = cvt_tf32_4(v);
        }
        __syncthreads();
#pragma unroll
        for (int kk = 0; kk < 16; kk += 8) {
            uint32_t af[2][4], bf[8][2];
#pragma unroll
            for (int mt = 0; mt < 2; mt++) {
                int r = wm + mt * 16 + lr;
                af[mt][0] = __float_as_uint(As[r * AS_STR + kk + lc]);
                af[mt][1] = __float_as_uint(As[(r + 8) * AS_STR + kk + lc]);
                af[mt][2] = __float_as_uint(As[r * AS_STR + kk + lc + 4]);
                af[mt][3] = __float_as_uint(As[(r + 8) * AS_STR + kk + lc + 4]);
            }
#pragma unroll
            for (int nt = 0; nt < 8; nt++) {
                int c = wn + nt * 8 + lr;
                bf[nt][0] = __float_as_uint(Bs[(kk + lc) * BS_STR + c]);
                bf[nt][1] = __float_as_uint(Bs[(kk + lc + 4) * BS_STR + c]);
            }
#pragma unroll
            for (int mt = 0; mt < 2; mt++)
#pragma unroll
                for (int nt = 0; nt < 8; nt++)
                    MMA_TF32(acc[mt][nt][0], acc[mt][nt][1], acc[mt][nt][2], acc[mt][nt][3],
                             af[mt][0], af[mt][1], af[mt][2], af[mt][3],
                             bf[nt][0], bf[nt][1]);
        }
        __syncthreads();
    }

    // epilogue: c0,c1 at (row, col), c2,c3 at (row+8, col)
#pragma unroll
    for (int mt = 0; mt < 2; mt++) {
#pragma unroll
        for (int half = 0; half < 2; half++) {
            int row = bm + wm + mt * 16 + lr + half * 8;
            size_t ro = (size_t)row * Cout;
#pragma unroll
            for (int nt = 0; nt < 8; nt++) {
                int col = bn + wn + nt * 8 + lc * 2;
                float v0 = acc[mt][nt][half * 2];
                float v1 = acc[mt][nt][half * 2 + 1];
                if (bias) { v0 += bias[col]; v1 += bias[col + 1]; }
                if (res)  { v0 += res[ro + col]; v1 += res[ro + col + 1]; }
                if (accum){ v0 += C[ro + col];  v1 += C[ro + col + 1]; }
                if (relu) { v0 = fmaxf(v0, 0.f); v1 = fmaxf(v1, 0.f); }
                *(float2*)&C[ro + col] = make_float2(v0, v1);
            }
        }
    }
}

// ---------------- Chebyshev lhat step (gather via CSR-by-dst) ----------------
__global__ void k_cheb(const float* __restrict__ Vc, const float* __restrict__ Vp,
                       float* __restrict__ Vo, const float* __restrict__ lam, int mode)
{
    int gw = (blockIdx.x * blockDim.x + threadIdx.x) >> 5;
    int lane = threadIdx.x & 31;
    if (gw >= NN) return;
    float sc = 2.0f / lam[0];
    int beg = g_rowptr[gw], end = g_rowptr[gw + 1];
    float dn = g_dis[gw];
    float4 acc = make_float4(0.f, 0.f, 0.f, 0.f);
    for (int j = beg; j < end; j++) {
        int s = g_ecol[j];
        float w = dn * g_dis[s];
        float4 v = *(const float4*)&Vc[(size_t)s * CC + lane * 4];
        acc.x = fmaf(w, v.x, acc.x);
        acc.y = fmaf(w, v.y, acc.y);
        acc.z = fmaf(w, v.z, acc.z);
        acc.w = fmaf(w, v.w, acc.w);
    }
    float4 vc = *(const float4*)&Vc[(size_t)gw * CC + lane * 4];
    float sm1 = sc - 1.0f;
    float4 r;
    r.x = sm1 * vc.x - sc * acc.x;
    r.y = sm1 * vc.y - sc * acc.y;
    r.z = sm1 * vc.z - sc * acc.z;
    r.w = sm1 * vc.w - sc * acc.w;
    if (mode) {
        float4 vp = *(const float4*)&Vp[(size_t)gw * CC + lane * 4];
        r.x = 2.f * r.x - vp.x; r.y = 2.f * r.y - vp.y;
        r.z = 2.f * r.z - vp.z; r.w = 2.f * r.w - vp.w;
    }
    *(float4*)&Vo[(size_t)gw * CC + lane * 4] = r;
}

// ---------------- split-K: S[k][c] += sum_n U[n][k] * Hp[n][c] (fp32 SIMT) ----------------
__global__ __launch_bounds__(256) void k_utgemm(const float* __restrict__ U,
                                                const float* __restrict__ Hp)
{
    __shared__ float Us[8][128];
    __shared__ float Hs[8][128];
    int n0 = blockIdx.x * 128;
    int tid = threadIdx.x, tx = tid & 15, ty = tid >> 4;
    int r = tid >> 5, c4 = (tid & 31) * 4;
    float acc[8][8];
#pragma unroll
    for (int i = 0; i < 8; i++)
#pragma unroll
        for (int j = 0; j < 8; j++) acc[i][j] = 0.f;

    for (int nn = 0; nn < 128; nn += 8) {
        *(float4*)&Us[r][c4] = *(const float4*)&U [(size_t)(n0 + nn + r) * 128 + c4];
        *(float4*)&Hs[r][c4] = *(const float4*)&Hp[(size_t)(n0 + nn + r) * 128 + c4];
        __syncthreads();
#pragma unroll
        for (int q = 0; q < 8; q++) {
            float a[8], b[8];
            *(float4*)(a)     = *(const float4*)&Us[q][ty * 8];
            *(float4*)(a + 4) = *(const float4*)&Us[q][ty * 8 + 4];
            *(float4*)(b)     = *(const float4*)&Hs[q][tx * 8];
            *(float4*)(b + 4) = *(const float4*)&Hs[q][tx * 8 + 4];
#pragma unroll
            for (int i = 0; i < 8; i++)
#pragma unroll
                for (int j = 0; j < 8; j++)
                    acc[i][j] = fmaf(a[i], b[j], acc[i][j]);
        }
        __syncthreads();
    }
#pragma unroll
    for (int i = 0; i < 8; i++)
#pragma unroll
        for (int j = 0; j < 8; j++)
            atomicAdd(&g_S[(ty * 8 + i) * 128 + tx * 8 + j], acc[i][j]);
}

__global__ void k_scaleS(const float* __restrict__ Lambda, const float* __restrict__ gamma) {
    int i = blockIdx.x * blockDim.x + threadIdx.x;
    if (i < KEIG * CC) {
        int k = i >> 7;
        float l = Lambda[k];
        g_S[i] *= expf(-gamma[0] * l * l);
    }
}

// ---------------- elementwise / BN ----------------
__global__ void k_pre1(const float* __restrict__ x, const float* __restrict__ chb) {
    int i = blockIdx.x * blockDim.x + threadIdx.x;
    int col4 = (i & 31) * 4;
    float4 l  = ((const float4*)g_loc)[i];
    float4 xx = ((const float4*)x)[i];
    float4 cb = *(const float4*)&chb[col4];
    float4 rv;
    rv.x = l.x + cb.x + xx.x; rv.y = l.y + cb.y + xx.y;
    rv.z = l.z + cb.z + xx.z; rv.w = l.w + cb.w + xx.w;
    ((float4*)g_pre1)[i] = rv;
}

__global__ void k_bnstats(const float* __restrict__ X, float* __restrict__ sum,
                          float* __restrict__ sumsq)
{
    int c = threadIdx.x & 127;
    int half = threadIdx.x >> 7;
    float s = 0.f, s2 = 0.f;
    for (int row = blockIdx.x * 2 + half; row < NN; row += gridDim.x * 2) {
        float v = X[(size_t)row * CC + c];
        s += v;
        s2 = fmaf(v, v, s2);
    }
    __shared__ float sh[256], sh2[256];
    sh[threadIdx.x] = s; sh2[threadIdx.x] = s2;
    __syncthreads();
    if (threadIdx.x < 128) {
        atomicAdd(&sum[c],   sh [threadIdx.x] + sh [threadIdx.x + 128]);
        atomicAdd(&sumsq[c], sh2[threadIdx.x] + sh2[threadIdx.x + 128]);
    }
}

__global__ void k_bnfin(const float* __restrict__ sum, const float* __restrict__ sq,
                        const float* __restrict__ w, const float* __restrict__ b,
                        float* __restrict__ a, float* __restrict__ bs)
{
    int c = threadIdx.x;
    float mu  = sum[c] * (1.0f / NN);
    float var = sq[c]  * (1.0f / NN) - mu * mu;
    float aa = w[c] * rsqrtf(var + BN_EPS);
    a[c]  = aa;
    bs[c] = b[c] - mu * aa;
}

__global__ void k_combine(const float* __restrict__ h2) {
    int i = blockIdx.x * blockDim.x + threadIdx.x;
    int col4 = (i & 31) * 4;
    float4 p = ((const float4*)g_pre1)[i];
    float4 q = ((const float4*)h2)[i];
    float4 a1 = *(const float4*)&g_ab[col4];
    float4 b1 = *(const float4*)&g_ab[128 + col4];
    float4 a2 = *(const float4*)&g_ab[256 + col4];
    float4 b2 = *(const float4*)&g_ab[384 + col4];
    float4 rv;
    rv.x = fmaf(p.x, a1.x, b1.x) + fmaf(q.x, a2.x, b2.x);
    rv.y = fmaf(p.y, a1.y, b1.y) + fmaf(q.y, a2.y, b2.y);
    rv.z = fmaf(p.z, a1.z, b1.z) + fmaf(q.z, a2.z, b2.z);
    rv.w = fmaf(p.w, a1.w, b1.w) + fmaf(q.w, a2.w, b2.w);
    ((float4*)g_loc)[i] = rv;
}

__global__ void k_final(const float* __restrict__ X, float* __restrict__ out) {
    int i = blockIdx.x * blockDim.x + threadIdx.x;
    int col4 = (i & 31) * 4;
    float4 v = ((const float4*)X)[i];
    float4 a3 = *(const float4*)&g_ab[512 + col4];
    float4 b3 = *(const float4*)&g_ab[640 + col4];
    float4 rv;
    rv.x = fmaf(v.x, a3.x, b3.x); rv.y = fmaf(v.y, a3.y, b3.y);
    rv.z = fmaf(v.z, a3.z, b3.z); rv.w = fmaf(v.w, a3.w, b3.w);
    ((float4*)out)[i] = rv;
}

// ---------------- attention (tf32 mma) ----------------
// scores[bh][i][j] = (1/sqrt(32)) * sum_d q[b,i,h,d] k[b,j,h,d]
#define QS_STR 36
__global__ __launch_bounds__(256) void k_qk(const float* __restrict__ qkv,
                                            float* __restrict__ scores)
{
    __shared__ float Qs[128 * QS_STR];
    __shared__ float Ks[128 * QS_STR];
    int bh = blockIdx.z;
    int b = bh >> 2, h = bh & 3;
    int i0 = blockIdx.x * 128, j0 = blockIdx.y * 128;
    int tid = threadIdx.x;
    int warp = tid >> 5, lane = tid & 31;
    int wm = (warp >> 1) * 32, wn = (warp & 1) * 64;
    int lr = lane >> 2, lc = lane & 3;

    const float* qb = qkv + (size_t)(b * NGR + i0) * 384 + h * DH;
    const float* kb = qkv + (size_t)(b * NGR + j0) * 384 + h * DH + 128;
#pragma unroll
    for (int l = 0; l < 4; l++) {
        int i = tid + l * 256;          // 1024 f4 total (128 rows x 8 f4)
        int row = i >> 3, c4 = (i & 7) * 4;
        float4 q = *(const float4*)&qb[(size_t)row * 384 + c4];
        *(float4*)&Qs[row * QS_STR + c4] = cvt_tf32_4(q);
        float4 kx = *(const float4*)&kb[(size_t)row * 384 + c4];
        *(float4*)&Ks[row * QS_STR + c4] = cvt_tf32_4(kx);
    }
    __syncthreads();

    float acc[2][8][4];
#pragma unroll
    for (int i = 0; i < 2; i++)
#pragma unroll
        for (int j = 0; j < 8; j++)
#pragma unroll
            for (int q = 0; q < 4; q++) acc[i][j][q] = 0.f;

#pragma unroll
    for (int kk = 0; kk < 32; kk += 8) {
        uint32_t af[2][4], bf[8][2];
#pragma unroll
        for (int mt = 0; mt < 2; mt++) {
            int r = wm + mt * 16 + lr;
            af[mt][0] = __float_as_uint(Qs[r * QS_STR + kk + lc]);
            af[mt][1] = __float_as_uint(Qs[(r + 8) * QS_STR + kk + lc]);
            af[mt][2] = __float_as_uint(Qs[r * QS_STR + kk + lc + 4]);
            af[mt][3] = __float_as_uint(Qs[(r + 8) * QS_STR + kk + lc + 4]);
        }
#pragma unroll
        for (int nt = 0; nt < 8; nt++) {
            int c = wn + nt * 8 + lr;   // key index
            bf[nt][0] = __float_as_uint(Ks[c * QS_STR + kk + lc]);
            bf[nt][1] = __float_as_uint(Ks[c * QS_STR + kk + lc + 4]);
        }
#pragma unroll
        for (int mt = 0; mt < 2; mt++)
#pragma unroll
            for (int nt = 0; nt < 8; nt++)
                MMA_TF32(acc[mt][nt][0], acc[mt][nt][1], acc[mt][nt][2], acc[mt][nt][3],
                         af[mt][0], af[mt][1], af[mt][2], af[mt][3],
                         bf[nt][0], bf[nt][1]);
    }

    const float scl = 0.17677669529663687f;  // 1/sqrt(32)
#pragma unroll
    for (int mt = 0; mt < 2; mt++)
#pragma unroll
        for (int half = 0; half < 2; half++) {
            int row = i0 + wm + mt * 16 + lr + half * 8;
            size_t ro = ((size_t)bh * NGR + row) * NGR;
#pragma unroll
            for (int nt = 0; nt < 8; nt++) {
                int col = j0 + wn + nt * 8 + lc * 2;
                *(float2*)&scores[ro + col] =
                    make_float2(acc[mt][nt][half * 2] * scl, acc[mt][nt][half * 2 + 1] * scl);
            }
        }
}

__global__ void k_softmax(float* __restrict__ sc) {
    int gw = (blockIdx.x * blockDim.x + threadIdx.x) >> 5;
    int lane = threadIdx.x & 31;
    if (gw >= BBG * HH * NGR) return;
    float4* row = (float4*)(sc + (size_t)gw * NGR);
    float4 v[4];
    float m = -1e30f;
#pragma unroll
    for (int t = 0; t < 4; t++) {
        v[t] = row[lane + 32 * t];
        m = fmaxf(m, fmaxf(fmaxf(v[t].x, v[t].y), fmaxf(v[t].z, v[t].w)));
    }
#pragma unroll
    for (int o = 16; o; o >>= 1) m = fmaxf(m, __shfl_xor_sync(0xffffffffu, m, o));
    float s = 0.f;
#pragma unroll
    for (int t = 0; t < 4; t++) {
        v[t].x = expf(v[t].x - m); v[t].y = expf(v[t].y - m);
        v[t].z = expf(v[t].z - m); v[t].w = expf(v[t].w - m);
        s += v[t].x + v[t].y + v[t].z + v[t].w;
    }
#pragma unroll
    for (int o = 16; o; o >>= 1) s += __shfl_xor_sync(0xffffffffu, s, o);
    float inv = 1.0f / s;
#pragma unroll
    for (int t = 0; t < 4; t++) {
        v[t].x *= inv; v[t].y *= inv; v[t].z *= inv; v[t].w *= inv;
        row[lane + 32 * t] = v[t];
    }
}

// out[b*512+i][h*32+d] = sum_j P[bh][i][j] * v[b,j,h,d]   (tf32 mma, block 128x32)
#define PS_STR 20
#define VS_STR 40
__global__ __launch_bounds__(256) void k_pv(const float* __restrict__ qkv,
                                            const float* __restrict__ scores,
                                            float* __restrict__ out)
{
    __shared__ float Ps[128 * PS_STR];
    __shared__ float Vs[16 * VS_STR];
    int bh = blockIdx.y;
    int b = bh >> 2, h = bh & 3;
    int i0 = blockIdx.x * 128;
    int tid = threadIdx.x;
    int warp = tid >> 5, lane = tid & 31;
    int wm = (warp >> 1) * 32, wn = (warp & 1) * 16;
    int lr = lane >> 2, lc = lane & 3;

    const float* vb = qkv + (size_t)(b * NGR) * 384 + h * DH + 256;
    const float* pb = scores + ((size_t)bh * NGR + i0) * NGR;

    float acc[2][2][4];
#pragma unroll
    for (int i = 0; i < 2; i++)
#pragma unroll
        for (int j = 0; j < 2; j++)
#pragma unroll
            for (int q = 0; q < 4; q++) acc[i][j][q] = 0.f;

    for (int k0 = 0; k0 < NGR; k0 += 16) {
#pragma unroll
        for (int l = 0; l < 2; l++) {
            int i = tid + l * 256;       // 512 f4: 128 rows x 4 f4
            int row = i >> 2, c4 = (i & 3) * 4;
            float4 p = *(const float4*)&pb[(size_t)row * NGR + k0 + c4];
            *(float4*)&Ps[row * PS_STR + c4] = cvt_tf32_4(p);
        }
        if (tid < 128) {
            int row = tid >> 3, c4 = (tid & 7) * 4;
            float4 v = *(const float4*)&vb[(size_t)(k0 + row) * 384 + c4];
            *(float4*)&Vs[row * VS_STR + c4] = cvt_tf32_4(v);
        }
        __syncthreads();
#pragma unroll
        for (int kk = 0; kk < 16; kk += 8) {
            uint32_t af[2][4], bf[2][2];
#pragma unroll
            for (int mt = 0; mt < 2; mt++) {
                int r = wm + mt * 16 + lr;
                af[mt][0] = __float_as_uint(Ps[r * PS_STR + kk + lc]);
                af[mt][1] = __float_as_uint(Ps[(r + 8) * PS_STR + kk + lc]);
                af[mt][2] = __float_as_uint(Ps[r * PS_STR + kk + lc + 4]);
                af[mt][3] = __float_as_uint(Ps[(r + 8) * PS_STR + kk + lc + 4]);
            }
#pragma unroll
            for (int nt = 0; nt < 2; nt++) {
                int c = wn + nt * 8 + lr;
                bf[nt][0] = __float_as_uint(Vs[(kk + lc) * VS_STR + c]);
                bf[nt][1] = __float_as_uint(Vs[(kk + lc + 4) * VS_STR + c]);
            }
#pragma unroll
            for (int mt = 0; mt < 2; mt++)
#pragma unroll
                for (int nt = 0; nt < 2; nt++)
                    MMA_TF32(acc[mt][nt][0], acc[mt][nt][1], acc[mt][nt][2], acc[mt][nt][3],
                             af[mt][0], af[mt][1], af[mt][2], af[mt][3],
                             bf[nt][0], bf[nt][1]);
        }
        __syncthreads();
    }

#pragma unroll
    for (int mt = 0; mt < 2; mt++)
#pragma unroll
        for (int half = 0; half < 2; half++) {
            int row = i0 + wm + mt * 16 + lr + half * 8;
            float* op = &out[(size_t)(b * NGR + row) * CC + h * DH];
#pragma unroll
            for (int nt = 0; nt < 2; nt++) {
                int col = wn + nt * 8 + lc * 2;
                *(float2*)&op[col] =
                    make_float2(acc[mt][nt][half * 2], acc[mt][nt][half * 2 + 1]);
            }
        }
}

// ---------------- host ----------------
static float* symf(const void* p) { return (float*)p; }

extern "C" void kernel_launch(void* const* d_in, const int* in_sizes, int n_in,
                              void* d_out, int out_size)
{
    const float* x      = (const float*)d_in[0];
    const float* U      = (const float*)d_in[1];
    const float* Lambda = (const float*)d_in[2];
    const float* lamMax = (const float*)d_in[3];
    const float* w_spa1 = (const float*)d_in[4];  const float* b_spa1 = (const float*)d_in[5];
    const float* w_spa2 = (const float*)d_in[6];  const float* b_spa2 = (const float*)d_in[7];
    const float* w_spe1 = (const float*)d_in[8];  const float* b_spe1 = (const float*)d_in[9];
    const float* w_spe2 = (const float*)d_in[10]; const float* b_spe2 = (const float*)d_in[11];
    const float* cheb_w = (const float*)d_in[12]; const float* cheb_b = (const float*)d_in[13];
    const float* gamma  = (const float*)d_in[14]; const float* w_proj = (const float*)d_in[15];
    const float* w_qkv  = (const float*)d_in[16]; const float* b_qkv  = (const float*)d_in[17];
    const float* w_out  = (const float*)d_in[18]; const float* b_out  = (const float*)d_in[19];
    const float* mlp_w1 = (const float*)d_in[20]; const float* mlp_b1 = (const float*)d_in[21];
    const float* mlp_w2 = (const float*)d_in[22]; const float* mlp_b2 = (const float*)d_in[23];
    const float* bn1w = (const float*)d_in[24]; const float* bn1b = (const float*)d_in[25];
    const float* bn2w = (const float*)d_in[26]; const float* bn2b = (const float*)d_in[27];
    const float* bn3w = (const float*)d_in[28]; const float* bn3b = (const float*)d_in[29];
    const int*   ei   = (const int*)d_in[30];
    const int* src = ei;
    const int* dst = ei + EE;
    float* out = (float*)d_out;

    void *pHID, *pT0, *pT1, *pT2, *pLOC, *pPRE, *pXSP, *pHPJ, *pQKV, *pSCO, *pS;
    void *pOUTD, *pIND, *pSUMS, *pAB;
    cudaGetSymbolAddress(&pHID, g_hid);   cudaGetSymbolAddress(&pT0, g_T0);
    cudaGetSymbolAddress(&pT1, g_T1);     cudaGetSymbolAddress(&pT2, g_T2);
    cudaGetSymbolAddress(&pLOC, g_loc);   cudaGetSymbolAddress(&pPRE, g_pre1);
    cudaGetSymbolAddress(&pXSP, g_xspec); cudaGetSymbolAddress(&pHPJ, g_hproj);
    cudaGetSymbolAddress(&pQKV, g_qkv);   cudaGetSymbolAddress(&pSCO, g_scores);
    cudaGetSymbolAddress(&pS, g_S);
    cudaGetSymbolAddress(&pOUTD, g_outdeg); cudaGetSymbolAddress(&pIND, g_indeg);
    cudaGetSymbolAddress(&pSUMS, g_sums);   cudaGetSymbolAddress(&pAB, g_ab);

    float* HID = symf(pHID); float* T0 = symf(pT0); float* T1 = symf(pT1); float* T2 = symf(pT2);
    float* LOC = symf(pLOC); float* PRE = symf(pPRE); float* XSP = symf(pXSP);
    float* HPJ = symf(pHPJ); float* QKV = symf(pQKV); float* SCO = symf(pSCO);
    float* S = symf(pS); float* SUMS = symf(pSUMS);

    cudaMemsetAsync(pOUTD, 0, NN * sizeof(int));
    cudaMemsetAsync(pIND,  0, NN * sizeof(int));
    cudaMemsetAsync(pS,    0, KEIG * CC * sizeof(float));
    cudaMemsetAsync(pSUMS, 0, 6 * CC * sizeof(float));

    k_count<<<EE / 256, 256>>>(src, dst);
    k_dis<<<NN / 256, 256>>>();
    k_scan<<<1, 256>>>();
    k_fill<<<EE / 256, 256>>>(src, dst);

    auto GEMM = [&](const float* A, const float* W, const float* bias, const float* res,
                    float* C, int M, int Kd, int Cout, int relu, int accum) {
        dim3 g(M / 128, Cout / 128);
        k_gemm<<<g, 256>>>(A, W, bias, res, C, M, Kd, Cout, relu, accum);
    };

    // ---- spatial MLP -> x_sp (T0) ----
    GEMM(x, w_spa1, b_spa1, nullptr, HID, NN, 128, 128, 1, 0);
    GEMM(HID, w_spa2, b_spa2, nullptr, T0, NN, 128, 128, 0, 0);

    // ---- Chebyshev conv ----
    GEMM(T0, cheb_w, nullptr, nullptr, LOC, NN, 128, 128, 0, 0);
    k_cheb<<<NN / 8, 256>>>(T0, nullptr, T1, lamMax, 0);
    GEMM(T1, cheb_w + 1 * 128 * 128, nullptr, nullptr, LOC, NN, 128, 128, 0, 1);
    {
        float* prev = T0; float* cur = T1; float* nxt = T2;
        for (int k = 2; k < KCH; k++) {
            k_cheb<<<NN / 8, 256>>>(cur, prev, nxt, lamMax, 1);
            GEMM(nxt, cheb_w + (size_t)k * 128 * 128, nullptr, nullptr, LOC, NN, 128, 128, 0, 1);
            float* t = prev; prev = cur; cur = nxt; nxt = t;
        }
    }

    // ---- spectral branch ----
    GEMM(x, w_spe1, b_spe1, nullptr, HID, NN, 128, 128, 1, 0);
    GEMM(HID, w_spe2, b_spe2, nullptr, XSP, NN, 128, 128, 0, 0);
    GEMM(XSP, w_proj, nullptr, nullptr, HPJ, NN, 128, 128, 0, 0);
    k_utgemm<<<NN / 128, 256>>>(U, HPJ);
    k_scaleS<<<(KEIG * CC) / 256, 256>>>(Lambda, gamma);
    GEMM(U, S, nullptr, nullptr, LOC, NN, 128, 128, 0, 1);

    k_pre1<<<(NN * CC / 4) / 256, 256>>>(x, cheb_b);
    k_bnstats<<<256, 256>>>(PRE, SUMS, SUMS + 128);

    // ---- global attention ----
    GEMM(x, w_qkv, b_qkv, nullptr, QKV, NN, 128, 384, 0, 0);
    {
        dim3 gqk(4, 4, BBG * HH);
        k_qk<<<gqk, 256>>>(QKV, SCO);
        k_softmax<<<(BBG * HH * NGR) / 8, 256>>>(SCO);
        dim3 gpv(4, BBG * HH);
        k_pv<<<gpv, 256>>>(QKV, SCO, XSP);
    }
    GEMM(XSP, w_out, b_out, x, HPJ, NN, 128, 128, 0, 0);
    k_bnstats<<<256, 256>>>(HPJ, SUMS + 256, SUMS + 384);

    k_bnfin<<<1, 128>>>(SUMS,       SUMS + 128, bn1w, bn1b, symf(pAB),       symf(pAB) + 128);
    k_bnfin<<<1, 128>>>(SUMS + 256, SUMS + 384, bn2w, bn2b, symf(pAB) + 256, symf(pAB) + 384);
    k_combine<<<(NN * CC / 4) / 256, 256>>>(HPJ);

    // ---- final MLP ----
    GEMM(LOC, mlp_w1, mlp_b1, nullptr, HID, NN, 128, 256, 1, 0);
    GEMM(HID, mlp_w2, mlp_b2, LOC, T0, NN, 256, 128, 0, 0);

    // ---- BN3 -> output ----
    k_bnstats<<<256, 256>>>(T0, SUMS + 512, SUMS + 640);
    k_bnfin<<<1, 128>>>(SUMS + 512, SUMS + 640, bn3w, bn3b, symf(pAB) + 512, symf(pAB) + 640);
    k_final<<<(NN * CC / 4) / 256, 256>>>(T0, out);
}

// round 5
// speedup vs baseline: 2.0634x; 1.2784x over previous
#include <cuda_runtime.h>
#include <math.h>
#include <stdint.h>

#define NN   32768
#define CC   128
#define EE   524288
#define BBG  64
#define NGR  512
#define HH   4
#define DH   32
#define KEIG 128
#define KCH  5
#define BN_EPS 1e-5f

__device__ float g_big [NN * 640];
__device__ float g_hid [NN * 2 * CC];
__device__ float g_loc [NN * CC];
__device__ float g_xspec[NN * CC];
__device__ float g_hproj[NN * CC];
__device__ float g_qkv [NN * 3 * CC];
__device__ float g_S   [KEIG * CC];
__device__ float g_dis [NN];
__device__ int   g_outdeg[NN];
__device__ int   g_indeg [NN];
__device__ int   g_rowptr[NN + 1];
__device__ int   g_cursor[NN];
__device__ int   g_ecol  [EE];
__device__ float g_sums[6 * CC];
__device__ float g_ab  [6 * CC];

__device__ __forceinline__ float cvt_tf32(float x) {
    float r;
    asm("cvt.rna.tf32.f32 %0, %1;" : "=f"(r) : "f"(x));
    return r;
}
__device__ __forceinline__ float4 cvt_tf32_4(float4 v) {
    v.x = cvt_tf32(v.x); v.y = cvt_tf32(v.y);
    v.z = cvt_tf32(v.z); v.w = cvt_tf32(v.w);
    return v;
}
#define MMA_TF32(d0,d1,d2,d3,a0,a1,a2,a3,b0,b1)                               \
    asm volatile("mma.sync.aligned.m16n8k8.row.col.f32.tf32.tf32.f32 "        \
        "{%0,%1,%2,%3}, {%4,%5,%6,%7}, {%8,%9}, {%0,%1,%2,%3};"               \
        : "+f"(d0), "+f"(d1), "+f"(d2), "+f"(d3)                              \
        : "r"(a0), "r"(a1), "r"(a2), "r"(a3), "r"(b0), "r"(b1))

__global__ void k_count(const int* __restrict__ src, const int* __restrict__ dst) {
    int e = blockIdx.x * blockDim.x + threadIdx.x;
    if (e < EE) {
        atomicAdd(&g_outdeg[src[e]], 1);
        atomicAdd(&g_indeg [dst[e]], 1);
    }
}

__global__ void k_dis() {
    int n = blockIdx.x * blockDim.x + threadIdx.x;
    if (n < NN) {
        int d = g_outdeg[n];
        g_dis[n] = (d > 0) ? rsqrtf((float)d) : 0.0f;
    }
}

__global__ void k_scan() {
    __shared__ int tot[256];
    __shared__ int base[257];
    int t = threadIdx.x;
    int s = 0;
    for (int i = 0; i < 128; i++) s += g_indeg[t * 128 + i];
    tot[t] = s;
    __syncthreads();
    if (t == 0) {
        int a = 0;
        for (int i = 0; i < 256; i++) { base[i] = a; a += tot[i]; }
        base[256] = a;
    }
    __syncthreads();
    int a = base[t];
    for (int i = 0; i < 128; i++) {
        int n = t * 128 + i;
        g_rowptr[n] = a;
        g_cursor[n] = a;
        a += g_indeg[n];
    }
    if (t == 0) g_rowptr[NN] = base[256];
}

__global__ void k_fill(const int* __restrict__ src, const int* __restrict__ dst) {
    int e = blockIdx.x * blockDim.x + threadIdx.x;
    if (e < EE) {
        int p = atomicAdd(&g_cursor[dst[e]], 1);
        g_ecol[p] = src[e];
    }
}

#define AS_STR 20
#define BS_STR 136
__global__ __launch_bounds__(256) void k_gemm(
    const float* __restrict__ A, const float* __restrict__ W,
    const float* __restrict__ bias, const float* __restrict__ res,
    float* __restrict__ C, int M, int Kd, int ldA, int Cout, int ldC,
    int relu, int accum, float* __restrict__ sums)
{
    __shared__ float As[128 * AS_STR];
    __shared__ float Bs[16 * BS_STR];
    int bm = blockIdx.x * 128;
    int bn = blockIdx.y * 128;
    int tid = threadIdx.x;
    int warp = tid >> 5, lane = tid & 31;
    int wm = (warp >> 1) * 32;
    int wn = (warp & 1) * 64;
    int lr = lane >> 2;
    int lc = lane & 3;

    float acc[2][8][4];
#pragma unroll
    for (int i = 0; i < 2; i++)
#pragma unroll
        for (int j = 0; j < 8; j++)
#pragma unroll
            for (int q = 0; q < 4; q++) acc[i][j][q] = 0.0f;

    for (int k0 = 0; k0 < Kd; k0 += 16) {
#pragma unroll
        for (int l = 0; l < 2; l++) {
            int i = tid + l * 256;
            int row = i >> 2, c4 = (i & 3) * 4;
            float4 v = *(const float4*)&A[(size_t)(bm + row) * ldA + k0 + c4];
            *(float4*)&As[row * AS_STR + c4] = cvt_tf32_4(v);
        }
#pragma unroll
        for (int l = 0; l < 2; l++) {
            int i = tid + l * 256;
            int row = i >> 5, c4 = (i & 31) * 4;
            float4 v = *(const float4*)&W[(size_t)(k0 + row) * Cout + bn + c4];
            *(float4*)&Bs[row * BS_STR + c4] = cvt_tf32_4(v);
        }
        __syncthreads();
#pragma unroll
        for (int kk = 0; kk < 16; kk += 8) {
            uint32_t af[2][4], bf[8][2];
#pragma unroll
            for (int mt = 0; mt < 2; mt++) {
                int r = wm + mt * 16 + lr;
                af[mt][0] = __float_as_uint(As[r * AS_STR + kk + lc]);
                af[mt][1] = __float_as_uint(As[(r + 8) * AS_STR + kk + lc]);
                af[mt][2] = __float_as_uint(As[r * AS_STR + kk + lc + 4]);
                af[mt][3] = __float_as_uint(As[(r + 8) * AS_STR + kk + lc + 4]);
            }
#pragma unroll
            for (int nt = 0; nt < 8; nt++) {
                int c = wn + nt * 8 + lr;
                bf[nt][0] = __float_as_uint(Bs[(kk + lc) * BS_STR + c]);
                bf[nt][1] = __float_as_uint(Bs[(kk + lc + 4) * BS_STR + c]);
            }
#pragma unroll
            for (int mt = 0; mt < 2; mt++)
#pragma unroll
                for (int nt = 0; nt < 8; nt++)
                    MMA_TF32(acc[mt][nt][0], acc[mt][nt][1], acc[mt][nt][2], acc[mt][nt][3],
                             af[mt][0], af[mt][1], af[mt][2], af[mt][3],
                             bf[nt][0], bf[nt][1]);
        }
        __syncthreads();
    }

    float csum[16], csq[16];
#pragma unroll
    for (int t = 0; t < 16; t++) { csum[t] = 0.f; csq[t] = 0.f; }

#pragma unroll
    for (int mt = 0; mt < 2; mt++) {
#pragma unroll
        for (int half = 0; half < 2; half++) {
            int row = bm + wm + mt * 16 + lr + half * 8;
            size_t ro = (size_t)row * ldC;
            size_t rr = (size_t)row * Cout;
#pragma unroll
            for (int nt = 0; nt < 8; nt++) {
                int col = bn + wn + nt * 8 + lc * 2;
                float v0 = acc[mt][nt][half * 2];
                float v1 = acc[mt][nt][half * 2 + 1];
                if (bias) { v0 += bias[col]; v1 += bias[col + 1]; }
                if (res)  { v0 += res[rr + col]; v1 += res[rr + col + 1]; }
                if (accum){ v0 += C[ro + col];  v1 += C[ro + col + 1]; }
                if (relu) { v0 = fmaxf(v0, 0.f); v1 = fmaxf(v1, 0.f); }
                if (sums) {
                    csum[nt * 2]     += v0; csq[nt * 2]     = fmaf(v0, v0, csq[nt * 2]);
                    csum[nt * 2 + 1] += v1; csq[nt * 2 + 1] = fmaf(v1, v1, csq[nt * 2 + 1]);
                }
                *(float2*)&C[ro + col] = make_float2(v0, v1);
            }
        }
    }

    if (sums) {
        if (tid < 256) As[tid] = 0.f;
        __syncthreads();
#pragma unroll
        for (int t = 0; t < 16; t++) {
            int col = wn + (t >> 1) * 8 + lc * 2 + (t & 1);
            atomicAdd(&As[col], csum[t]);
            atomicAdd(&As[128 + col], csq[t]);
        }
        __syncthreads();
        if (tid < 128) {
            atomicAdd(&sums[tid],       As[tid]);
            atomicAdd(&sums[tid + 128], As[tid + 128]);
        }
    }
}

__global__ void k_cheb(const float* __restrict__ Vc, const float* __restrict__ Vp,
                       float* __restrict__ Vo, const float* __restrict__ lam,
                       int mode, int ld)
{
    int gw = (blockIdx.x * blockDim.x + threadIdx.x) >> 5;
    int lane = threadIdx.x & 31;
    if (gw >= NN) return;
    float sc = 2.0f / lam[0];
    int beg = g_rowptr[gw], end = g_rowptr[gw + 1];
    float dn = g_dis[gw];
    float4 acc = make_float4(0.f, 0.f, 0.f, 0.f);
    for (int j = beg; j < end; j++) {
        int s = g_ecol[j];
        float w = dn * g_dis[s];
        float4 v = *(const float4*)&Vc[(size_t)s * ld + lane * 4];
        acc.x = fmaf(w, v.x, acc.x);
        acc.y = fmaf(w, v.y, acc.y);
        acc.z = fmaf(w, v.z, acc.z);
        acc.w = fmaf(w, v.w, acc.w);
    }
    float4 vc = *(const float4*)&Vc[(size_t)gw * ld + lane * 4];
    float sm1 = sc - 1.0f;
    float4 r;
    r.x = sm1 * vc.x - sc * acc.x;
    r.y = sm1 * vc.y - sc * acc.y;
    r.z = sm1 * vc.z - sc * acc.z;
    r.w = sm1 * vc.w - sc * acc.w;
    if (mode) {
        float4 vp = *(const float4*)&Vp[(size_t)gw * ld + lane * 4];
        r.x = 2.f * r.x - vp.x; r.y = 2.f * r.y - vp.y;
        r.z = 2.f * r.z - vp.z; r.w = 2.f * r.w - vp.w;
    }
    *(float4*)&Vo[(size_t)gw * ld + lane * 4] = r;
}

#define US_STR 132
__global__ __launch_bounds__(256) void k_utgemm_tc(const float* __restrict__ U,
                                                   const float* __restrict__ Hp)
{
    __shared__ float Us[16 * US_STR];
    __shared__ float Hs[16 * US_STR];
    int n0 = blockIdx.x * 256;
    int tid = threadIdx.x;
    int warp = tid >> 5, lane = tid & 31;
    int wm = (warp >> 1) * 32, wn = (warp & 1) * 64;
    int lr = lane >> 2, lc = lane & 3;

    float acc[2][8][4];
#pragma unroll
    for (int i = 0; i < 2; i++)
#pragma unroll
        for (int j = 0; j < 8; j++)
#pragma unroll
            for (int q = 0; q < 4; q++) acc[i][j][q] = 0.f;

    for (int nb = 0; nb < 256; nb += 16) {
#pragma unroll
        for (int l = 0; l < 2; l++) {
            int i = tid + l * 256;
            int row = i >> 5, c4 = (i & 31) * 4;
            *(float4*)&Us[row * US_STR + c4] =
                cvt_tf32_4(*(const float4*)&U [(size_t)(n0 + nb + row) * 128 + c4]);
            *(float4*)&Hs[row * US_STR + c4] =
                cvt_tf32_4(*(const float4*)&Hp[(size_t)(n0 + nb + row) * 128 + c4]);
        }
        __syncthreads();
#pragma unroll
        for (int kk = 0; kk < 16; kk += 8) {
            uint32_t af[2][4], bf[8][2];
#pragma unroll
            for (int mt = 0; mt < 2; mt++) {
                int m = wm + mt * 16 + lr;
                af[mt][0] = __float_as_uint(Us[(kk + lc) * US_STR + m]);
                af[mt][1] = __float_as_uint(Us[(kk + lc) * US_STR + m + 8]);
                af[mt][2] = __float_as_uint(Us[(kk + lc + 4) * US_STR + m]);
                af[mt][3] = __float_as_uint(Us[(kk + lc + 4) * US_STR + m + 8]);
            }
#pragma unroll
            for (int nt = 0; nt < 8; nt++) {
                int c = wn + nt * 8 + lr;
                bf[nt][0] = __float_as_uint(Hs[(kk + lc) * US_STR + c]);
                bf[nt][1] = __float_as_uint(Hs[(kk + lc + 4) * US_STR + c]);
            }
#pragma unroll
            for (int mt = 0; mt < 2; mt++)
#pragma unroll
                for (int nt = 0; nt < 8; nt++)
                    MMA_TF32(acc[mt][nt][0], acc[mt][nt][1], acc[mt][nt][2], acc[mt][nt][3],
                             af[mt][0], af[mt][1], af[mt][2], af[mt][3],
                             bf[nt][0], bf[nt][1]);
        }
        __syncthreads();
    }
#pragma unroll
    for (int mt = 0; mt < 2; mt++)
#pragma unroll
        for (int half = 0; half < 2; half++) {
            int row = wm + mt * 16 + lr + half * 8;
#pragma unroll
            for (int nt = 0; nt < 8; nt++) {
                int col = wn + nt * 8 + lc * 2;
                atomicAdd(&g_S[row * 128 + col],     acc[mt][nt][half * 2]);
                atomicAdd(&g_S[row * 128 + col + 1], acc[mt][nt][half * 2 + 1]);
            }
        }
}

__global__ void k_scaleS(const float* __restrict__ Lambda, const float* __restrict__ gamma) {
    int i = blockIdx.x * blockDim.x + threadIdx.x;
    if (i < KEIG * CC) {
        int k = i >> 7;
        float l = Lambda[k];
        g_S[i] *= expf(-gamma[0] * l * l);
    }
}

__global__ void k_bnfin(const float* __restrict__ sum, const float* __restrict__ sq,
                        const float* __restrict__ w, const float* __restrict__ b,
                        float* __restrict__ a, float* __restrict__ bs)
{
    int c = threadIdx.x;
    float mu  = sum[c] * (1.0f / NN);
    float var = sq[c]  * (1.0f / NN) - mu * mu;
    float aa = w[c] * rsqrtf(var + BN_EPS);
    a[c]  = aa;
    bs[c] = b[c] - mu * aa;
}

__global__ void k_combine(const float* __restrict__ pre, const float* __restrict__ h2,
                          float* __restrict__ out0)
{
    int i = blockIdx.x * blockDim.x + threadIdx.x;
    int col4 = (i & 31) * 4;
    float4 p = ((const float4*)pre)[i];
    float4 q = ((const float4*)h2)[i];
    float4 a1 = *(const float4*)&g_ab[col4];
    float4 b1 = *(const float4*)&g_ab[128 + col4];
    float4 a2 = *(const float4*)&g_ab[256 + col4];
    float4 b2 = *(const float4*)&g_ab[384 + col4];
    float4 rv;
    rv.x = fmaf(p.x, a1.x, b1.x) + fmaf(q.x, a2.x, b2.x);
    rv.y = fmaf(p.y, a1.y, b1.y) + fmaf(q.y, a2.y, b2.y);
    rv.z = fmaf(p.z, a1.z, b1.z) + fmaf(q.z, a2.z, b2.z);
    rv.w = fmaf(p.w, a1.w, b1.w) + fmaf(q.w, a2.w, b2.w);
    ((float4*)out0)[i] = rv;
}

__global__ void k_final(const float* __restrict__ X, float* __restrict__ out) {
    int i = blockIdx.x * blockDim.x + threadIdx.x;
    int col4 = (i & 31) * 4;
    float4 v = ((const float4*)X)[i];
    float4 a3 = *(const float4*)&g_ab[512 + col4];
    float4 b3 = *(const float4*)&g_ab[640 + col4];
    float4 rv;
    rv.x = fmaf(v.x, a3.x, b3.x); rv.y = fmaf(v.y, a3.y, b3.y);
    rv.z = fmaf(v.z, a3.z, b3.z); rv.w = fmaf(v.w, a3.w, b3.w);
    ((float4*)out)[i] = rv;
}

#define KV_STR 36
__global__ __launch_bounds__(256) void k_flash(const float* __restrict__ qkv,
                                               float* __restrict__ out)
{
    __shared__ float Ks[128 * KV_STR];
    __shared__ float Vs[128 * KV_STR];
    int bh = blockIdx.y;
    int b = bh >> 2, h = bh & 3;
    int i0 = blockIdx.x * 128;
    int tid = threadIdx.x;
    int warp = tid >> 5, lane = tid & 31;
    int lr = lane >> 2, lc = lane & 3;
    const unsigned FULL = 0xffffffffu;
    const float scl = 0.17677669529663687f;

    const float* qb = qkv + (size_t)(b * NGR + i0 + warp * 16) * 384 + h * DH;
    uint32_t qf[4][4];
#pragma unroll
    for (int kc = 0; kc < 4; kc++) {
        qf[kc][0] = __float_as_uint(cvt_tf32(qb[(size_t)lr * 384 + kc * 8 + lc]));
        qf[kc][1] = __float_as_uint(cvt_tf32(qb[(size_t)(lr + 8) * 384 + kc * 8 + lc]));
        qf[kc][2] = __float_as_uint(cvt_tf32(qb[(size_t)lr * 384 + kc * 8 + lc + 4]));
        qf[kc][3] = __float_as_uint(cvt_tf32(qb[(size_t)(lr + 8) * 384 + kc * 8 + lc + 4]));
    }

    float m0 = -1e30f, m1 = -1e30f, l0 = 0.f, l1 = 0.f;
    float o[4][4];
#pragma unroll
    for (int nt = 0; nt < 4; nt++)
#pragma unroll
        for (int q = 0; q < 4; q++) o[nt][q] = 0.f;

    int lsrcA = (lane & ~3) | (lc >> 1);
    int lsrcB = lsrcA + 2;
    bool odd = (lc & 1);

    for (int j0 = 0; j0 < NGR; j0 += 128) {
        __syncthreads();
        const float* kb = qkv + (size_t)(b * NGR + j0) * 384 + 128 + h * DH;
        const float* vb = qkv + (size_t)(b * NGR + j0) * 384 + 256 + h * DH;
#pragma unroll
        for (int l4 = 0; l4 < 4; l4++) {
            int i = tid + l4 * 256;
            int row = i >> 3, c4 = (i & 7) * 4;
            *(float4*)&Ks[row * KV_STR + c4] =
                cvt_tf32_4(*(const float4*)&kb[(size_t)row * 384 + c4]);
            *(float4*)&Vs[row * KV_STR + c4] =
                cvt_tf32_4(*(const float4*)&vb[(size_t)row * 384 + c4]);
        }
        __syncthreads();

        float s[16][4];
#pragma unroll
        for (int g = 0; g < 16; g++)
#pragma unroll
            for (int q = 0; q < 4; q++) s[g][q] = 0.f;
#pragma unroll
        for (int kc = 0; kc < 4; kc++) {
#pragma unroll
            for (int g = 0; g < 16; g++) {
                int c = g * 8 + lr;
                uint32_t b0 = __float_as_uint(Ks[c * KV_STR + kc * 8 + lc]);
                uint32_t b1 = __float_as_uint(Ks[c * KV_STR + kc * 8 + lc + 4]);
                MMA_TF32(s[g][0], s[g][1], s[g][2], s[g][3],
                         qf[kc][0], qf[kc][1], qf[kc][2], qf[kc][3], b0, b1);
            }
        }

        float mn0 = m0, mn1 = m1;
#pragma unroll
        for (int g = 0; g < 16; g++) {
            s[g][0] *= scl; s[g][1] *= scl; s[g][2] *= scl; s[g][3] *= scl;
            mn0 = fmaxf(mn0, fmaxf(s[g][0], s[g][1]));
            mn1 = fmaxf(mn1, fmaxf(s[g][2], s[g][3]));
        }
        mn0 = fmaxf(mn0, __shfl_xor_sync(FULL, mn0, 1));
        mn0 = fmaxf(mn0, __shfl_xor_sync(FULL, mn0, 2));
        mn1 = fmaxf(mn1, __shfl_xor_sync(FULL, mn1, 1));
        mn1 = fmaxf(mn1, __shfl_xor_sync(FULL, mn1, 2));
        float al0 = __expf(m0 - mn0);
        float al1 = __expf(m1 - mn1);
        m0 = mn0; m1 = mn1;
        float rs0 = 0.f, rs1 = 0.f;
#pragma unroll
        for (int g = 0; g < 16; g++) {
            s[g][0] = __expf(s[g][0] - mn0);
            s[g][1] = __expf(s[g][1] - mn0);
            s[g][2] = __expf(s[g][2] - mn1);
            s[g][3] = __expf(s[g][3] - mn1);
            rs0 += s[g][0] + s[g][1];
            rs1 += s[g][2] + s[g][3];
            s[g][0] = cvt_tf32(s[g][0]); s[g][1] = cvt_tf32(s[g][1]);
            s[g][2] = cvt_tf32(s[g][2]); s[g][3] = cvt_tf32(s[g][3]);
        }
        rs0 += __shfl_xor_sync(FULL, rs0, 1);
        rs0 += __shfl_xor_sync(FULL, rs0, 2);
        rs1 += __shfl_xor_sync(FULL, rs1, 1);
        rs1 += __shfl_xor_sync(FULL, rs1, 2);
        l0 = l0 * al0 + rs0;
        l1 = l1 * al1 + rs1;
#pragma unroll
        for (int nt = 0; nt < 4; nt++) {
            o[nt][0] *= al0; o[nt][1] *= al0;
            o[nt][2] *= al1; o[nt][3] *= al1;
        }

#pragma unroll
        for (int g = 0; g < 16; g++) {
            float t0A = __shfl_sync(FULL, s[g][0], lsrcA);
            float t1A = __shfl_sync(FULL, s[g][1], lsrcA);
            float t2A = __shfl_sync(FULL, s[g][2], lsrcA);
            float t3A = __shfl_sync(FULL, s[g][3], lsrcA);
            float t0B = __shfl_sync(FULL, s[g][0], lsrcB);
            float t1B = __shfl_sync(FULL, s[g][1], lsrcB);
            float t2B = __shfl_sync(FULL, s[g][2], lsrcB);
            float t3B = __shfl_sync(FULL, s[g][3], lsrcB);
            uint32_t a0 = __float_as_uint(odd ? t1A : t0A);
            uint32_t a1 = __float_as_uint(odd ? t3A : t2A);
            uint32_t a2 = __float_as_uint(odd ? t1B : t0B);
            uint32_t a3 = __float_as_uint(odd ? t3B : t2B);
#pragma unroll
            for (int nt = 0; nt < 4; nt++) {
                uint32_t b0 = __float_as_uint(Vs[(g * 8 + lc) * KV_STR + nt * 8 + lr]);
                uint32_t b1 = __float_as_uint(Vs[(g * 8 + lc + 4) * KV_STR + nt * 8 + lr]);
                MMA_TF32(o[nt][0], o[nt][1], o[nt][2], o[nt][3],
                         a0, a1, a2, a3, b0, b1);
            }
        }
    }

    float inv0 = 1.0f / l0, inv1 = 1.0f / l1;
    int row0 = b * NGR + i0 + warp * 16 + lr;
#pragma unroll
    for (int nt = 0; nt < 4; nt++) {
        int col = h * DH + nt * 8 + lc * 2;
        *(float2*)&out[(size_t)row0 * CC + col] =
            make_float2(o[nt][0] * inv0, o[nt][1] * inv0);
        *(float2*)&out[(size_t)(row0 + 8) * CC + col] =
            make_float2(o[nt][2] * inv1, o[nt][3] * inv1);
    }
}

static float* symf(const void* p) { return (float*)p; }

extern "C" void kernel_launch(void* const* d_in, const int* in_sizes, int n_in,
                              void* d_out, int out_size)
{
    const float* x      = (const float*)d_in[0];
    const float* U      = (const float*)d_in[1];
    const float* Lambda = (const float*)d_in[2];
    const float* lamMax = (const float*)d_in[3];
    const float* w_spa1 = (const float*)d_in[4];  const float* b_spa1 = (const float*)d_in[5];
    const float* w_spa2 = (const float*)d_in[6];  const float* b_spa2 = (const float*)d_in[7];
    const float* w_spe1 = (const float*)d_in[8];  const float* b_spe1 = (const float*)d_in[9];
    const float* w_spe2 = (const float*)d_in[10]; const float* b_spe2 = (const float*)d_in[11];
    const float* cheb_w = (const float*)d_in[12]; const float* cheb_b = (const float*)d_in[13];
    const float* gamma  = (const float*)d_in[14]; const float* w_proj = (const float*)d_in[15];
    const float* w_qkv  = (const float*)d_in[16]; const float* b_qkv  = (const float*)d_in[17];
    const float* w_out  = (const float*)d_in[18]; const float* b_out  = (const float*)d_in[19];
    const float* mlp_w1 = (const float*)d_in[20]; const float* mlp_b1 = (const float*)d_in[21];
    const float* mlp_w2 = (const float*)d_in[22]; const float* mlp_b2 = (const float*)d_in[23];
    const float* bn1w = (const float*)d_in[24]; const float* bn1b = (const float*)d_in[25];
    const float* bn2w = (const float*)d_in[26]; const float* bn2b = (const float*)d_in[27];
    const float* bn3w = (const float*)d_in[28]; const float* bn3b = (const float*)d_in[29];
    const int*   ei   = (const int*)d_in[30];
    const int* src = ei;
    const int* dst = ei + EE;
    float* out = (float*)d_out;

    void *pBIG, *pHID, *pLOC, *pXSP, *pHPJ, *pQKV, *pS, *pOUTD, *pIND, *pSUMS, *pAB;
    cudaGetSymbolAddress(&pBIG, g_big);   cudaGetSymbolAddress(&pHID, g_hid);
    cudaGetSymbolAddress(&pLOC, g_loc);   cudaGetSymbolAddress(&pXSP, g_xspec);
    cudaGetSymbolAddress(&pHPJ, g_hproj); cudaGetSymbolAddress(&pQKV, g_qkv);
    cudaGetSymbolAddress(&pS, g_S);
    cudaGetSymbolAddress(&pOUTD, g_outdeg); cudaGetSymbolAddress(&pIND, g_indeg);
    cudaGetSymbolAddress(&pSUMS, g_sums);   cudaGetSymbolAddress(&pAB, g_ab);

    float* BIG = symf(pBIG); float* HID = symf(pHID); float* LOC = symf(pLOC);
    float* XSP = symf(pXSP); float* HPJ = symf(pHPJ); float* QKV = symf(pQKV);
    float* SUMS = symf(pSUMS);

    cudaMemsetAsync(pOUTD, 0, NN * sizeof(int));
    cudaMemsetAsync(pIND,  0, NN * sizeof(int));
    cudaMemsetAsync(pS,    0, KEIG * CC * sizeof(float));
    cudaMemsetAsync(pSUMS, 0, 6 * CC * sizeof(float));

    k_count<<<EE / 256, 256>>>(src, dst);
    k_dis<<<NN / 256, 256>>>();
    k_scan<<<1, 256>>>();
    k_fill<<<EE / 256, 256>>>(src, dst);

    auto GEMM = [&](const float* A, const float* W, const float* bias, const float* res,
                    float* C, int M, int Kd, int ldA, int Cout, int ldC,
                    int relu, int accum, float* sums) {
        dim3 g(M / 128, Cout / 128);
        k_gemm<<<g, 256>>>(A, W, bias, res, C, M, Kd, ldA, Cout, ldC, relu, accum, sums);
    };

    // ---- spatial MLP -> Tx0 (BIG col 0, ld 640) ----
    GEMM(x, w_spa1, b_spa1, nullptr, HID, NN, 128, 128, 128, 128, 1, 0, nullptr);
    GEMM(HID, w_spa2, b_spa2, nullptr, BIG, NN, 128, 128, 128, 640, 0, 0, nullptr);

    // ---- Chebyshev recurrence into BIG columns ----
    k_cheb<<<NN / 8, 256>>>(BIG, nullptr, BIG + 128, lamMax, 0, 640);
    for (int k = 2; k < KCH; k++)
        k_cheb<<<NN / 8, 256>>>(BIG + (k - 1) * 128, BIG + (k - 2) * 128,
                                BIG + k * 128, lamMax, 1, 640);
    // one wide GEMM over K=640
    GEMM(BIG, cheb_w, nullptr, nullptr, LOC, NN, 640, 640, 128, 128, 0, 0, nullptr);

    // ---- spectral branch ----
    GEMM(x, w_spe1, b_spe1, nullptr, HID, NN, 128, 128, 128, 128, 1, 0, nullptr);
    GEMM(HID, w_spe2, b_spe2, nullptr, XSP, NN, 128, 128, 128, 128, 0, 0, nullptr);
    GEMM(XSP, w_proj, nullptr, nullptr, HPJ, NN, 128, 128, 128, 128, 0, 0, nullptr);
    k_utgemm_tc<<<NN / 256, 256>>>(U, HPJ);
    k_scaleS<<<(KEIG * CC) / 256, 256>>>(Lambda, gamma);
    // LOC = pre1 = U@S + LOC + cheb_b + x  (fused BN1 stats)
    GEMM(U, symf(pS), cheb_b, x, LOC, NN, 128, 128, 128, 128, 0, 1, SUMS);

    // ---- global attention (fused flash) ----
    GEMM(x, w_qkv, b_qkv, nullptr, QKV, NN, 128, 128, 384, 384, 0, 0, nullptr);
    {
        dim3 gf(NGR / 128, BBG * HH);
        k_flash<<<gf, 256>>>(QKV, XSP);
    }
    // HPJ = h2 = attn@w_out + b_out + x  (fused BN2 stats)
    GEMM(XSP, w_out, b_out, x, HPJ, NN, 128, 128, 128, 128, 0, 0, SUMS + 256);

    k_bnfin<<<1, 128>>>(SUMS,       SUMS + 128, bn1w, bn1b, symf(pAB),       symf(pAB) + 128);
    k_bnfin<<<1, 128>>>(SUMS + 256, SUMS + 384, bn2w, bn2b, symf(pAB) + 256, symf(pAB) + 384);
    k_combine<<<(NN * CC / 4) / 256, 256>>>(LOC, HPJ, XSP);

    // ---- final MLP with residual (fused BN3 stats) ----
    GEMM(XSP, mlp_w1, mlp_b1, nullptr, HID, NN, 128, 128, 256, 256, 1, 0, nullptr);
    GEMM(HID, mlp_w2, mlp_b2, XSP, LOC, NN, 256, 256, 128, 128, 0, 0, SUMS + 512);

    k_bnfin<<<1, 128>>>(SUMS + 512, SUMS + 640, bn3w, bn3b, symf(pAB) + 512, symf(pAB) + 640);
    k_final<<<(NN * CC / 4) / 256, 256>>>(LOC, out);
}

// round 6
// speedup vs baseline: 2.7073x; 1.3120x over previous
#include <cuda_runtime.h>
#include <math.h>
#include <stdint.h>

#define NN   32768
#define CC   128
#define EE   524288
#define BBG  64
#define NGR  512
#define HH   4
#define DH   32
#define KEIG 128
#define KCH  5
#define BN_EPS 1e-5f

// ---------------- static scratch ----------------
__device__ float g_big [NN * 640];
__device__ float g_hid [NN * 2 * CC];     // A-branch: first half; B-branch: second half; MLP: full
__device__ float g_loc [NN * CC];
__device__ float g_xspec[NN * CC];
__device__ float g_hproj[NN * CC];
__device__ float g_att [NN * CC];
__device__ float g_h2  [NN * CC];
__device__ float g_qkv [NN * 3 * CC];
__device__ float g_S   [KEIG * CC];
__device__ float g_dis [NN];
__device__ int   g_outdeg[NN];
__device__ int   g_indeg [NN];
__device__ int   g_rowptr[NN + 1];
__device__ int   g_cursor[NN];
__device__ int   g_ecol  [EE];
__device__ float g_sums[6 * CC];
__device__ float g_ab  [6 * CC];

// pre-rounded (tf32) weights
#define OSPA1 0
#define OSPA2 16384
#define OSPE1 32768
#define OSPE2 49152
#define OPROJ 65536
#define OCHEB 81920
#define OQKV  163840
#define OWOUT 212992
#define OMLP1 229376
#define OMLP2 262144
#define WTOT  294912
__device__ float g_wrd[WTOT];

__device__ __forceinline__ float cvt_tf32(float x) {
    float r;
    asm("cvt.rna.tf32.f32 %0, %1;" : "=f"(r) : "f"(x));
    return r;
}
__device__ __forceinline__ float4 cvt_tf32_4(float4 v) {
    v.x = cvt_tf32(v.x); v.y = cvt_tf32(v.y);
    v.z = cvt_tf32(v.z); v.w = cvt_tf32(v.w);
    return v;
}
#define MMA_TF32(d0,d1,d2,d3,a0,a1,a2,a3,b0,b1)                               \
    asm volatile("mma.sync.aligned.m16n8k8.row.col.f32.tf32.tf32.f32 "        \
        "{%0,%1,%2,%3}, {%4,%5,%6,%7}, {%8,%9}, {%0,%1,%2,%3};"               \
        : "+f"(d0), "+f"(d1), "+f"(d2), "+f"(d3)                              \
        : "r"(a0), "r"(a1), "r"(a2), "r"(a3), "r"(b0), "r"(b1))

#define CP16(dst32, srcp) \
    asm volatile("cp.async.cg.shared.global [%0], [%1], 16;" :: "r"(dst32), "l"(srcp))
#define CPCOMMIT() asm volatile("cp.async.commit_group;")
#define CPWAIT0()  asm volatile("cp.async.wait_group 0;")
#define CPWAIT1()  asm volatile("cp.async.wait_group 1;")

// ---------------- weight pre-rounding ----------------
__global__ void k_roundw(const float* __restrict__ w0, const float* __restrict__ w1,
                         const float* __restrict__ w2, const float* __restrict__ w3,
                         const float* __restrict__ w4, const float* __restrict__ w5,
                         const float* __restrict__ w6, const float* __restrict__ w7,
                         const float* __restrict__ w8, const float* __restrict__ w9)
{
    int i = (blockIdx.x * blockDim.x + threadIdx.x) * 4;
    if (i >= WTOT) return;
    const float* src; int off;
    if      (i < OSPA2) { src = w0; off = OSPA1; }
    else if (i < OSPE1) { src = w1; off = OSPA2; }
    else if (i < OSPE2) { src = w2; off = OSPE1; }
    else if (i < OPROJ) { src = w3; off = OSPE2; }
    else if (i < OCHEB) { src = w4; off = OPROJ; }
    else if (i < OQKV)  { src = w5; off = OCHEB; }
    else if (i < OWOUT) { src = w6; off = OQKV;  }
    else if (i < OMLP1) { src = w7; off = OWOUT; }
    else if (i < OMLP2) { src = w8; off = OMLP1; }
    else                { src = w9; off = OMLP2; }
    float4 v = *(const float4*)&src[i - off];
    *(float4*)&g_wrd[i] = cvt_tf32_4(v);
}

// ---------------- graph preprocessing ----------------
__global__ void k_count(const int* __restrict__ src, const int* __restrict__ dst) {
    int e = blockIdx.x * blockDim.x + threadIdx.x;
    if (e < EE) {
        atomicAdd(&g_outdeg[src[e]], 1);
        atomicAdd(&g_indeg [dst[e]], 1);
    }
}

__global__ void k_dis() {
    int n = blockIdx.x * blockDim.x + threadIdx.x;
    if (n < NN) {
        int d = g_outdeg[n];
        g_dis[n] = (d > 0) ? rsqrtf((float)d) : 0.0f;
    }
}

__global__ void k_scan() {
    __shared__ int tot[256];
    __shared__ int base[257];
    int t = threadIdx.x;
    int s = 0;
    for (int i = 0; i < 128; i++) s += g_indeg[t * 128 + i];
    tot[t] = s;
    __syncthreads();
    if (t == 0) {
        int a = 0;
        for (int i = 0; i < 256; i++) { base[i] = a; a += tot[i]; }
        base[256] = a;
    }
    __syncthreads();
    int a = base[t];
    for (int i = 0; i < 128; i++) {
        int n = t * 128 + i;
        g_rowptr[n] = a;
        g_cursor[n] = a;
        a += g_indeg[n];
    }
    if (t == 0) g_rowptr[NN] = base[256];
}

__global__ void k_fill(const int* __restrict__ src, const int* __restrict__ dst) {
    int e = blockIdx.x * blockDim.x + threadIdx.x;
    if (e < EE) {
        int p = atomicAdd(&g_cursor[dst[e]], 1);
        g_ecol[p] = src[e];
    }
}

// ---------------- tf32 GEMM, cp.async double-buffered ----------------
// W must be pre-rounded to tf32 values; A is rounded at fragment load.
#define AS_STR 20
#define BS_STR 136
#define A_WORDS (128 * AS_STR)
#define B_WORDS (16 * BS_STR)
__global__ __launch_bounds__(256) void k_gemm(
    const float* __restrict__ A, const float* __restrict__ W,
    const float* __restrict__ bias, const float* __restrict__ res,
    float* __restrict__ C, int M, int Kd, int ldA, int Cout, int ldC,
    int relu, int accum, float* __restrict__ sums)
{
    __shared__ float As[2 * A_WORDS];
    __shared__ float Bs[2 * B_WORDS];
    int bm = blockIdx.x * 128;
    int bn = blockIdx.y * 128;
    int tid = threadIdx.x;
    int warp = tid >> 5, lane = tid & 31;
    int wm = (warp >> 1) * 32;
    int wn = (warp & 1) * 64;
    int lr = lane >> 2;
    int lc = lane & 3;

    uint32_t asB = (uint32_t)__cvta_generic_to_shared(As);
    uint32_t bsB = (uint32_t)__cvta_generic_to_shared(Bs);
    int aRow = tid >> 2, aC4 = (tid & 3) * 4;
    int bRow = tid >> 5, bC4 = (tid & 31) * 4;

#define GISSUE(buf, k0) do {                                                        \
    CP16(asB + (uint32_t)((buf) * A_WORDS + aRow * AS_STR + aC4) * 4u,              \
         A + (size_t)(bm + aRow) * ldA + (k0) + aC4);                               \
    CP16(asB + (uint32_t)((buf) * A_WORDS + (aRow + 64) * AS_STR + aC4) * 4u,       \
         A + (size_t)(bm + aRow + 64) * ldA + (k0) + aC4);                          \
    CP16(bsB + (uint32_t)((buf) * B_WORDS + bRow * BS_STR + bC4) * 4u,              \
         W + (size_t)((k0) + bRow) * Cout + bn + bC4);                              \
    CP16(bsB + (uint32_t)((buf) * B_WORDS + (bRow + 8) * BS_STR + bC4) * 4u,        \
         W + (size_t)((k0) + bRow + 8) * Cout + bn + bC4);                          \
    CPCOMMIT(); } while (0)

    float acc[2][8][4];
#pragma unroll
    for (int i = 0; i < 2; i++)
#pragma unroll
        for (int j = 0; j < 8; j++)
#pragma unroll
            for (int q = 0; q < 4; q++) acc[i][j][q] = 0.0f;

    int niter = Kd >> 4;
    GISSUE(0, 0);
    for (int it = 0; it < niter; it++) {
        const float* Ac = As + (it & 1) * A_WORDS;
        const float* Bc = Bs + (it & 1) * B_WORDS;
        if (it + 1 < niter) {
            GISSUE((it + 1) & 1, (it + 1) * 16);
            CPWAIT1();
        } else {
            CPWAIT0();
        }
        __syncthreads();
#pragma unroll
        for (int kk = 0; kk < 16; kk += 8) {
            uint32_t af[2][4], bf[8][2];
#pragma unroll
            for (int mt = 0; mt < 2; mt++) {
                int r = wm + mt * 16 + lr;
                af[mt][0] = __float_as_uint(cvt_tf32(Ac[r * AS_STR + kk + lc]));
                af[mt][1] = __float_as_uint(cvt_tf32(Ac[(r + 8) * AS_STR + kk + lc]));
                af[mt][2] = __float_as_uint(cvt_tf32(Ac[r * AS_STR + kk + lc + 4]));
                af[mt][3] = __float_as_uint(cvt_tf32(Ac[(r + 8) * AS_STR + kk + lc + 4]));
            }
#pragma unroll
            for (int nt = 0; nt < 8; nt++) {
                int c = wn + nt * 8 + lr;
                bf[nt][0] = __float_as_uint(Bc[(kk + lc) * BS_STR + c]);
                bf[nt][1] = __float_as_uint(Bc[(kk + lc + 4) * BS_STR + c]);
            }
#pragma unroll
            for (int mt = 0; mt < 2; mt++)
#pragma unroll
                for (int nt = 0; nt < 8; nt++)
                    MMA_TF32(acc[mt][nt][0], acc[mt][nt][1], acc[mt][nt][2], acc[mt][nt][3],
                             af[mt][0], af[mt][1], af[mt][2], af[mt][3],
                             bf[nt][0], bf[nt][1]);
        }
        __syncthreads();
    }
#undef GISSUE

    float csum[16], csq[16];
#pragma unroll
    for (int t = 0; t < 16; t++) { csum[t] = 0.f; csq[t] = 0.f; }

#pragma unroll
    for (int mt = 0; mt < 2; mt++) {
#pragma unroll
        for (int half = 0; half < 2; half++) {
            int row = bm + wm + mt * 16 + lr + half * 8;
            size_t ro = (size_t)row * ldC;
            size_t rr = (size_t)row * Cout;
#pragma unroll
            for (int nt = 0; nt < 8; nt++) {
                int col = bn + wn + nt * 8 + lc * 2;
                float v0 = acc[mt][nt][half * 2];
                float v1 = acc[mt][nt][half * 2 + 1];
                if (bias) { v0 += bias[col]; v1 += bias[col + 1]; }
                if (res)  { v0 += res[rr + col]; v1 += res[rr + col + 1]; }
                if (accum){ v0 += C[ro + col];  v1 += C[ro + col + 1]; }
                if (relu) { v0 = fmaxf(v0, 0.f); v1 = fmaxf(v1, 0.f); }
                if (sums) {
                    csum[nt * 2]     += v0; csq[nt * 2]     = fmaf(v0, v0, csq[nt * 2]);
                    csum[nt * 2 + 1] += v1; csq[nt * 2 + 1] = fmaf(v1, v1, csq[nt * 2 + 1]);
                }
                *(float2*)&C[ro + col] = make_float2(v0, v1);
            }
        }
    }

    if (sums) {
        if (tid < 256) As[tid] = 0.f;
        __syncthreads();
#pragma unroll
        for (int t = 0; t < 16; t++) {
            int col = wn + (t >> 1) * 8 + lc * 2 + (t & 1);
            atomicAdd(&As[col], csum[t]);
            atomicAdd(&As[128 + col], csq[t]);
        }
        __syncthreads();
        if (tid < 128) {
            atomicAdd(&sums[tid],       As[tid]);
            atomicAdd(&sums[tid + 128], As[tid + 128]);
        }
    }
}

// ---------------- Chebyshev gather ----------------
__global__ void k_cheb(const float* __restrict__ Vc, const float* __restrict__ Vp,
                       float* __restrict__ Vo, const float* __restrict__ lam,
                       int mode, int ld)
{
    int gw = (blockIdx.x * blockDim.x + threadIdx.x) >> 5;
    int lane = threadIdx.x & 31;
    if (gw >= NN) return;
    float sc = 2.0f / lam[0];
    int beg = g_rowptr[gw], end = g_rowptr[gw + 1];
    float dn = g_dis[gw];
    float4 acc = make_float4(0.f, 0.f, 0.f, 0.f);
    for (int j = beg; j < end; j++) {
        int s = g_ecol[j];
        float w = dn * g_dis[s];
        float4 v = *(const float4*)&Vc[(size_t)s * ld + lane * 4];
        acc.x = fmaf(w, v.x, acc.x);
        acc.y = fmaf(w, v.y, acc.y);
        acc.z = fmaf(w, v.z, acc.z);
        acc.w = fmaf(w, v.w, acc.w);
    }
    float4 vc = *(const float4*)&Vc[(size_t)gw * ld + lane * 4];
    float sm1 = sc - 1.0f;
    float4 r;
    r.x = sm1 * vc.x - sc * acc.x;
    r.y = sm1 * vc.y - sc * acc.y;
    r.z = sm1 * vc.z - sc * acc.z;
    r.w = sm1 * vc.w - sc * acc.w;
    if (mode) {
        float4 vp = *(const float4*)&Vp[(size_t)gw * ld + lane * 4];
        r.x = 2.f * r.x - vp.x; r.y = 2.f * r.y - vp.y;
        r.z = 2.f * r.z - vp.z; r.w = 2.f * r.w - vp.w;
    }
    *(float4*)&Vo[(size_t)gw * ld + lane * 4] = r;
}

// ---------------- S = U^T @ Hp (tf32 mma, atomic accumulate) ----------------
#define US_STR 132
__global__ __launch_bounds__(256) void k_utgemm_tc(const float* __restrict__ U,
                                                   const float* __restrict__ Hp)
{
    __shared__ float Us[16 * US_STR];
    __shared__ float Hs[16 * US_STR];
    int n0 = blockIdx.x * 256;
    int tid = threadIdx.x;
    int warp = tid >> 5, lane = tid & 31;
    int wm = (warp >> 1) * 32, wn = (warp & 1) * 64;
    int lr = lane >> 2, lc = lane & 3;

    float acc[2][8][4];
#pragma unroll
    for (int i = 0; i < 2; i++)
#pragma unroll
        for (int j = 0; j < 8; j++)
#pragma unroll
            for (int q = 0; q < 4; q++) acc[i][j][q] = 0.f;

    for (int nb = 0; nb < 256; nb += 16) {
#pragma unroll
        for (int l = 0; l < 2; l++) {
            int i = tid + l * 256;
            int row = i >> 5, c4 = (i & 31) * 4;
            *(float4*)&Us[row * US_STR + c4] =
                cvt_tf32_4(*(const float4*)&U [(size_t)(n0 + nb + row) * 128 + c4]);
            *(float4*)&Hs[row * US_STR + c4] =
                cvt_tf32_4(*(const float4*)&Hp[(size_t)(n0 + nb + row) * 128 + c4]);
        }
        __syncthreads();
#pragma unroll
        for (int kk = 0; kk < 16; kk += 8) {
            uint32_t af[2][4], bf[8][2];
#pragma unroll
            for (int mt = 0; mt < 2; mt++) {
                int m = wm + mt * 16 + lr;
                af[mt][0] = __float_as_uint(Us[(kk + lc) * US_STR + m]);
                af[mt][1] = __float_as_uint(Us[(kk + lc) * US_STR + m + 8]);
                af[mt][2] = __float_as_uint(Us[(kk + lc + 4) * US_STR + m]);
                af[mt][3] = __float_as_uint(Us[(kk + lc + 4) * US_STR + m + 8]);
            }
#pragma unroll
            for (int nt = 0; nt < 8; nt++) {
                int c = wn + nt * 8 + lr;
                bf[nt][0] = __float_as_uint(Hs[(kk + lc) * US_STR + c]);
                bf[nt][1] = __float_as_uint(Hs[(kk + lc + 4) * US_STR + c]);
            }
#pragma unroll
            for (int mt = 0; mt < 2; mt++)
#pragma unroll
                for (int nt = 0; nt < 8; nt++)
                    MMA_TF32(acc[mt][nt][0], acc[mt][nt][1], acc[mt][nt][2], acc[mt][nt][3],
                             af[mt][0], af[mt][1], af[mt][2], af[mt][3],
                             bf[nt][0], bf[nt][1]);
        }
        __syncthreads();
    }
#pragma unroll
    for (int mt = 0; mt < 2; mt++)
#pragma unroll
        for (int half = 0; half < 2; half++) {
            int row = wm + mt * 16 + lr + half * 8;
#pragma unroll
            for (int nt = 0; nt < 8; nt++) {
                int col = wn + nt * 8 + lc * 2;
                atomicAdd(&g_S[row * 128 + col],     acc[mt][nt][half * 2]);
                atomicAdd(&g_S[row * 128 + col + 1], acc[mt][nt][half * 2 + 1]);
            }
        }
}

// scale + round S to tf32 so the final GEMM can load it raw
__global__ void k_scaleS(const float* __restrict__ Lambda, const float* __restrict__ gamma) {
    int i = blockIdx.x * blockDim.x + threadIdx.x;
    if (i < KEIG * CC) {
        int k = i >> 7;
        float l = Lambda[k];
        g_S[i] = cvt_tf32(g_S[i] * expf(-gamma[0] * l * l));
    }
}

// ---------------- BN finalize / elementwise ----------------
__global__ void k_bnfin(const float* __restrict__ sum, const float* __restrict__ sq,
                        const float* __restrict__ w, const float* __restrict__ b,
                        float* __restrict__ a, float* __restrict__ bs)
{
    int c = threadIdx.x;
    float mu  = sum[c] * (1.0f / NN);
    float var = sq[c]  * (1.0f / NN) - mu * mu;
    float aa = w[c] * rsqrtf(var + BN_EPS);
    a[c]  = aa;
    bs[c] = b[c] - mu * aa;
}

__global__ void k_combine(const float* __restrict__ pre, const float* __restrict__ h2,
                          float* __restrict__ out0)
{
    int i = blockIdx.x * blockDim.x + threadIdx.x;
    int col4 = (i & 31) * 4;
    float4 p = ((const float4*)pre)[i];
    float4 q = ((const float4*)h2)[i];
    float4 a1 = *(const float4*)&g_ab[col4];
    float4 b1 = *(const float4*)&g_ab[128 + col4];
    float4 a2 = *(const float4*)&g_ab[256 + col4];
    float4 b2 = *(const float4*)&g_ab[384 + col4];
    float4 rv;
    rv.x = fmaf(p.x, a1.x, b1.x) + fmaf(q.x, a2.x, b2.x);
    rv.y = fmaf(p.y, a1.y, b1.y) + fmaf(q.y, a2.y, b2.y);
    rv.z = fmaf(p.z, a1.z, b1.z) + fmaf(q.z, a2.z, b2.z);
    rv.w = fmaf(p.w, a1.w, b1.w) + fmaf(q.w, a2.w, b2.w);
    ((float4*)out0)[i] = rv;
}

__global__ void k_final(const float* __restrict__ X, float* __restrict__ out) {
    int i = blockIdx.x * blockDim.x + threadIdx.x;
    int col4 = (i & 31) * 4;
    float4 v = ((const float4*)X)[i];
    float4 a3 = *(const float4*)&g_ab[512 + col4];
    float4 b3 = *(const float4*)&g_ab[640 + col4];
    float4 rv;
    rv.x = fmaf(v.x, a3.x, b3.x); rv.y = fmaf(v.y, a3.y, b3.y);
    rv.z = fmaf(v.z, a3.z, b3.z); rv.w = fmaf(v.w, a3.w, b3.w);
    ((float4*)out)[i] = rv;
}

// ---------------- fused flash attention ----------------
#define KV_STR 36
__global__ __launch_bounds__(256) void k_flash(const float* __restrict__ qkv,
                                               float* __restrict__ out)
{
    __shared__ float Ks[128 * KV_STR];
    __shared__ float Vs[128 * KV_STR];
    int bh = blockIdx.y;
    int b = bh >> 2, h = bh & 3;
    int i0 = blockIdx.x * 128;
    int tid = threadIdx.x;
    int warp = tid >> 5, lane = tid & 31;
    int lr = lane >> 2, lc = lane & 3;
    const unsigned FULL = 0xffffffffu;
    const float scl = 0.17677669529663687f;

    const float* qb = qkv + (size_t)(b * NGR + i0 + warp * 16) * 384 + h * DH;
    uint32_t qf[4][4];
#pragma unroll
    for (int kc = 0; kc < 4; kc++) {
        qf[kc][0] = __float_as_uint(cvt_tf32(qb[(size_t)lr * 384 + kc * 8 + lc]));
        qf[kc][1] = __float_as_uint(cvt_tf32(qb[(size_t)(lr + 8) * 384 + kc * 8 + lc]));
        qf[kc][2] = __float_as_uint(cvt_tf32(qb[(size_t)lr * 384 + kc * 8 + lc + 4]));
        qf[kc][3] = __float_as_uint(cvt_tf32(qb[(size_t)(lr + 8) * 384 + kc * 8 + lc + 4]));
    }

    float m0 = -1e30f, m1 = -1e30f, l0 = 0.f, l1 = 0.f;
    float o[4][4];
#pragma unroll
    for (int nt = 0; nt < 4; nt++)
#pragma unroll
        for (int q = 0; q < 4; q++) o[nt][q] = 0.f;

    int lsrcA = (lane & ~3) | (lc >> 1);
    int lsrcB = lsrcA + 2;
    bool odd = (lc & 1);

    for (int j0 = 0; j0 < NGR; j0 += 128) {
        __syncthreads();
        const float* kb = qkv + (size_t)(b * NGR + j0) * 384 + 128 + h * DH;
        const float* vb = qkv + (size_t)(b * NGR + j0) * 384 + 256 + h * DH;
#pragma unroll
        for (int l4 = 0; l4 < 4; l4++) {
            int i = tid + l4 * 256;
            int row = i >> 3, c4 = (i & 7) * 4;
            *(float4*)&Ks[row * KV_STR + c4] =
                cvt_tf32_4(*(const float4*)&kb[(size_t)row * 384 + c4]);
            *(float4*)&Vs[row * KV_STR + c4] =
                cvt_tf32_4(*(const float4*)&vb[(size_t)row * 384 + c4]);
        }
        __syncthreads();

        float s[16][4];
#pragma unroll
        for (int g = 0; g < 16; g++)
#pragma unroll
            for (int q = 0; q < 4; q++) s[g][q] = 0.f;
#pragma unroll
        for (int kc = 0; kc < 4; kc++) {
#pragma unroll
            for (int g = 0; g < 16; g++) {
                int c = g * 8 + lr;
                uint32_t b0 = __float_as_uint(Ks[c * KV_STR + kc * 8 + lc]);
                uint32_t b1 = __float_as_uint(Ks[c * KV_STR + kc * 8 + lc + 4]);
                MMA_TF32(s[g][0], s[g][1], s[g][2], s[g][3],
                         qf[kc][0], qf[kc][1], qf[kc][2], qf[kc][3], b0, b1);
            }
        }

        float mn0 = m0, mn1 = m1;
#pragma unroll
        for (int g = 0; g < 16; g++) {
            s[g][0] *= scl; s[g][1] *= scl; s[g][2] *= scl; s[g][3] *= scl;
            mn0 = fmaxf(mn0, fmaxf(s[g][0], s[g][1]));
            mn1 = fmaxf(mn1, fmaxf(s[g][2], s[g][3]));
        }
        mn0 = fmaxf(mn0, __shfl_xor_sync(FULL, mn0, 1));
        mn0 = fmaxf(mn0, __shfl_xor_sync(FULL, mn0, 2));
        mn1 = fmaxf(mn1, __shfl_xor_sync(FULL, mn1, 1));
        mn1 = fmaxf(mn1, __shfl_xor_sync(FULL, mn1, 2));
        float al0 = __expf(m0 - mn0);
        float al1 = __expf(m1 - mn1);
        m0 = mn0; m1 = mn1;
        float rs0 = 0.f, rs1 = 0.f;
#pragma unroll
        for (int g = 0; g < 16; g++) {
            s[g][0] = __expf(s[g][0] - mn0);
            s[g][1] = __expf(s[g][1] - mn0);
            s[g][2] = __expf(s[g][2] - mn1);
            s[g][3] = __expf(s[g][3] - mn1);
            rs0 += s[g][0] + s[g][1];
            rs1 += s[g][2] + s[g][3];
            s[g][0] = cvt_tf32(s[g][0]); s[g][1] = cvt_tf32(s[g][1]);
            s[g][2] = cvt_tf32(s[g][2]); s[g][3] = cvt_tf32(s[g][3]);
        }
        rs0 += __shfl_xor_sync(FULL, rs0, 1);
        rs0 += __shfl_xor_sync(FULL, rs0, 2);
        rs1 += __shfl_xor_sync(FULL, rs1, 1);
        rs1 += __shfl_xor_sync(FULL, rs1, 2);
        l0 = l0 * al0 + rs0;
        l1 = l1 * al1 + rs1;
#pragma unroll
        for (int nt = 0; nt < 4; nt++) {
            o[nt][0] *= al0; o[nt][1] *= al0;
            o[nt][2] *= al1; o[nt][3] *= al1;
        }

#pragma unroll
        for (int g = 0; g < 16; g++) {
            float t0A = __shfl_sync(FULL, s[g][0], lsrcA);
            float t1A = __shfl_sync(FULL, s[g][1], lsrcA);
            float t2A = __shfl_sync(FULL, s[g][2], lsrcA);
            float t3A = __shfl_sync(FULL, s[g][3], lsrcA);
            float t0B = __shfl_sync(FULL, s[g][0], lsrcB);
            float t1B = __shfl_sync(FULL, s[g][1], lsrcB);
            float t2B = __shfl_sync(FULL, s[g][2], lsrcB);
            float t3B = __shfl_sync(FULL, s[g][3], lsrcB);
            uint32_t a0 = __float_as_uint(odd ? t1A : t0A);
            uint32_t a1 = __float_as_uint(odd ? t3A : t2A);
            uint32_t a2 = __float_as_uint(odd ? t1B : t0B);
            uint32_t a3 = __float_as_uint(odd ? t3B : t2B);
#pragma unroll
            for (int nt = 0; nt < 4; nt++) {
                uint32_t b0 = __float_as_uint(Vs[(g * 8 + lc) * KV_STR + nt * 8 + lr]);
                uint32_t b1 = __float_as_uint(Vs[(g * 8 + lc + 4) * KV_STR + nt * 8 + lr]);
                MMA_TF32(o[nt][0], o[nt][1], o[nt][2], o[nt][3],
                         a0, a1, a2, a3, b0, b1);
            }
        }
    }

    float inv0 = 1.0f / l0, inv1 = 1.0f / l1;
    int row0 = b * NGR + i0 + warp * 16 + lr;
#pragma unroll
    for (int nt = 0; nt < 4; nt++) {
        int col = h * DH + nt * 8 + lc * 2;
        *(float2*)&out[(size_t)row0 * CC + col] =
            make_float2(o[nt][0] * inv0, o[nt][1] * inv0);
        *(float2*)&out[(size_t)(row0 + 8) * CC + col] =
            make_float2(o[nt][2] * inv1, o[nt][3] * inv1);
    }
}

// ---------------- host ----------------
static float* symf(const void* p) { return (float*)p; }

extern "C" void kernel_launch(void* const* d_in, const int* in_sizes, int n_in,
                              void* d_out, int out_size)
{
    const float* x      = (const float*)d_in[0];
    const float* U      = (const float*)d_in[1];
    const float* Lambda = (const float*)d_in[2];
    const float* lamMax = (const float*)d_in[3];
    const float* w_spa1 = (const float*)d_in[4];  const float* b_spa1 = (const float*)d_in[5];
    const float* w_spa2 = (const float*)d_in[6];  const float* b_spa2 = (const float*)d_in[7];
    const float* w_spe1 = (const float*)d_in[8];  const float* b_spe1 = (const float*)d_in[9];
    const float* w_spe2 = (const float*)d_in[10]; const float* b_spe2 = (const float*)d_in[11];
    const float* cheb_w = (const float*)d_in[12]; const float* cheb_b = (const float*)d_in[13];
    const float* gamma  = (const float*)d_in[14]; const float* w_proj = (const float*)d_in[15];
    const float* w_qkv  = (const float*)d_in[16]; const float* b_qkv  = (const float*)d_in[17];
    const float* w_out  = (const float*)d_in[18]; const float* b_out  = (const float*)d_in[19];
    const float* mlp_w1 = (const float*)d_in[20]; const float* mlp_b1 = (const float*)d_in[21];
    const float* mlp_w2 = (const float*)d_in[22]; const float* mlp_b2 = (const float*)d_in[23];
    const float* bn1w = (const float*)d_in[24]; const float* bn1b = (const float*)d_in[25];
    const float* bn2w = (const float*)d_in[26]; const float* bn2b = (const float*)d_in[27];
    const float* bn3w = (const float*)d_in[28]; const float* bn3b = (const float*)d_in[29];
    const int*   ei   = (const int*)d_in[30];
    const int* src = ei;
    const int* dst = ei + EE;
    float* out = (float*)d_out;

    void *pBIG, *pHID, *pLOC, *pXSP, *pHPJ, *pATT, *pH2, *pQKV, *pS, *pOUTD, *pIND,
         *pSUMS, *pAB, *pWRD;
    cudaGetSymbolAddress(&pBIG, g_big);   cudaGetSymbolAddress(&pHID, g_hid);
    cudaGetSymbolAddress(&pLOC, g_loc);   cudaGetSymbolAddress(&pXSP, g_xspec);
    cudaGetSymbolAddress(&pHPJ, g_hproj); cudaGetSymbolAddress(&pATT, g_att);
    cudaGetSymbolAddress(&pH2, g_h2);     cudaGetSymbolAddress(&pQKV, g_qkv);
    cudaGetSymbolAddress(&pS, g_S);
    cudaGetSymbolAddress(&pOUTD, g_outdeg); cudaGetSymbolAddress(&pIND, g_indeg);
    cudaGetSymbolAddress(&pSUMS, g_sums);   cudaGetSymbolAddress(&pAB, g_ab);
    cudaGetSymbolAddress(&pWRD, g_wrd);

    float* BIG = symf(pBIG); float* HID = symf(pHID); float* LOC = symf(pLOC);
    float* XSP = symf(pXSP); float* HPJ = symf(pHPJ); float* ATT = symf(pATT);
    float* H2  = symf(pH2);  float* QKV = symf(pQKV); float* SUMS = symf(pSUMS);
    float* WR  = symf(pWRD);
    float* HIDa = HID;
    float* HIDb = HID + (size_t)NN * CC;

    static cudaStream_t s2 = 0, s3 = 0;
    static cudaEvent_t evF = 0, evB = 0, evC = 0;
    if (!s2) {
        cudaStreamCreateWithFlags(&s2, cudaStreamNonBlocking);
        cudaStreamCreateWithFlags(&s3, cudaStreamNonBlocking);
        cudaEventCreateWithFlags(&evF, cudaEventDisableTiming);
        cudaEventCreateWithFlags(&evB, cudaEventDisableTiming);
        cudaEventCreateWithFlags(&evC, cudaEventDisableTiming);
    }

    cudaMemsetAsync(pOUTD, 0, NN * sizeof(int));
    cudaMemsetAsync(pIND,  0, NN * sizeof(int));
    cudaMemsetAsync(pS,    0, KEIG * CC * sizeof(float));
    cudaMemsetAsync(pSUMS, 0, 6 * CC * sizeof(float));
    k_roundw<<<(WTOT / 4 + 255) / 256, 256>>>(w_spa1, w_spa2, w_spe1, w_spe2, w_proj,
                                              cheb_w, w_qkv, w_out, mlp_w1, mlp_w2);
    cudaEventRecord(evF, 0);
    cudaStreamWaitEvent(s2, evF, 0);
    cudaStreamWaitEvent(s3, evF, 0);

    auto GEMM = [&](cudaStream_t st, const float* A, const float* W, const float* bias,
                    const float* res, float* C, int M, int Kd, int ldA, int Cout, int ldC,
                    int relu, int accum, float* sums) {
        dim3 g(M / 128, Cout / 128);
        k_gemm<<<g, 256, 0, st>>>(A, W, bias, res, C, M, Kd, ldA, Cout, ldC, relu, accum, sums);
    };

    // ---- branch A (stream 0): prep + spatial MLP + Chebyshev ----
    k_count<<<EE / 256, 256>>>(src, dst);
    k_dis<<<NN / 256, 256>>>();
    k_scan<<<1, 256>>>();
    k_fill<<<EE / 256, 256>>>(src, dst);
    GEMM(0, x, WR + OSPA1, b_spa1, nullptr, HIDa, NN, 128, 128, 128, 128, 1, 0, nullptr);
    GEMM(0, HIDa, WR + OSPA2, b_spa2, nullptr, BIG, NN, 128, 128, 128, 640, 0, 0, nullptr);
    k_cheb<<<NN / 8, 256>>>(BIG, nullptr, BIG + 128, lamMax, 0, 640);
    for (int k = 2; k < KCH; k++)
        k_cheb<<<NN / 8, 256>>>(BIG + (k - 1) * 128, BIG + (k - 2) * 128,
                                BIG + k * 128, lamMax, 1, 640);
    GEMM(0, BIG, WR + OCHEB, nullptr, nullptr, LOC, NN, 640, 640, 128, 128, 0, 0, nullptr);

    // ---- branch B (s2): spectral ----
    GEMM(s2, x, WR + OSPE1, b_spe1, nullptr, HIDb, NN, 128, 128, 128, 128, 1, 0, nullptr);
    GEMM(s2, HIDb, WR + OSPE2, b_spe2, nullptr, XSP, NN, 128, 128, 128, 128, 0, 0, nullptr);
    GEMM(s2, XSP, WR + OPROJ, nullptr, nullptr, HPJ, NN, 128, 128, 128, 128, 0, 0, nullptr);
    k_utgemm_tc<<<NN / 256, 256, 0, s2>>>(U, HPJ);
    k_scaleS<<<(KEIG * CC) / 256, 256, 0, s2>>>(Lambda, gamma);
    cudaEventRecord(evB, s2);

    // ---- branch C (s3): attention ----
    GEMM(s3, x, WR + OQKV, b_qkv, nullptr, QKV, NN, 128, 128, 384, 384, 0, 0, nullptr);
    {
        dim3 gf(NGR / 128, BBG * HH);
        k_flash<<<gf, 256, 0, s3>>>(QKV, ATT);
    }
    GEMM(s3, ATT, WR + OWOUT, b_out, x, H2, NN, 128, 128, 128, 128, 0, 0, SUMS + 256);
    cudaEventRecord(evC, s3);

    // ---- join on stream 0 ----
    cudaStreamWaitEvent(0, evB, 0);
    // LOC = pre1 = U@S + LOC + cheb_b + x   (fused BN1 stats)
    GEMM(0, U, symf(pS), cheb_b, x, LOC, NN, 128, 128, 128, 128, 0, 1, SUMS);
    cudaStreamWaitEvent(0, evC, 0);

    k_bnfin<<<1, 128>>>(SUMS,       SUMS + 128, bn1w, bn1b, symf(pAB),       symf(pAB) + 128);
    k_bnfin<<<1, 128>>>(SUMS + 256, SUMS + 384, bn2w, bn2b, symf(pAB) + 256, symf(pAB) + 384);
    k_combine<<<(NN * CC / 4) / 256, 256>>>(LOC, H2, XSP);

    // ---- final MLP with residual (fused BN3 stats) ----
    GEMM(0, XSP, WR + OMLP1, mlp_b1, nullptr, HID, NN, 128, 128, 256, 256, 1, 0, nullptr);
    GEMM(0, HID, WR + OMLP2, mlp_b2, XSP, LOC, NN, 256, 256, 128, 128, 0, 0, SUMS + 512);

    k_bnfin<<<1, 128>>>(SUMS + 512, SUMS + 640, bn3w, bn3b, symf(pAB) + 512, symf(pAB) + 640);
    k_final<<<(NN * CC / 4) / 256, 256>>>(LOC, out);
}

// round 8
// speedup vs baseline: 2.7097x; 1.0009x over previous
#include <cuda_runtime.h>
#include <math.h>
#include <stdint.h>

#define NN   32768
#define CC   128
#define EE   524288
#define BBG  64
#define NGR  512
#define HH   4
#define DH   32
#define KEIG 128
#define KCH  5
#define BN_EPS 1e-5f

// ---------------- static scratch ----------------
__device__ float g_big [NN * 640];
__device__ float g_hid [NN * 2 * CC];
__device__ float g_loc [NN * CC];
__device__ float g_xspec[NN * CC];
__device__ float g_hproj[NN * CC];
__device__ float g_att [NN * CC];
__device__ float g_h2  [NN * CC];
__device__ float g_qkv [NN * 3 * CC];
__device__ float g_S   [KEIG * CC];
__device__ float g_dis [NN];
__device__ int   g_outdeg[NN];
__device__ int   g_indeg [NN];
__device__ int   g_rowptr[NN + 1];
__device__ int   g_cursor[NN];
__device__ int   g_ecol  [EE];
__device__ int   g_blksum[128];
__device__ int   g_blkoff[128];
__device__ float g_sums[6 * CC];
__device__ float g_ab  [6 * CC];

// pre-rounded (tf32) weights
#define OSPA1 0
#define OSPA2 16384
#define OSPE1 32768
#define OSPE2 49152
#define OPROJ 65536
#define OCHEB 81920
#define OQKV  163840
#define OWOUT 212992
#define OMLP1 229376
#define OMLP2 262144
#define WTOT  294912
__device__ float g_wrd[WTOT];

__device__ __forceinline__ float cvt_tf32(float x) {
    float r;
    asm("cvt.rna.tf32.f32 %0, %1;" : "=f"(r) : "f"(x));
    return r;
}
__device__ __forceinline__ float4 cvt_tf32_4(float4 v) {
    v.x = cvt_tf32(v.x); v.y = cvt_tf32(v.y);
    v.z = cvt_tf32(v.z); v.w = cvt_tf32(v.w);
    return v;
}
#define MMA_TF32(d0,d1,d2,d3,a0,a1,a2,a3,b0,b1)                               \
    asm volatile("mma.sync.aligned.m16n8k8.row.col.f32.tf32.tf32.f32 "        \
        "{%0,%1,%2,%3}, {%4,%5,%6,%7}, {%8,%9}, {%0,%1,%2,%3};"               \
        : "+f"(d0), "+f"(d1), "+f"(d2), "+f"(d3)                              \
        : "r"(a0), "r"(a1), "r"(a2), "r"(a3), "r"(b0), "r"(b1))

#define CP16(dst32, srcp) \
    asm volatile("cp.async.cg.shared.global [%0], [%1], 16;" :: "r"(dst32), "l"(srcp))
#define CPCOMMIT() asm volatile("cp.async.commit_group;")
#define CPWAIT0()  asm volatile("cp.async.wait_group 0;")
#define CPWAIT1()  asm volatile("cp.async.wait_group 1;")

// ---------------- weight pre-rounding ----------------
__global__ void k_roundw(const float* __restrict__ w0, const float* __restrict__ w1,
                         const float* __restrict__ w2, const float* __restrict__ w3,
                         const float* __restrict__ w4, const float* __restrict__ w5,
                         const float* __restrict__ w6, const float* __restrict__ w7,
                         const float* __restrict__ w8, const float* __restrict__ w9)
{
    int i = (blockIdx.x * blockDim.x + threadIdx.x) * 4;
    if (i >= WTOT) return;
    const float* src; int off;
    if      (i < OSPA2) { src = w0; off = OSPA1; }
    else if (i < OSPE1) { src = w1; off = OSPA2; }
    else if (i < OSPE2) { src = w2; off = OSPE1; }
    else if (i < OPROJ) { src = w3; off = OSPE2; }
    else if (i < OCHEB) { src = w4; off = OPROJ; }
    else if (i < OQKV)  { src = w5; off = OCHEB; }
    else if (i < OWOUT) { src = w6; off = OQKV;  }
    else if (i < OMLP1) { src = w7; off = OWOUT; }
    else if (i < OMLP2) { src = w8; off = OMLP1; }
    else                { src = w9; off = OMLP2; }
    float4 v = *(const float4*)&src[i - off];
    *(float4*)&g_wrd[i] = cvt_tf32_4(v);
}

// ---------------- graph preprocessing ----------------
__global__ void k_count(const int* __restrict__ src, const int* __restrict__ dst) {
    int e = blockIdx.x * blockDim.x + threadIdx.x;
    if (e < EE) {
        atomicAdd(&g_outdeg[src[e]], 1);
        atomicAdd(&g_indeg [dst[e]], 1);
    }
}

__global__ void k_dis() {
    int n = blockIdx.x * blockDim.x + threadIdx.x;
    if (n < NN) {
        int d = g_outdeg[n];
        g_dis[n] = (d > 0) ? rsqrtf((float)d) : 0.0f;
    }
}

// parallel scan stage 1: per-block (256 elems) exclusive scan + block sums
__global__ void k_scan1() {
    __shared__ int sh[256];
    int t = threadIdx.x;
    int i = blockIdx.x * 256 + t;
    int v = g_indeg[i];
    sh[t] = v;
    __syncthreads();
#pragma unroll
    for (int off = 1; off < 256; off <<= 1) {
        int u = (t >= off) ? sh[t - off] : 0;
        __syncthreads();
        sh[t] += u;
        __syncthreads();
    }
    g_rowptr[i] = sh[t] - v;
    if (t == 255) g_blksum[blockIdx.x] = sh[255];
}

// stage 2: scan the 128 block sums
__global__ void k_scan2() {
    __shared__ int sh[128];
    int t = threadIdx.x;
    int v = g_blksum[t];
    sh[t] = v;
    __syncthreads();
#pragma unroll
    for (int off = 1; off < 128; off <<= 1) {
        int u = (t >= off) ? sh[t - off] : 0;
        __syncthreads();
        sh[t] += u;
        __syncthreads();
    }
    g_blkoff[t] = sh[t] - v;
    if (t == 127) g_rowptr[NN] = sh[127];
}

// stage 3: add block offsets, init cursor
__global__ void k_scan3() {
    int t = threadIdx.x;
    int i = blockIdx.x * 256 + t;
    int r = g_rowptr[i] + g_blkoff[blockIdx.x];
    g_rowptr[i] = r;
    g_cursor[i] = r;
}

__global__ void k_fill(const int* __restrict__ src, const int* __restrict__ dst) {
    int e = blockIdx.x * blockDim.x + threadIdx.x;
    if (e < EE) {
        int p = atomicAdd(&g_cursor[dst[e]], 1);
        g_ecol[p] = src[e];
    }
}

// ---------------- tf32 GEMM, 3-stage cp.async ring, 1 sync/iter ----------------
#define AS_STR 20
#define BS_STR 136
#define A_WORDS (128 * AS_STR)
#define B_WORDS (16 * BS_STR)
__global__ __launch_bounds__(256) void k_gemm(
    const float* __restrict__ A, const float* __restrict__ W,
    const float* __restrict__ bias, const float* __restrict__ res,
    float* __restrict__ C, int M, int Kd, int ldA, int Cout, int ldC,
    int relu, int accum, float* __restrict__ sums)
{
    __shared__ float As[3 * A_WORDS];
    __shared__ float Bs[3 * B_WORDS];
    int bm = blockIdx.x * 128;
    int bn = blockIdx.y * 128;
    int tid = threadIdx.x;
    int warp = tid >> 5, lane = tid & 31;
    int wm = (warp >> 1) * 32;
    int wn = (warp & 1) * 64;
    int lr = lane >> 2;
    int lc = lane & 3;

    uint32_t asB = (uint32_t)__cvta_generic_to_shared(As);
    uint32_t bsB = (uint32_t)__cvta_generic_to_shared(Bs);
    int aRow = tid >> 2, aC4 = (tid & 3) * 4;
    int bRow = tid >> 5, bC4 = (tid & 31) * 4;

#define GISSUE(buf, k0) do {                                                        \
    CP16(asB + (uint32_t)((buf) * A_WORDS + aRow * AS_STR + aC4) * 4u,              \
         A + (size_t)(bm + aRow) * ldA + (k0) + aC4);                               \
    CP16(asB + (uint32_t)((buf) * A_WORDS + (aRow + 64) * AS_STR + aC4) * 4u,       \
         A + (size_t)(bm + aRow + 64) * ldA + (k0) + aC4);                          \
    CP16(bsB + (uint32_t)((buf) * B_WORDS + bRow * BS_STR + bC4) * 4u,              \
         W + (size_t)((k0) + bRow) * Cout + bn + bC4);                              \
    CP16(bsB + (uint32_t)((buf) * B_WORDS + (bRow + 8) * BS_STR + bC4) * 4u,        \
         W + (size_t)((k0) + bRow + 8) * Cout + bn + bC4);                          \
    CPCOMMIT(); } while (0)

    float acc[2][8][4];
#pragma unroll
    for (int i = 0; i < 2; i++)
#pragma unroll
        for (int j = 0; j < 8; j++)
#pragma unroll
            for (int q = 0; q < 4; q++) acc[i][j][q] = 0.0f;

    int niter = Kd >> 4;
    GISSUE(0, 0);
    GISSUE(1, 16);
    int slot = 0;
    for (int it = 0; it < niter; it++) {
        if (it + 1 < niter) { CPWAIT1(); } else { CPWAIT0(); }
        __syncthreads();
        if (it + 2 < niter) {
            int ns = slot + 2; if (ns >= 3) ns -= 3;
            GISSUE(ns, (it + 2) * 16);
        }
        const float* Ac = As + slot * A_WORDS;
        const float* Bc = Bs + slot * B_WORDS;
#pragma unroll
        for (int kk = 0; kk < 16; kk += 8) {
            uint32_t af[2][4], bf[8][2];
#pragma unroll
            for (int mt = 0; mt < 2; mt++) {
                int r = wm + mt * 16 + lr;
                af[mt][0] = __float_as_uint(cvt_tf32(Ac[r * AS_STR + kk + lc]));
                af[mt][1] = __float_as_uint(cvt_tf32(Ac[(r + 8) * AS_STR + kk + lc]));
                af[mt][2] = __float_as_uint(cvt_tf32(Ac[r * AS_STR + kk + lc + 4]));
                af[mt][3] = __float_as_uint(cvt_tf32(Ac[(r + 8) * AS_STR + kk + lc + 4]));
            }
#pragma unroll
            for (int nt = 0; nt < 8; nt++) {
                int c = wn + nt * 8 + lr;
                bf[nt][0] = __float_as_uint(Bc[(kk + lc) * BS_STR + c]);
                bf[nt][1] = __float_as_uint(Bc[(kk + lc + 4) * BS_STR + c]);
            }
#pragma unroll
            for (int mt = 0; mt < 2; mt++)
#pragma unroll
                for (int nt = 0; nt < 8; nt++)
                    MMA_TF32(acc[mt][nt][0], acc[mt][nt][1], acc[mt][nt][2], acc[mt][nt][3],
                             af[mt][0], af[mt][1], af[mt][2], af[mt][3],
                             bf[nt][0], bf[nt][1]);
        }
        slot++; if (slot >= 3) slot = 0;
    }
#undef GISSUE
    __syncthreads();

    float csum[16], csq[16];
#pragma unroll
    for (int t = 0; t < 16; t++) { csum[t] = 0.f; csq[t] = 0.f; }

#pragma unroll
    for (int mt = 0; mt < 2; mt++) {
#pragma unroll
        for (int half = 0; half < 2; half++) {
            int row = bm + wm + mt * 16 + lr + half * 8;
            size_t ro = (size_t)row * ldC;
            size_t rr = (size_t)row * Cout;
#pragma unroll
            for (int nt = 0; nt < 8; nt++) {
                int col = bn + wn + nt * 8 + lc * 2;
                float v0 = acc[mt][nt][half * 2];
                float v1 = acc[mt][nt][half * 2 + 1];
                if (bias) { v0 += bias[col]; v1 += bias[col + 1]; }
                if (res)  { v0 += res[rr + col]; v1 += res[rr + col + 1]; }
                if (accum){ v0 += C[ro + col];  v1 += C[ro + col + 1]; }
                if (relu) { v0 = fmaxf(v0, 0.f); v1 = fmaxf(v1, 0.f); }
                if (sums) {
                    csum[nt * 2]     += v0; csq[nt * 2]     = fmaf(v0, v0, csq[nt * 2]);
                    csum[nt * 2 + 1] += v1; csq[nt * 2 + 1] = fmaf(v1, v1, csq[nt * 2 + 1]);
                }
                *(float2*)&C[ro + col] = make_float2(v0, v1);
            }
        }
    }

    if (sums) {
        if (tid < 256) As[tid] = 0.f;
        __syncthreads();
#pragma unroll
        for (int t = 0; t < 16; t++) {
            int col = wn + (t >> 1) * 8 + lc * 2 + (t & 1);
            atomicAdd(&As[col], csum[t]);
            atomicAdd(&As[128 + col], csq[t]);
        }
        __syncthreads();
        if (tid < 128) {
            atomicAdd(&sums[tid],       As[tid]);
            atomicAdd(&sums[tid + 128], As[tid + 128]);
        }
    }
}

// ---------------- Chebyshev gather ----------------
__global__ void k_cheb(const float* __restrict__ Vc, const float* __restrict__ Vp,
                       float* __restrict__ Vo, const float* __restrict__ lam,
                       int mode, int ld)
{
    int gw = (blockIdx.x * blockDim.x + threadIdx.x) >> 5;
    int lane = threadIdx.x & 31;
    if (gw >= NN) return;
    float sc = 2.0f / lam[0];
    int beg = g_rowptr[gw], end = g_rowptr[gw + 1];
    float dn = g_dis[gw];
    float4 acc = make_float4(0.f, 0.f, 0.f, 0.f);
    for (int j = beg; j < end; j++) {
        int s = g_ecol[j];
        float w = dn * g_dis[s];
        float4 v = *(const float4*)&Vc[(size_t)s * ld + lane * 4];
        acc.x = fmaf(w, v.x, acc.x);
        acc.y = fmaf(w, v.y, acc.y);
        acc.z = fmaf(w, v.z, acc.z);
        acc.w = fmaf(w, v.w, acc.w);
    }
    float4 vc = *(const float4*)&Vc[(size_t)gw * ld + lane * 4];
    float sm1 = sc - 1.0f;
    float4 r;
    r.x = sm1 * vc.x - sc * acc.x;
    r.y = sm1 * vc.y - sc * acc.y;
    r.z = sm1 * vc.z - sc * acc.z;
    r.w = sm1 * vc.w - sc * acc.w;
    if (mode) {
        float4 vp = *(const float4*)&Vp[(size_t)gw * ld + lane * 4];
        r.x = 2.f * r.x - vp.x; r.y = 2.f * r.y - vp.y;
        r.z = 2.f * r.z - vp.z; r.w = 2.f * r.w - vp.w;
    }
    *(float4*)&Vo[(size_t)gw * ld + lane * 4] = r;
}

// ---------------- S = U^T @ Hp (tf32 mma, atomic accumulate) ----------------
#define US_STR 132
__global__ __launch_bounds__(256) void k_utgemm_tc(const float* __restrict__ U,
                                                   const float* __restrict__ Hp)
{
    __shared__ float Us[16 * US_STR];
    __shared__ float Hs[16 * US_STR];
    int n0 = blockIdx.x * 256;
    int tid = threadIdx.x;
    int warp = tid >> 5, lane = tid & 31;
    int wm = (warp >> 1) * 32, wn = (warp & 1) * 64;
    int lr = lane >> 2, lc = lane & 3;

    float acc[2][8][4];
#pragma unroll
    for (int i = 0; i < 2; i++)
#pragma unroll
        for (int j = 0; j < 8; j++)
#pragma unroll
            for (int q = 0; q < 4; q++) acc[i][j][q] = 0.f;

    for (int nb = 0; nb < 256; nb += 16) {
#pragma unroll
        for (int l = 0; l < 2; l++) {
            int i = tid + l * 256;
            int row = i >> 5, c4 = (i & 31) * 4;
            *(float4*)&Us[row * US_STR + c4] =
                cvt_tf32_4(*(const float4*)&U [(size_t)(n0 + nb + row) * 128 + c4]);
            *(float4*)&Hs[row * US_STR + c4] =
                cvt_tf32_4(*(const float4*)&Hp[(size_t)(n0 + nb + row) * 128 + c4]);
        }
        __syncthreads();
#pragma unroll
        for (int kk = 0; kk < 16; kk += 8) {
            uint32_t af[2][4], bf[8][2];
#pragma unroll
            for (int mt = 0; mt < 2; mt++) {
                int m = wm + mt * 16 + lr;
                af[mt][0] = __float_as_uint(Us[(kk + lc) * US_STR + m]);
                af[mt][1] = __float_as_uint(Us[(kk + lc) * US_STR + m + 8]);
                af[mt][2] = __float_as_uint(Us[(kk + lc + 4) * US_STR + m]);
                af[mt][3] = __float_as_uint(Us[(kk + lc + 4) * US_STR + m + 8]);
            }
#pragma unroll
            for (int nt = 0; nt < 8; nt++) {
                int c = wn + nt * 8 + lr;
                bf[nt][0] = __float_as_uint(Hs[(kk + lc) * US_STR + c]);
                bf[nt][1] = __float_as_uint(Hs[(kk + lc + 4) * US_STR + c]);
            }
#pragma unroll
            for (int mt = 0; mt < 2; mt++)
#pragma unroll
                for (int nt = 0; nt < 8; nt++)
                    MMA_TF32(acc[mt][nt][0], acc[mt][nt][1], acc[mt][nt][2], acc[mt][nt][3],
                             af[mt][0], af[mt][1], af[mt][2], af[mt][3],
                             bf[nt][0], bf[nt][1]);
        }
        __syncthreads();
    }
#pragma unroll
    for (int mt = 0; mt < 2; mt++)
#pragma unroll
        for (int half = 0; half < 2; half++) {
            int row = wm + mt * 16 + lr + half * 8;
#pragma unroll
            for (int nt = 0; nt < 8; nt++) {
                int col = wn + nt * 8 + lc * 2;
                atomicAdd(&g_S[row * 128 + col],     acc[mt][nt][half * 2]);
                atomicAdd(&g_S[row * 128 + col + 1], acc[mt][nt][half * 2 + 1]);
            }
        }
}

__global__ void k_scaleS(const float* __restrict__ Lambda, const float* __restrict__ gamma) {
    int i = blockIdx.x * blockDim.x + threadIdx.x;
    if (i < KEIG * CC) {
        int k = i >> 7;
        float l = Lambda[k];
        g_S[i] = cvt_tf32(g_S[i] * expf(-gamma[0] * l * l));
    }
}

// ---------------- BN finalize / elementwise ----------------
__global__ void k_bnfin(const float* __restrict__ sum, const float* __restrict__ sq,
                        const float* __restrict__ w, const float* __restrict__ b,
                        float* __restrict__ a, float* __restrict__ bs)
{
    int c = threadIdx.x;
    float mu  = sum[c] * (1.0f / NN);
    float var = sq[c]  * (1.0f / NN) - mu * mu;
    float aa = w[c] * rsqrtf(var + BN_EPS);
    a[c]  = aa;
    bs[c] = b[c] - mu * aa;
}

__global__ void k_combine(const float* __restrict__ pre, const float* __restrict__ h2,
                          float* __restrict__ out0)
{
    int i = blockIdx.x * blockDim.x + threadIdx.x;
    int col4 = (i & 31) * 4;
    float4 p = ((const float4*)pre)[i];
    float4 q = ((const float4*)h2)[i];
    float4 a1 = *(const float4*)&g_ab[col4];
    float4 b1 = *(const float4*)&g_ab[128 + col4];
    float4 a2 = *(const float4*)&g_ab[256 + col4];
    float4 b2 = *(const float4*)&g_ab[384 + col4];
    float4 rv;
    rv.x = fmaf(p.x, a1.x, b1.x) + fmaf(q.x, a2.x, b2.x);
    rv.y = fmaf(p.y, a1.y, b1.y) + fmaf(q.y, a2.y, b2.y);
    rv.z = fmaf(p.z, a1.z, b1.z) + fmaf(q.z, a2.z, b2.z);
    rv.w = fmaf(p.w, a1.w, b1.w) + fmaf(q.w, a2.w, b2.w);
    ((float4*)out0)[i] = rv;
}

__global__ void k_final(const float* __restrict__ X, float* __restrict__ out) {
    int i = blockIdx.x * blockDim.x + threadIdx.x;
    int col4 = (i & 31) * 4;
    float4 v = ((const float4*)X)[i];
    float4 a3 = *(const float4*)&g_ab[512 + col4];
    float4 b3 = *(const float4*)&g_ab[640 + col4];
    float4 rv;
    rv.x = fmaf(v.x, a3.x, b3.x); rv.y = fmaf(v.y, a3.y, b3.y);
    rv.z = fmaf(v.z, a3.z, b3.z); rv.w = fmaf(v.w, a3.w, b3.w);
    ((float4*)out)[i] = rv;
}

// ---------------- fused flash attention ----------------
#define KV_STR 36
__global__ __launch_bounds__(256) void k_flash(const float* __restrict__ qkv,
                                               float* __restrict__ out)
{
    __shared__ float Ks[128 * KV_STR];
    __shared__ float Vs[128 * KV_STR];
    int bh = blockIdx.y;
    int b = bh >> 2, h = bh & 3;
    int i0 = blockIdx.x * 128;
    int tid = threadIdx.x;
    int warp = tid >> 5, lane = tid & 31;
    int lr = lane >> 2, lc = lane & 3;
    const unsigned FULL = 0xffffffffu;
    const float scl = 0.17677669529663687f;

    const float* qb = qkv + (size_t)(b * NGR + i0 + warp * 16) * 384 + h * DH;
    uint32_t qf[4][4];
#pragma unroll
    for (int kc = 0; kc < 4; kc++) {
        qf[kc][0] = __float_as_uint(cvt_tf32(qb[(size_t)lr * 384 + kc * 8 + lc]));
        qf[kc][1] = __float_as_uint(cvt_tf32(qb[(size_t)(lr + 8) * 384 + kc * 8 + lc]));
        qf[kc][2] = __float_as_uint(cvt_tf32(qb[(size_t)lr * 384 + kc * 8 + lc + 4]));
        qf[kc][3] = __float_as_uint(cvt_tf32(qb[(size_t)(lr + 8) * 384 + kc * 8 + lc + 4]));
    }

    float m0 = -1e30f, m1 = -1e30f, l0 = 0.f, l1 = 0.f;
    float o[4][4];
#pragma unroll
    for (int nt = 0; nt < 4; nt++)
#pragma unroll
        for (int q = 0; q < 4; q++) o[nt][q] = 0.f;

    int lsrcA = (lane & ~3) | (lc >> 1);
    int lsrcB = lsrcA + 2;
    bool odd = (lc & 1);

    for (int j0 = 0; j0 < NGR; j0 += 128) {
        __syncthreads();
        const float* kb = qkv + (size_t)(b * NGR + j0) * 384 + 128 + h * DH;
        const float* vb = qkv + (size_t)(b * NGR + j0) * 384 + 256 + h * DH;
#pragma unroll
        for (int l4 = 0; l4 < 4; l4++) {
            int i = tid + l4 * 256;
            int row = i >> 3, c4 = (i & 7) * 4;
            *(float4*)&Ks[row * KV_STR + c4] =
                cvt_tf32_4(*(const float4*)&kb[(size_t)row * 384 + c4]);
            *(float4*)&Vs[row * KV_STR + c4] =
                cvt_tf32_4(*(const float4*)&vb[(size_t)row * 384 + c4]);
        }
        __syncthreads();

        float s[16][4];
#pragma unroll
        for (int g = 0; g < 16; g++)
#pragma unroll
            for (int q = 0; q < 4; q++) s[g][q] = 0.f;
#pragma unroll
        for (int kc = 0; kc < 4; kc++) {
#pragma unroll
            for (int g = 0; g < 16; g++) {
                int c = g * 8 + lr;
                uint32_t b0 = __float_as_uint(Ks[c * KV_STR + kc * 8 + lc]);
                uint32_t b1 = __float_as_uint(Ks[c * KV_STR + kc * 8 + lc + 4]);
                MMA_TF32(s[g][0], s[g][1], s[g][2], s[g][3],
                         qf[kc][0], qf[kc][1], qf[kc][2], qf[kc][3], b0, b1);
            }
        }

        float mn0 = m0, mn1 = m1;
#pragma unroll
        for (int g = 0; g < 16; g++) {
            s[g][0] *= scl; s[g][1] *= scl; s[g][2] *= scl; s[g][3] *= scl;
            mn0 = fmaxf(mn0, fmaxf(s[g][0], s[g][1]));
            mn1 = fmaxf(mn1, fmaxf(s[g][2], s[g][3]));
        }
        mn0 = fmaxf(mn0, __shfl_xor_sync(FULL, mn0, 1));
        mn0 = fmaxf(mn0, __shfl_xor_sync(FULL, mn0, 2));
        mn1 = fmaxf(mn1, __shfl_xor_sync(FULL, mn1, 1));
        mn1 = fmaxf(mn1, __shfl_xor_sync(FULL, mn1, 2));
        float al0 = __expf(m0 - mn0);
        float al1 = __expf(m1 - mn1);
        m0 = mn0; m1 = mn1;
        float rs0 = 0.f, rs1 = 0.f;
#pragma unroll
        for (int g = 0; g < 16; g++) {
            s[g][0] = __expf(s[g][0] - mn0);
            s[g][1] = __expf(s[g][1] - mn0);
            s[g][2] = __expf(s[g][2] - mn1);
            s[g][3] = __expf(s[g][3] - mn1);
            rs0 += s[g][0] + s[g][1];
            rs1 += s[g][2] + s[g][3];
            s[g][0] = cvt_tf32(s[g][0]); s[g][1] = cvt_tf32(s[g][1]);
            s[g][2] = cvt_tf32(s[g][2]); s[g][3] = cvt_tf32(s[g][3]);
        }
        rs0 += __shfl_xor_sync(FULL, rs0, 1);
        rs0 += __shfl_xor_sync(FULL, rs0, 2);
        rs1 += __shfl_xor_sync(FULL, rs1, 1);
        rs1 += __shfl_xor_sync(FULL, rs1, 2);
        l0 = l0 * al0 + rs0;
        l1 = l1 * al1 + rs1;
#pragma unroll
        for (int nt = 0; nt < 4; nt++) {
            o[nt][0] *= al0; o[nt][1] *= al0;
            o[nt][2] *= al1; o[nt][3] *= al1;
        }

#pragma unroll
        for (int g = 0; g < 16; g++) {
            float t0A = __shfl_sync(FULL, s[g][0], lsrcA);
            float t1A = __shfl_sync(FULL, s[g][1], lsrcA);
            float t2A = __shfl_sync(FULL, s[g][2], lsrcA);
            float t3A = __shfl_sync(FULL, s[g][3], lsrcA);
            float t0B = __shfl_sync(FULL, s[g][0], lsrcB);
            float t1B = __shfl_sync(FULL, s[g][1], lsrcB);
            float t2B = __shfl_sync(FULL, s[g][2], lsrcB);
            float t3B = __shfl_sync(FULL, s[g][3], lsrcB);
            uint32_t a0 = __float_as_uint(odd ? t1A : t0A);
            uint32_t a1 = __float_as_uint(odd ? t3A : t2A);
            uint32_t a2 = __float_as_uint(odd ? t1B : t0B);
            uint32_t a3 = __float_as_uint(odd ? t3B : t2B);
#pragma unroll
            for (int nt = 0; nt < 4; nt++) {
                uint32_t b0 = __float_as_uint(Vs[(g * 8 + lc) * KV_STR + nt * 8 + lr]);
                uint32_t b1 = __float_as_uint(Vs[(g * 8 + lc + 4) * KV_STR + nt * 8 + lr]);
                MMA_TF32(o[nt][0], o[nt][1], o[nt][2], o[nt][3],
                         a0, a1, a2, a3, b0, b1);
            }
        }
    }

    float inv0 = 1.0f / l0, inv1 = 1.0f / l1;
    int row0 = b * NGR + i0 + warp * 16 + lr;
#pragma unroll
    for (int nt = 0; nt < 4; nt++) {
        int col = h * DH + nt * 8 + lc * 2;
        *(float2*)&out[(size_t)row0 * CC + col] =
            make_float2(o[nt][0] * inv0, o[nt][1] * inv0);
        *(float2*)&out[(size_t)(row0 + 8) * CC + col] =
            make_float2(o[nt][2] * inv1, o[nt][3] * inv1);
    }
}

// ---------------- host ----------------
static float* symf(const void* p) { return (float*)p; }

extern "C" void kernel_launch(void* const* d_in, const int* in_sizes, int n_in,
                              void* d_out, int out_size)
{
    const float* x      = (const float*)d_in[0];
    const float* U      = (const float*)d_in[1];
    const float* Lambda = (const float*)d_in[2];
    const float* lamMax = (const float*)d_in[3];
    const float* w_spa1 = (const float*)d_in[4];  const float* b_spa1 = (const float*)d_in[5];
    const float* w_spa2 = (const float*)d_in[6];  const float* b_spa2 = (const float*)d_in[7];
    const float* w_spe1 = (const float*)d_in[8];  const float* b_spe1 = (const float*)d_in[9];
    const float* w_spe2 = (const float*)d_in[10]; const float* b_spe2 = (const float*)d_in[11];
    const float* cheb_w = (const float*)d_in[12]; const float* cheb_b = (const float*)d_in[13];
    const float* gamma  = (const float*)d_in[14]; const float* w_proj = (const float*)d_in[15];
    const float* w_qkv  = (const float*)d_in[16]; const float* b_qkv  = (const float*)d_in[17];
    const float* w_out  = (const float*)d_in[18]; const float* b_out  = (const float*)d_in[19];
    const float* mlp_w1 = (const float*)d_in[20]; const float* mlp_b1 = (const float*)d_in[21];
    const float* mlp_w2 = (const float*)d_in[22]; const float* mlp_b2 = (const float*)d_in[23];
    const float* bn1w = (const float*)d_in[24]; const float* bn1b = (const float*)d_in[25];
    const float* bn2w = (const float*)d_in[26]; const float* bn2b = (const float*)d_in[27];
    const float* bn3w = (const float*)d_in[28]; const float* bn3b = (const float*)d_in[29];
    const int*   ei   = (const int*)d_in[30];
    const int* src = ei;
    const int* dst = ei + EE;
    float* out = (float*)d_out;

    void *pBIG, *pHID, *pLOC, *pXSP, *pHPJ, *pATT, *pH2, *pQKV, *pS, *pOUTD, *pIND,
         *pSUMS, *pAB, *pWRD;
    cudaGetSymbolAddress(&pBIG, g_big);   cudaGetSymbolAddress(&pHID, g_hid);
    cudaGetSymbolAddress(&pLOC, g_loc);   cudaGetSymbolAddress(&pXSP, g_xspec);
    cudaGetSymbolAddress(&pHPJ, g_hproj); cudaGetSymbolAddress(&pATT, g_att);
    cudaGetSymbolAddress(&pH2, g_h2);     cudaGetSymbolAddress(&pQKV, g_qkv);
    cudaGetSymbolAddress(&pS, g_S);
    cudaGetSymbolAddress(&pOUTD, g_outdeg); cudaGetSymbolAddress(&pIND, g_indeg);
    cudaGetSymbolAddress(&pSUMS, g_sums);   cudaGetSymbolAddress(&pAB, g_ab);
    cudaGetSymbolAddress(&pWRD, g_wrd);

    float* BIG = symf(pBIG); float* HID = symf(pHID); float* LOC = symf(pLOC);
    float* XSP = symf(pXSP); float* HPJ = symf(pHPJ); float* ATT = symf(pATT);
    float* H2  = symf(pH2);  float* QKV = symf(pQKV); float* SUMS = symf(pSUMS);
    float* WR  = symf(pWRD);
    float* HIDa = HID;
    float* HIDb = HID + (size_t)NN * CC;

    static cudaStream_t s2 = 0, s3 = 0;
    static cudaEvent_t evF = 0, evB = 0, evC = 0;
    if (!s2) {
        cudaStreamCreateWithFlags(&s2, cudaStreamNonBlocking);
        cudaStreamCreateWithFlags(&s3, cudaStreamNonBlocking);
        cudaEventCreateWithFlags(&evF, cudaEventDisableTiming);
        cudaEventCreateWithFlags(&evB, cudaEventDisableTiming);
        cudaEventCreateWithFlags(&evC, cudaEventDisableTiming);
    }

    cudaMemsetAsync(pOUTD, 0, NN * sizeof(int));
    cudaMemsetAsync(pIND,  0, NN * sizeof(int));
    cudaMemsetAsync(pS,    0, KEIG * CC * sizeof(float));
    cudaMemsetAsync(pSUMS, 0, 6 * CC * sizeof(float));
    k_roundw<<<(WTOT / 4 + 255) / 256, 256>>>(w_spa1, w_spa2, w_spe1, w_spe2, w_proj,
                                              cheb_w, w_qkv, w_out, mlp_w1, mlp_w2);
    cudaEventRecord(evF, 0);
    cudaStreamWaitEvent(s2, evF, 0);
    cudaStreamWaitEvent(s3, evF, 0);

    auto GEMM = [&](cudaStream_t st, const float* A, const float* W, const float* bias,
                    const float* res, float* C, int M, int Kd, int ldA, int Cout, int ldC,
                    int relu, int accum, float* sums) {
        dim3 g(M / 128, Cout / 128);
        k_gemm<<<g, 256, 0, st>>>(A, W, bias, res, C, M, Kd, ldA, Cout, ldC, relu, accum, sums);
    };

    // ---- branch A (stream 0): spatial MLP + prep + Chebyshev ----
    GEMM(0, x, WR + OSPA1, b_spa1, nullptr, HIDa, NN, 128, 128, 128, 128, 1, 0, nullptr);
    GEMM(0, HIDa, WR + OSPA2, b_spa2, nullptr, BIG, NN, 128, 128, 128, 640, 0, 0, nullptr);
    k_count<<<EE / 256, 256>>>(src, dst);
    k_dis<<<NN / 256, 256>>>();
    k_scan1<<<128, 256>>>();
    k_scan2<<<1, 128>>>();
    k_scan3<<<128, 256>>>();
    k_fill<<<EE / 256, 256>>>(src, dst);
    k_cheb<<<NN / 8, 256>>>(BIG, nullptr, BIG + 128, lamMax, 0, 640);
    for (int k = 2; k < KCH; k++)
        k_cheb<<<NN / 8, 256>>>(BIG + (k - 1) * 128, BIG + (k - 2) * 128,
                                BIG + k * 128, lamMax, 1, 640);
    GEMM(0, BIG, WR + OCHEB, nullptr, nullptr, LOC, NN, 640, 640, 128, 128, 0, 0, nullptr);

    // ---- branch B (s2): spectral ----
    GEMM(s2, x, WR + OSPE1, b_spe1, nullptr, HIDb, NN, 128, 128, 128, 128, 1, 0, nullptr);
    GEMM(s2, HIDb, WR + OSPE2, b_spe2, nullptr, XSP, NN, 128, 128, 128, 128, 0, 0, nullptr);
    GEMM(s2, XSP, WR + OPROJ, nullptr, nullptr, HPJ, NN, 128, 128, 128, 128, 0, 0, nullptr);
    k_utgemm_tc<<<NN / 256, 256, 0, s2>>>(U, HPJ);
    k_scaleS<<<(KEIG * CC) / 256, 256, 0, s2>>>(Lambda, gamma);
    cudaEventRecord(evB, s2);

    // ---- branch C (s3): attention ----
    GEMM(s3, x, WR + OQKV, b_qkv, nullptr, QKV, NN, 128, 128, 384, 384, 0, 0, nullptr);
    {
        dim3 gf(NGR / 128, BBG * HH);
        k_flash<<<gf, 256, 0, s3>>>(QKV, ATT);
    }
    GEMM(s3, ATT, WR + OWOUT, b_out, x, H2, NN, 128, 128, 128, 128, 0, 0, SUMS + 256);
    cudaEventRecord(evC, s3);

    // ---- join on stream 0 ----
    cudaStreamWaitEvent(0, evB, 0);
    // LOC = pre1 = U@S + LOC + cheb_b + x   (fused BN1 stats)
    GEMM(0, U, symf(pS), cheb_b, x, LOC, NN, 128, 128, 128, 128, 0, 1, SUMS);
    cudaStreamWaitEvent(0, evC, 0);

    k_bnfin<<<1, 128>>>(SUMS,       SUMS + 128, bn1w, bn1b, symf(pAB),       symf(pAB) + 128);
    k_bnfin<<<1, 128>>>(SUMS + 256, SUMS + 384, bn2w, bn2b, symf(pAB) + 256, symf(pAB) + 384);
    k_combine<<<(NN * CC / 4) / 256, 256>>>(LOC, H2, XSP);

    // ---- final MLP with residual (fused BN3 stats) ----
    GEMM(0, XSP, WR + OMLP1, mlp_b1, nullptr, HID, NN, 128, 128, 256, 256, 1, 0, nullptr);
    GEMM(0, HID, WR + OMLP2, mlp_b2, XSP, LOC, NN, 256, 256, 128, 128, 0, 0, SUMS + 512);

    k_bnfin<<<1, 128>>>(SUMS + 512, SUMS + 640, bn3w, bn3b, symf(pAB) + 512, symf(pAB) + 640);
    k_final<<<(NN * CC / 4) / 256, 256>>>(LOC, out);
}

// round 9
// speedup vs baseline: 2.7635x; 1.0198x over previous
#include <cuda_runtime.h>
#include <math.h>
#include <stdint.h>

#define NN   32768
#define CC   128
#define EE   524288
#define BBG  64
#define NGR  512
#define HH   4
#define DH   32
#define KEIG 128
#define KCH  5
#define BN_EPS 1e-5f

// ---------------- static scratch ----------------
__device__ float g_big [NN * 640];
__device__ float g_hid [NN * 2 * CC];
__device__ float g_loc [NN * CC];
__device__ float g_xspec[NN * CC];
__device__ float g_hproj[NN * CC];
__device__ float g_att [NN * CC];
__device__ float g_h2  [NN * CC];
__device__ float g_qkv [NN * 3 * CC];
__device__ float g_S   [KEIG * CC];
__device__ float g_dis [NN];
__device__ int   g_outdeg[NN];
__device__ int   g_indeg [NN];
__device__ int   g_rowptr[NN + 1];
__device__ int   g_cursor[NN];
__device__ int   g_ecol  [EE];
__device__ int   g_blksum[128];
__device__ int   g_blkoff[128];
__device__ float g_sums[6 * CC];
__device__ float g_ab  [6 * CC];

// pre-rounded (tf32) weights
#define OSPA1 0
#define OSPA2 16384
#define OSPE1 32768
#define OSPE2 49152
#define OPROJ 65536
#define OCHEB 81920
#define OQKV  163840
#define OWOUT 212992
#define OMLP1 229376
#define OMLP2 262144
#define WTOT  294912
__device__ float g_wrd[WTOT];

__device__ __forceinline__ float cvt_tf32(float x) {
    float r;
    asm("cvt.rna.tf32.f32 %0, %1;" : "=f"(r) : "f"(x));
    return r;
}
__device__ __forceinline__ float4 cvt_tf32_4(float4 v) {
    v.x = cvt_tf32(v.x); v.y = cvt_tf32(v.y);
    v.z = cvt_tf32(v.z); v.w = cvt_tf32(v.w);
    return v;
}
#define MMA_TF32(d0,d1,d2,d3,a0,a1,a2,a3,b0,b1)                               \
    asm volatile("mma.sync.aligned.m16n8k8.row.col.f32.tf32.tf32.f32 "        \
        "{%0,%1,%2,%3}, {%4,%5,%6,%7}, {%8,%9}, {%0,%1,%2,%3};"               \
        : "+f"(d0), "+f"(d1), "+f"(d2), "+f"(d3)                              \
        : "r"(a0), "r"(a1), "r"(a2), "r"(a3), "r"(b0), "r"(b1))

#define CP16(dst32, srcp) \
    asm volatile("cp.async.cg.shared.global [%0], [%1], 16;" :: "r"(dst32), "l"(srcp))
#define CPCOMMIT() asm volatile("cp.async.commit_group;")
#define CPWAIT0()  asm volatile("cp.async.wait_group 0;")
#define CPWAIT1()  asm volatile("cp.async.wait_group 1;")

// ---------------- weight pre-rounding ----------------
__global__ void k_roundw(const float* __restrict__ w0, const float* __restrict__ w1,
                         const float* __restrict__ w2, const float* __restrict__ w3,
                         const float* __restrict__ w4, const float* __restrict__ w5,
                         const float* __restrict__ w6, const float* __restrict__ w7,
                         const float* __restrict__ w8, const float* __restrict__ w9)
{
    int i = (blockIdx.x * blockDim.x + threadIdx.x) * 4;
    if (i >= WTOT) return;
    const float* src; int off;
    if      (i < OSPA2) { src = w0; off = OSPA1; }
    else if (i < OSPE1) { src = w1; off = OSPA2; }
    else if (i < OSPE2) { src = w2; off = OSPE1; }
    else if (i < OPROJ) { src = w3; off = OSPE2; }
    else if (i < OCHEB) { src = w4; off = OPROJ; }
    else if (i < OQKV)  { src = w5; off = OCHEB; }
    else if (i < OWOUT) { src = w6; off = OQKV;  }
    else if (i < OMLP1) { src = w7; off = OWOUT; }
    else if (i < OMLP2) { src = w8; off = OMLP1; }
    else                { src = w9; off = OMLP2; }
    float4 v = *(const float4*)&src[i - off];
    *(float4*)&g_wrd[i] = cvt_tf32_4(v);
}

// ---------------- graph preprocessing ----------------
__global__ void k_count(const int* __restrict__ src, const int* __restrict__ dst) {
    int e = blockIdx.x * blockDim.x + threadIdx.x;
    if (e < EE) {
        atomicAdd(&g_outdeg[src[e]], 1);
        atomicAdd(&g_indeg [dst[e]], 1);
    }
}

__global__ void k_dis() {
    int n = blockIdx.x * blockDim.x + threadIdx.x;
    if (n < NN) {
        int d = g_outdeg[n];
        g_dis[n] = (d > 0) ? rsqrtf((float)d) : 0.0f;
    }
}

__global__ void k_scan1() {
    __shared__ int sh[256];
    int t = threadIdx.x;
    int i = blockIdx.x * 256 + t;
    int v = g_indeg[i];
    sh[t] = v;
    __syncthreads();
#pragma unroll
    for (int off = 1; off < 256; off <<= 1) {
        int u = (t >= off) ? sh[t - off] : 0;
        __syncthreads();
        sh[t] += u;
        __syncthreads();
    }
    g_rowptr[i] = sh[t] - v;
    if (t == 255) g_blksum[blockIdx.x] = sh[255];
}

__global__ void k_scan2() {
    __shared__ int sh[128];
    int t = threadIdx.x;
    int v = g_blksum[t];
    sh[t] = v;
    __syncthreads();
#pragma unroll
    for (int off = 1; off < 128; off <<= 1) {
        int u = (t >= off) ? sh[t - off] : 0;
        __syncthreads();
        sh[t] += u;
        __syncthreads();
    }
    g_blkoff[t] = sh[t] - v;
    if (t == 127) g_rowptr[NN] = sh[127];
}

__global__ void k_scan3() {
    int t = threadIdx.x;
    int i = blockIdx.x * 256 + t;
    int r = g_rowptr[i] + g_blkoff[blockIdx.x];
    g_rowptr[i] = r;
    g_cursor[i] = r;
}

__global__ void k_fill(const int* __restrict__ src, const int* __restrict__ dst) {
    int e = blockIdx.x * blockDim.x + threadIdx.x;
    if (e < EE) {
        int p = atomicAdd(&g_cursor[dst[e]], 1);
        g_ecol[p] = src[e];
    }
}

// ---------------- tf32 GEMM, 3-stage cp.async ring, 2 CTAs/SM ----------------
#define AS_STR 20
#define BS_STR 136
#define A_WORDS (128 * AS_STR)
#define B_WORDS (16 * BS_STR)
__global__ __launch_bounds__(256, 2) void k_gemm(
    const float* __restrict__ A, const float* __restrict__ W,
    const float* __restrict__ bias, const float* __restrict__ res,
    float* __restrict__ C, int M, int Kd, int ldA, int Cout, int ldC,
    int relu, int accum, float* __restrict__ sums)
{
    __shared__ float As[3 * A_WORDS];
    __shared__ float Bs[3 * B_WORDS];
    int bm = blockIdx.x * 128;
    int bn = blockIdx.y * 128;
    int tid = threadIdx.x;
    int warp = tid >> 5, lane = tid & 31;
    int wm = (warp >> 1) * 32;
    int wn = (warp & 1) * 64;
    int lr = lane >> 2;
    int lc = lane & 3;

    uint32_t asB = (uint32_t)__cvta_generic_to_shared(As);
    uint32_t bsB = (uint32_t)__cvta_generic_to_shared(Bs);
    int aRow = tid >> 2, aC4 = (tid & 3) * 4;
    int bRow = tid >> 5, bC4 = (tid & 31) * 4;

#define GISSUE(buf, k0) do {                                                        \
    CP16(asB + (uint32_t)((buf) * A_WORDS + aRow * AS_STR + aC4) * 4u,              \
         A + (size_t)(bm + aRow) * ldA + (k0) + aC4);                               \
    CP16(asB + (uint32_t)((buf) * A_WORDS + (aRow + 64) * AS_STR + aC4) * 4u,       \
         A + (size_t)(bm + aRow + 64) * ldA + (k0) + aC4);                          \
    CP16(bsB + (uint32_t)((buf) * B_WORDS + bRow * BS_STR + bC4) * 4u,              \
         W + (size_t)((k0) + bRow) * Cout + bn + bC4);                              \
    CP16(bsB + (uint32_t)((buf) * B_WORDS + (bRow + 8) * BS_STR + bC4) * 4u,        \
         W + (size_t)((k0) + bRow + 8) * Cout + bn + bC4);                          \
    CPCOMMIT(); } while (0)

    float acc[2][8][4];
#pragma unroll
    for (int i = 0; i < 2; i++)
#pragma unroll
        for (int j = 0; j < 8; j++)
#pragma unroll
            for (int q = 0; q < 4; q++) acc[i][j][q] = 0.0f;

    int niter = Kd >> 4;
    GISSUE(0, 0);
    GISSUE(1, 16);
    int slot = 0;
    for (int it = 0; it < niter; it++) {
        if (it + 1 < niter) { CPWAIT1(); } else { CPWAIT0(); }
        __syncthreads();
        if (it + 2 < niter) {
            int ns = slot + 2; if (ns >= 3) ns -= 3;
            GISSUE(ns, (it + 2) * 16);
        }
        const float* Ac = As + slot * A_WORDS;
        const float* Bc = Bs + slot * B_WORDS;
#pragma unroll
        for (int kk = 0; kk < 16; kk += 8) {
            uint32_t af[2][4], bf[8][2];
#pragma unroll
            for (int mt = 0; mt < 2; mt++) {
                int r = wm + mt * 16 + lr;
                af[mt][0] = __float_as_uint(cvt_tf32(Ac[r * AS_STR + kk + lc]));
                af[mt][1] = __float_as_uint(cvt_tf32(Ac[(r + 8) * AS_STR + kk + lc]));
                af[mt][2] = __float_as_uint(cvt_tf32(Ac[r * AS_STR + kk + lc + 4]));
                af[mt][3] = __float_as_uint(cvt_tf32(Ac[(r + 8) * AS_STR + kk + lc + 4]));
            }
#pragma unroll
            for (int nt = 0; nt < 8; nt++) {
                int c = wn + nt * 8 + lr;
                bf[nt][0] = __float_as_uint(Bc[(kk + lc) * BS_STR + c]);
                bf[nt][1] = __float_as_uint(Bc[(kk + lc + 4) * BS_STR + c]);
            }
#pragma unroll
            for (int mt = 0; mt < 2; mt++)
#pragma unroll
                for (int nt = 0; nt < 8; nt++)
                    MMA_TF32(acc[mt][nt][0], acc[mt][nt][1], acc[mt][nt][2], acc[mt][nt][3],
                             af[mt][0], af[mt][1], af[mt][2], af[mt][3],
                             bf[nt][0], bf[nt][1]);
        }
        slot++; if (slot >= 3) slot = 0;
    }
#undef GISSUE
    __syncthreads();

    float csum[16], csq[16];
#pragma unroll
    for (int t = 0; t < 16; t++) { csum[t] = 0.f; csq[t] = 0.f; }

#pragma unroll
    for (int mt = 0; mt < 2; mt++) {
#pragma unroll
        for (int half = 0; half < 2; half++) {
            int row = bm + wm + mt * 16 + lr + half * 8;
            size_t ro = (size_t)row * ldC;
            size_t rr = (size_t)row * Cout;
#pragma unroll
            for (int nt = 0; nt < 8; nt++) {
                int col = bn + wn + nt * 8 + lc * 2;
                float v0 = acc[mt][nt][half * 2];
                float v1 = acc[mt][nt][half * 2 + 1];
                if (bias) { v0 += bias[col]; v1 += bias[col + 1]; }
                if (res)  { v0 += res[rr + col]; v1 += res[rr + col + 1]; }
                if (accum){ v0 += C[ro + col];  v1 += C[ro + col + 1]; }
                if (relu) { v0 = fmaxf(v0, 0.f); v1 = fmaxf(v1, 0.f); }
                if (sums) {
                    csum[nt * 2]     += v0; csq[nt * 2]     = fmaf(v0, v0, csq[nt * 2]);
                    csum[nt * 2 + 1] += v1; csq[nt * 2 + 1] = fmaf(v1, v1, csq[nt * 2 + 1]);
                }
                *(float2*)&C[ro + col] = make_float2(v0, v1);
            }
        }
    }

    if (sums) {
        if (tid < 256) As[tid] = 0.f;
        __syncthreads();
#pragma unroll
        for (int t = 0; t < 16; t++) {
            int col = wn + (t >> 1) * 8 + lc * 2 + (t & 1);
            atomicAdd(&As[col], csum[t]);
            atomicAdd(&As[128 + col], csq[t]);
        }
        __syncthreads();
        if (tid < 128) {
            atomicAdd(&sums[tid],       As[tid]);
            atomicAdd(&sums[tid + 128], As[tid + 128]);
        }
    }
}

// ---------------- Chebyshev gather ----------------
__global__ void k_cheb(const float* __restrict__ Vc, const float* __restrict__ Vp,
                       float* __restrict__ Vo, const float* __restrict__ lam,
                       int mode, int ld)
{
    int gw = (blockIdx.x * blockDim.x + threadIdx.x) >> 5;
    int lane = threadIdx.x & 31;
    if (gw >= NN) return;
    float sc = 2.0f / lam[0];
    int beg = g_rowptr[gw], end = g_rowptr[gw + 1];
    float dn = g_dis[gw];
    float4 acc = make_float4(0.f, 0.f, 0.f, 0.f);
    for (int j = beg; j < end; j++) {
        int s = g_ecol[j];
        float w = dn * g_dis[s];
        float4 v = *(const float4*)&Vc[(size_t)s * ld + lane * 4];
        acc.x = fmaf(w, v.x, acc.x);
        acc.y = fmaf(w, v.y, acc.y);
        acc.z = fmaf(w, v.z, acc.z);
        acc.w = fmaf(w, v.w, acc.w);
    }
    float4 vc = *(const float4*)&Vc[(size_t)gw * ld + lane * 4];
    float sm1 = sc - 1.0f;
    float4 r;
    r.x = sm1 * vc.x - sc * acc.x;
    r.y = sm1 * vc.y - sc * acc.y;
    r.z = sm1 * vc.z - sc * acc.z;
    r.w = sm1 * vc.w - sc * acc.w;
    if (mode) {
        float4 vp = *(const float4*)&Vp[(size_t)gw * ld + lane * 4];
        r.x = 2.f * r.x - vp.x; r.y = 2.f * r.y - vp.y;
        r.z = 2.f * r.z - vp.z; r.w = 2.f * r.w - vp.w;
    }
    *(float4*)&Vo[(size_t)gw * ld + lane * 4] = r;
}

// ---------------- S = U^T @ Hp (tf32 mma, atomic accumulate) ----------------
#define US_STR 132
__global__ __launch_bounds__(256, 2) void k_utgemm_tc(const float* __restrict__ U,
                                                      const float* __restrict__ Hp)
{
    __shared__ float Us[16 * US_STR];
    __shared__ float Hs[16 * US_STR];
    int n0 = blockIdx.x * 256;
    int tid = threadIdx.x;
    int warp = tid >> 5, lane = tid & 31;
    int wm = (warp >> 1) * 32, wn = (warp & 1) * 64;
    int lr = lane >> 2, lc = lane & 3;

    float acc[2][8][4];
#pragma unroll
    for (int i = 0; i < 2; i++)
#pragma unroll
        for (int j = 0; j < 8; j++)
#pragma unroll
            for (int q = 0; q < 4; q++) acc[i][j][q] = 0.f;

    for (int nb = 0; nb < 256; nb += 16) {
#pragma unroll
        for (int l = 0; l < 2; l++) {
            int i = tid + l * 256;
            int row = i >> 5, c4 = (i & 31) * 4;
            *(float4*)&Us[row * US_STR + c4] =
                cvt_tf32_4(*(const float4*)&U [(size_t)(n0 + nb + row) * 128 + c4]);
            *(float4*)&Hs[row * US_STR + c4] =
                cvt_tf32_4(*(const float4*)&Hp[(size_t)(n0 + nb + row) * 128 + c4]);
        }
        __syncthreads();
#pragma unroll
        for (int kk = 0; kk < 16; kk += 8) {
            uint32_t af[2][4], bf[8][2];
#pragma unroll
            for (int mt = 0; mt < 2; mt++) {
                int m = wm + mt * 16 + lr;
                af[mt][0] = __float_as_uint(Us[(kk + lc) * US_STR + m]);
                af[mt][1] = __float_as_uint(Us[(kk + lc) * US_STR + m + 8]);
                af[mt][2] = __float_as_uint(Us[(kk + lc + 4) * US_STR + m]);
                af[mt][3] = __float_as_uint(Us[(kk + lc + 4) * US_STR + m + 8]);
            }
#pragma unroll
            for (int nt = 0; nt < 8; nt++) {
                int c = wn + nt * 8 + lr;
                bf[nt][0] = __float_as_uint(Hs[(kk + lc) * US_STR + c]);
                bf[nt][1] = __float_as_uint(Hs[(kk + lc + 4) * US_STR + c]);
            }
#pragma unroll
            for (int mt = 0; mt < 2; mt++)
#pragma unroll
                for (int nt = 0; nt < 8; nt++)
                    MMA_TF32(acc[mt][nt][0], acc[mt][nt][1], acc[mt][nt][2], acc[mt][nt][3],
                             af[mt][0], af[mt][1], af[mt][2], af[mt][3],
                             bf[nt][0], bf[nt][1]);
        }
        __syncthreads();
    }
#pragma unroll
    for (int mt = 0; mt < 2; mt++)
#pragma unroll
        for (int half = 0; half < 2; half++) {
            int row = wm + mt * 16 + lr + half * 8;
#pragma unroll
            for (int nt = 0; nt < 8; nt++) {
                int col = wn + nt * 8 + lc * 2;
                atomicAdd(&g_S[row * 128 + col],     acc[mt][nt][half * 2]);
                atomicAdd(&g_S[row * 128 + col + 1], acc[mt][nt][half * 2 + 1]);
            }
        }
}

__global__ void k_scaleS(const float* __restrict__ Lambda, const float* __restrict__ gamma) {
    int i = blockIdx.x * blockDim.x + threadIdx.x;
    if (i < KEIG * CC) {
        int k = i >> 7;
        float l = Lambda[k];
        g_S[i] = cvt_tf32(g_S[i] * expf(-gamma[0] * l * l));
    }
}

// ---------------- BN finalize / elementwise ----------------
__global__ void k_bnfin(const float* __restrict__ sum, const float* __restrict__ sq,
                        const float* __restrict__ w, const float* __restrict__ b,
                        float* __restrict__ a, float* __restrict__ bs)
{
    int c = threadIdx.x;
    float mu  = sum[c] * (1.0f / NN);
    float var = sq[c]  * (1.0f / NN) - mu * mu;
    float aa = w[c] * rsqrtf(var + BN_EPS);
    a[c]  = aa;
    bs[c] = b[c] - mu * aa;
}

__global__ void k_combine(const float* __restrict__ pre, const float* __restrict__ h2,
                          float* __restrict__ out0)
{
    int i = blockIdx.x * blockDim.x + threadIdx.x;
    int col4 = (i & 31) * 4;
    float4 p = ((const float4*)pre)[i];
    float4 q = ((const float4*)h2)[i];
    float4 a1 = *(const float4*)&g_ab[col4];
    float4 b1 = *(const float4*)&g_ab[128 + col4];
    float4 a2 = *(const float4*)&g_ab[256 + col4];
    float4 b2 = *(const float4*)&g_ab[384 + col4];
    float4 rv;
    rv.x = fmaf(p.x, a1.x, b1.x) + fmaf(q.x, a2.x, b2.x);
    rv.y = fmaf(p.y, a1.y, b1.y) + fmaf(q.y, a2.y, b2.y);
    rv.z = fmaf(p.z, a1.z, b1.z) + fmaf(q.z, a2.z, b2.z);
    rv.w = fmaf(p.w, a1.w, b1.w) + fmaf(q.w, a2.w, b2.w);
    ((float4*)out0)[i] = rv;
}

__global__ void k_final(const float* __restrict__ X, float* __restrict__ out) {
    int i = blockIdx.x * blockDim.x + threadIdx.x;
    int col4 = (i & 31) * 4;
    float4 v = ((const float4*)X)[i];
    float4 a3 = *(const float4*)&g_ab[512 + col4];
    float4 b3 = *(const float4*)&g_ab[640 + col4];
    float4 rv;
    rv.x = fmaf(v.x, a3.x, b3.x); rv.y = fmaf(v.y, a3.y, b3.y);
    rv.z = fmaf(v.z, a3.z, b3.z); rv.w = fmaf(v.w, a3.w, b3.w);
    ((float4*)out)[i] = rv;
}

// ---------------- fused flash attention ----------------
#define KV_STR 36
__global__ __launch_bounds__(256, 2) void k_flash(const float* __restrict__ qkv,
                                                  float* __restrict__ out)
{
    __shared__ float Ks[128 * KV_STR];
    __shared__ float Vs[128 * KV_STR];
    int bh = blockIdx.y;
    int b = bh >> 2, h = bh & 3;
    int i0 = blockIdx.x * 128;
    int tid = threadIdx.x;
    int warp = tid >> 5, lane = tid & 31;
    int lr = lane >> 2, lc = lane & 3;
    const unsigned FULL = 0xffffffffu;
    const float scl = 0.17677669529663687f;

    const float* qb = qkv + (size_t)(b * NGR + i0 + warp * 16) * 384 + h * DH;
    uint32_t qf[4][4];
#pragma unroll
    for (int kc = 0; kc < 4; kc++) {
        qf[kc][0] = __float_as_uint(cvt_tf32(qb[(size_t)lr * 384 + kc * 8 + lc]));
        qf[kc][1] = __float_as_uint(cvt_tf32(qb[(size_t)(lr + 8) * 384 + kc * 8 + lc]));
        qf[kc][2] = __float_as_uint(cvt_tf32(qb[(size_t)lr * 384 + kc * 8 + lc + 4]));
        qf[kc][3] = __float_as_uint(cvt_tf32(qb[(size_t)(lr + 8) * 384 + kc * 8 + lc + 4]));
    }

    float m0 = -1e30f, m1 = -1e30f, l0 = 0.f, l1 = 0.f;
    float o[4][4];
#pragma unroll
    for (int nt = 0; nt < 4; nt++)
#pragma unroll
        for (int q = 0; q < 4; q++) o[nt][q] = 0.f;

    int lsrcA = (lane & ~3) | (lc >> 1);
    int lsrcB = lsrcA + 2;
    bool odd = (lc & 1);

    for (int j0 = 0; j0 < NGR; j0 += 128) {
        __syncthreads();
        const float* kb = qkv + (size_t)(b * NGR + j0) * 384 + 128 + h * DH;
        const float* vb = qkv + (size_t)(b * NGR + j0) * 384 + 256 + h * DH;
#pragma unroll
        for (int l4 = 0; l4 < 4; l4++) {
            int i = tid + l4 * 256;
            int row = i >> 3, c4 = (i & 7) * 4;
            *(float4*)&Ks[row * KV_STR + c4] =
                cvt_tf32_4(*(const float4*)&kb[(size_t)row * 384 + c4]);
            *(float4*)&Vs[row * KV_STR + c4] =
                cvt_tf32_4(*(const float4*)&vb[(size_t)row * 384 + c4]);
        }
        __syncthreads();

        float s[16][4];
#pragma unroll
        for (int g = 0; g < 16; g++)
#pragma unroll
            for (int q = 0; q < 4; q++) s[g][q] = 0.f;
#pragma unroll
        for (int kc = 0; kc < 4; kc++) {
#pragma unroll
            for (int g = 0; g < 16; g++) {
                int c = g * 8 + lr;
                uint32_t b0 = __float_as_uint(Ks[c * KV_STR + kc * 8 + lc]);
                uint32_t b1 = __float_as_uint(Ks[c * KV_STR + kc * 8 + lc + 4]);
                MMA_TF32(s[g][0], s[g][1], s[g][2], s[g][3],
                         qf[kc][0], qf[kc][1], qf[kc][2], qf[kc][3], b0, b1);
            }
        }

        float mn0 = m0, mn1 = m1;
#pragma unroll
        for (int g = 0; g < 16; g++) {
            s[g][0] *= scl; s[g][1] *= scl; s[g][2] *= scl; s[g][3] *= scl;
            mn0 = fmaxf(mn0, fmaxf(s[g][0], s[g][1]));
            mn1 = fmaxf(mn1, fmaxf(s[g][2], s[g][3]));
        }
        mn0 = fmaxf(mn0, __shfl_xor_sync(FULL, mn0, 1));
        mn0 = fmaxf(mn0, __shfl_xor_sync(FULL, mn0, 2));
        mn1 = fmaxf(mn1, __shfl_xor_sync(FULL, mn1, 1));
        mn1 = fmaxf(mn1, __shfl_xor_sync(FULL, mn1, 2));
        float al0 = __expf(m0 - mn0);
        float al1 = __expf(m1 - mn1);
        m0 = mn0; m1 = mn1;
        float rs0 = 0.f, rs1 = 0.f;
#pragma unroll
        for (int g = 0; g < 16; g++) {
            s[g][0] = __expf(s[g][0] - mn0);
            s[g][1] = __expf(s[g][1] - mn0);
            s[g][2] = __expf(s[g][2] - mn1);
            s[g][3] = __expf(s[g][3] - mn1);
            rs0 += s[g][0] + s[g][1];
            rs1 += s[g][2] + s[g][3];
            s[g][0] = cvt_tf32(s[g][0]); s[g][1] = cvt_tf32(s[g][1]);
            s[g][2] = cvt_tf32(s[g][2]); s[g][3] = cvt_tf32(s[g][3]);
        }
        rs0 += __shfl_xor_sync(FULL, rs0, 1);
        rs0 += __shfl_xor_sync(FULL, rs0, 2);
        rs1 += __shfl_xor_sync(FULL, rs1, 1);
        rs1 += __shfl_xor_sync(FULL, rs1, 2);
        l0 = l0 * al0 + rs0;
        l1 = l1 * al1 + rs1;
#pragma unroll
        for (int nt = 0; nt < 4; nt++) {
            o[nt][0] *= al0; o[nt][1] *= al0;
            o[nt][2] *= al1; o[nt][3] *= al1;
        }

#pragma unroll
        for (int g = 0; g < 16; g++) {
            float t0A = __shfl_sync(FULL, s[g][0], lsrcA);
            float t1A = __shfl_sync(FULL, s[g][1], lsrcA);
            float t2A = __shfl_sync(FULL, s[g][2], lsrcA);
            float t3A = __shfl_sync(FULL, s[g][3], lsrcA);
            float t0B = __shfl_sync(FULL, s[g][0], lsrcB);
            float t1B = __shfl_sync(FULL, s[g][1], lsrcB);
            float t2B = __shfl_sync(FULL, s[g][2], lsrcB);
            float t3B = __shfl_sync(FULL, s[g][3], lsrcB);
            uint32_t a0 = __float_as_uint(odd ? t1A : t0A);
            uint32_t a1 = __float_as_uint(odd ? t3A : t2A);
            uint32_t a2 = __float_as_uint(odd ? t1B : t0B);
            uint32_t a3 = __float_as_uint(odd ? t3B : t2B);
#pragma unroll
            for (int nt = 0; nt < 4; nt++) {
                uint32_t b0 = __float_as_uint(Vs[(g * 8 + lc) * KV_STR + nt * 8 + lr]);
                uint32_t b1 = __float_as_uint(Vs[(g * 8 + lc + 4) * KV_STR + nt * 8 + lr]);
                MMA_TF32(o[nt][0], o[nt][1], o[nt][2], o[nt][3],
                         a0, a1, a2, a3, b0, b1);
            }
        }
    }

    float inv0 = 1.0f / l0, inv1 = 1.0f / l1;
    int row0 = b * NGR + i0 + warp * 16 + lr;
#pragma unroll
    for (int nt = 0; nt < 4; nt++) {
        int col = h * DH + nt * 8 + lc * 2;
        *(float2*)&out[(size_t)row0 * CC + col] =
            make_float2(o[nt][0] * inv0, o[nt][1] * inv0);
        *(float2*)&out[(size_t)(row0 + 8) * CC + col] =
            make_float2(o[nt][2] * inv1, o[nt][3] * inv1);
    }
}

// ---------------- host ----------------
static float* symf(const void* p) { return (float*)p; }

extern "C" void kernel_launch(void* const* d_in, const int* in_sizes, int n_in,
                              void* d_out, int out_size)
{
    const float* x      = (const float*)d_in[0];
    const float* U      = (const float*)d_in[1];
    const float* Lambda = (const float*)d_in[2];
    const float* lamMax = (const float*)d_in[3];
    const float* w_spa1 = (const float*)d_in[4];  const float* b_spa1 = (const float*)d_in[5];
    const float* w_spa2 = (const float*)d_in[6];  const float* b_spa2 = (const float*)d_in[7];
    const float* w_spe1 = (const float*)d_in[8];  const float* b_spe1 = (const float*)d_in[9];
    const float* w_spe2 = (const float*)d_in[10]; const float* b_spe2 = (const float*)d_in[11];
    const float* cheb_w = (const float*)d_in[12]; const float* cheb_b = (const float*)d_in[13];
    const float* gamma  = (const float*)d_in[14]; const float* w_proj = (const float*)d_in[15];
    const float* w_qkv  = (const float*)d_in[16]; const float* b_qkv  = (const float*)d_in[17];
    const float* w_out  = (const float*)d_in[18]; const float* b_out  = (const float*)d_in[19];
    const float* mlp_w1 = (const float*)d_in[20]; const float* mlp_b1 = (const float*)d_in[21];
    const float* mlp_w2 = (const float*)d_in[22]; const float* mlp_b2 = (const float*)d_in[23];
    const float* bn1w = (const float*)d_in[24]; const float* bn1b = (const float*)d_in[25];
    const float* bn2w = (const float*)d_in[26]; const float* bn2b = (const float*)d_in[27];
    const float* bn3w = (const float*)d_in[28]; const float* bn3b = (const float*)d_in[29];
    const int*   ei   = (const int*)d_in[30];
    const int* src = ei;
    const int* dst = ei + EE;
    float* out = (float*)d_out;

    void *pBIG, *pHID, *pLOC, *pXSP, *pHPJ, *pATT, *pH2, *pQKV, *pS, *pOUTD, *pIND,
         *pSUMS, *pAB, *pWRD;
    cudaGetSymbolAddress(&pBIG, g_big);   cudaGetSymbolAddress(&pHID, g_hid);
    cudaGetSymbolAddress(&pLOC, g_loc);   cudaGetSymbolAddress(&pXSP, g_xspec);
    cudaGetSymbolAddress(&pHPJ, g_hproj); cudaGetSymbolAddress(&pATT, g_att);
    cudaGetSymbolAddress(&pH2, g_h2);     cudaGetSymbolAddress(&pQKV, g_qkv);
    cudaGetSymbolAddress(&pS, g_S);
    cudaGetSymbolAddress(&pOUTD, g_outdeg); cudaGetSymbolAddress(&pIND, g_indeg);
    cudaGetSymbolAddress(&pSUMS, g_sums);   cudaGetSymbolAddress(&pAB, g_ab);
    cudaGetSymbolAddress(&pWRD, g_wrd);

    float* BIG = symf(pBIG); float* HID = symf(pHID); float* LOC = symf(pLOC);
    float* XSP = symf(pXSP); float* HPJ = symf(pHPJ); float* ATT = symf(pATT);
    float* H2  = symf(pH2);  float* QKV = symf(pQKV); float* SUMS = symf(pSUMS);
    float* WR  = symf(pWRD);
    float* HIDa = HID;
    float* HIDb = HID + (size_t)NN * CC;

    static cudaStream_t s2 = 0, s3 = 0;
    static cudaEvent_t evF = 0, evB = 0, evC = 0;
    if (!s2) {
        cudaStreamCreateWithFlags(&s2, cudaStreamNonBlocking);
        cudaStreamCreateWithFlags(&s3, cudaStreamNonBlocking);
        cudaEventCreateWithFlags(&evF, cudaEventDisableTiming);
        cudaEventCreateWithFlags(&evB, cudaEventDisableTiming);
        cudaEventCreateWithFlags(&evC, cudaEventDisableTiming);
    }

    cudaMemsetAsync(pOUTD, 0, NN * sizeof(int));
    cudaMemsetAsync(pIND,  0, NN * sizeof(int));
    cudaMemsetAsync(pS,    0, KEIG * CC * sizeof(float));
    cudaMemsetAsync(pSUMS, 0, 6 * CC * sizeof(float));
    k_roundw<<<(WTOT / 4 + 255) / 256, 256>>>(w_spa1, w_spa2, w_spe1, w_spe2, w_proj,
                                              cheb_w, w_qkv, w_out, mlp_w1, mlp_w2);
    cudaEventRecord(evF, 0);
    cudaStreamWaitEvent(s2, evF, 0);
    cudaStreamWaitEvent(s3, evF, 0);

    auto GEMM = [&](cudaStream_t st, const float* A, const float* W, const float* bias,
                    const float* res, float* C, int M, int Kd, int ldA, int Cout, int ldC,
                    int relu, int accum, float* sums) {
        dim3 g(M / 128, Cout / 128);
        k_gemm<<<g, 256, 0, st>>>(A, W, bias, res, C, M, Kd, ldA, Cout, ldC, relu, accum, sums);
    };

    // ---- branch A (stream 0): spatial MLP + prep + Chebyshev ----
    GEMM(0, x, WR + OSPA1, b_spa1, nullptr, HIDa, NN, 128, 128, 128, 128, 1, 0, nullptr);
    GEMM(0, HIDa, WR + OSPA2, b_spa2, nullptr, BIG, NN, 128, 128, 128, 640, 0, 0, nullptr);
    k_count<<<EE / 256, 256>>>(src, dst);
    k_dis<<<NN / 256, 256>>>();
    k_scan1<<<128, 256>>>();
    k_scan2<<<1, 128>>>();
    k_scan3<<<128, 256>>>();
    k_fill<<<EE / 256, 256>>>(src, dst);
    k_cheb<<<NN / 8, 256>>>(BIG, nullptr, BIG + 128, lamMax, 0, 640);
    for (int k = 2; k < KCH; k++)
        k_cheb<<<NN / 8, 256>>>(BIG + (k - 1) * 128, BIG + (k - 2) * 128,
                                BIG + k * 128, lamMax, 1, 640);
    GEMM(0, BIG, WR + OCHEB, nullptr, nullptr, LOC, NN, 640, 640, 128, 128, 0, 0, nullptr);

    // ---- branch B (s2): spectral ----
    GEMM(s2, x, WR + OSPE1, b_spe1, nullptr, HIDb, NN, 128, 128, 128, 128, 1, 0, nullptr);
    GEMM(s2, HIDb, WR + OSPE2, b_spe2, nullptr, XSP, NN, 128, 128, 128, 128, 0, 0, nullptr);
    GEMM(s2, XSP, WR + OPROJ, nullptr, nullptr, HPJ, NN, 128, 128, 128, 128, 0, 0, nullptr);
    k_utgemm_tc<<<NN / 256, 256, 0, s2>>>(U, HPJ);
    k_scaleS<<<(KEIG * CC) / 256, 256, 0, s2>>>(Lambda, gamma);
    cudaEventRecord(evB, s2);

    // ---- branch C (s3): attention ----
    GEMM(s3, x, WR + OQKV, b_qkv, nullptr, QKV, NN, 128, 128, 384, 384, 0, 0, nullptr);
    {
        dim3 gf(NGR / 128, BBG * HH);
        k_flash<<<gf, 256, 0, s3>>>(QKV, ATT);
    }
    GEMM(s3, ATT, WR + OWOUT, b_out, x, H2, NN, 128, 128, 128, 128, 0, 0, SUMS + 256);
    cudaEventRecord(evC, s3);

    // ---- join on stream 0 ----
    cudaStreamWaitEvent(0, evB, 0);
    GEMM(0, U, symf(pS), cheb_b, x, LOC, NN, 128, 128, 128, 128, 0, 1, SUMS);
    cudaStreamWaitEvent(0, evC, 0);

    k_bnfin<<<1, 128>>>(SUMS,       SUMS + 128, bn1w, bn1b, symf(pAB),       symf(pAB) + 128);
    k_bnfin<<<1, 128>>>(SUMS + 256, SUMS + 384, bn2w, bn2b, symf(pAB) + 256, symf(pAB) + 384);
    k_combine<<<(NN * CC / 4) / 256, 256>>>(LOC, H2, XSP);

    // ---- final MLP with residual (fused BN3 stats) ----
    GEMM(0, XSP, WR + OMLP1, mlp_b1, nullptr, HID, NN, 128, 128, 256, 256, 1, 0, nullptr);
    GEMM(0, HID, WR + OMLP2, mlp_b2, XSP, LOC, NN, 256, 256, 128, 128, 0, 0, SUMS + 512);

    k_bnfin<<<1, 128>>>(SUMS + 512, SUMS + 640, bn3w, bn3b, symf(pAB) + 512, symf(pAB) + 640);
    k_final<<<(NN * CC / 4) / 256, 256>>>(LOC, out);
}